// round 1
// baseline (speedup 1.0000x reference)
#include <cuda_runtime.h>
#include <math.h>
#include <stdint.h>

// Problem constants
#define BB 2
#define TT 1024
#define DD 768
#define HH 12
#define EE 4
#define HD 64
#define NN 2048          // B*T
#define LL 2
#define VV 50257
#define FF 3072          // 4*D

// ---------------- scratch (static device allocations; no cudaMalloc) -------
__device__ float g_x[NN * DD];     // residual stream
__device__ float g_ln[NN * DD];    // layernorm output
__device__ float g_k[NN * DD];
__device__ float g_v[NN * DD];
__device__ float g_q[NN * DD];
__device__ float g_o[NN * DD];
__device__ float g_coef[NN * EE];
__device__ float g_h1[NN * FF];

// ---------------------------------------------------------------------------
// Embedding: x[n,:] = wte[idx[n],:] + wpe[n%T,:]
__global__ void embed_kernel(const int* __restrict__ idx,
                             const float* __restrict__ wte,
                             const float* __restrict__ wpe,
                             float* __restrict__ x) {
    int n = blockIdx.x;
    int t = n % TT;
    int tok = idx[n];
    const float* we = wte + (size_t)tok * DD;
    const float* wp = wpe + (size_t)t * DD;
    float* xr = x + (size_t)n * DD;
    for (int d = threadIdx.x; d < DD; d += blockDim.x)
        xr[d] = we[d] + wp[d];
}

// ---------------------------------------------------------------------------
// LayerNorm: one block (256 threads) per row of 768
__global__ void ln_kernel(const float* __restrict__ x,
                          const float* __restrict__ g,
                          const float* __restrict__ b,
                          float* __restrict__ y) {
    int r = blockIdx.x;
    int tid = threadIdx.x;   // 256
    const float* xr = x + (size_t)r * DD;
    float v0 = xr[tid], v1 = xr[tid + 256], v2 = xr[tid + 512];

    __shared__ float red[8];
    // sum
    float s = v0 + v1 + v2;
    #pragma unroll
    for (int o = 16; o > 0; o >>= 1) s += __shfl_xor_sync(0xffffffffu, s, o);
    if ((tid & 31) == 0) red[tid >> 5] = s;
    __syncthreads();
    float tot = 0.f;
    #pragma unroll
    for (int i = 0; i < 8; i++) tot += red[i];
    float mean = tot * (1.0f / DD);
    __syncthreads();

    float c0 = v0 - mean, c1 = v1 - mean, c2 = v2 - mean;
    float sq = c0 * c0 + c1 * c1 + c2 * c2;
    #pragma unroll
    for (int o = 16; o > 0; o >>= 1) sq += __shfl_xor_sync(0xffffffffu, sq, o);
    if ((tid & 31) == 0) red[tid >> 5] = sq;
    __syncthreads();
    float var = 0.f;
    #pragma unroll
    for (int i = 0; i < 8; i++) var += red[i];
    var *= (1.0f / DD);
    float rstd = rsqrtf(var + 1e-5f);

    float* yr = y + (size_t)r * DD;
    yr[tid]       = c0 * rstd * g[tid]       + b[tid];
    yr[tid + 256] = c1 * rstd * g[tid + 256] + b[tid + 256];
    yr[tid + 512] = c2 * rstd * g[tid + 512] + b[tid + 512];
}

// ---------------------------------------------------------------------------
// Gate: per token compute gate logits, top-2, softmax -> coef[N,E]
__device__ __forceinline__ float softplusf(float x) {
    if (x > 20.f) return x;
    if (x < -20.f) return expf(x);
    return log1pf(expf(x));
}

__global__ void gate_kernel(const float* __restrict__ ln,
                            const float* __restrict__ gw,   // [D,E]
                            const float* __restrict__ nw,   // [D,E]
                            const float* __restrict__ noise,// [N,E]
                            float* __restrict__ coef) {
    int r = blockIdx.x;
    int tid = threadIdx.x; // 128
    const float* xr = ln + (size_t)r * DD;
    float acc[8] = {0.f, 0.f, 0.f, 0.f, 0.f, 0.f, 0.f, 0.f};
    for (int d = tid; d < DD; d += 128) {
        float xv = xr[d];
        #pragma unroll
        for (int e = 0; e < EE; e++) {
            acc[e]      += xv * gw[d * EE + e];
            acc[4 + e]  += xv * nw[d * EE + e];
        }
    }
    __shared__ float part[8 * 128];
    #pragma unroll
    for (int e = 0; e < 8; e++) part[e * 128 + tid] = acc[e];
    __syncthreads();
    __shared__ float red[8];
    if (tid < 8) {
        float s = 0.f;
        for (int i = 0; i < 128; i++) s += part[tid * 128 + i];
        red[tid] = s;
    }
    __syncthreads();
    if (tid == 0) {
        float lg[4];
        #pragma unroll
        for (int e = 0; e < EE; e++)
            lg[e] = red[e] + noise[(size_t)r * EE + e] * softplusf(red[4 + e]);
        // top-2 (stable: first index wins ties, matching lax.top_k)
        int i1 = 0;
        #pragma unroll
        for (int e = 1; e < EE; e++) if (lg[e] > lg[i1]) i1 = e;
        int i2 = -1;
        #pragma unroll
        for (int e = 0; e < EE; e++) {
            if (e == i1) continue;
            if (i2 < 0 || lg[e] > lg[i2]) i2 = e;
        }
        float m = lg[i1];
        float e1 = expf(lg[i1] - m), e2 = expf(lg[i2] - m);
        float inv = 1.f / (e1 + e2);
        float c[4] = {0.f, 0.f, 0.f, 0.f};
        c[i1] = e1 * inv;
        c[i2] = e2 * inv;
        #pragma unroll
        for (int e = 0; e < EE; e++) coef[(size_t)r * EE + e] = c[e];
    }
}

// ---------------------------------------------------------------------------
// Tiled fp32 GEMM. A:[M,K] row-major. B:[K,N] row-major, or (BT) [N,K] row-major.
// EPI: 0 = C = acc
//      1 = C = gelu(acc + bias[c])
//      2 = C += acc + bias[c]
//      3 = C += rs[r*EE] * acc      (rs points at coef column base)
__device__ __forceinline__ float geluf(float x) {
    float inner = 0.7978845608028654f * (x + 0.044715f * x * x * x);
    return 0.5f * x * (1.0f + tanhf(inner));
}

template <int EPI, bool BT>
__global__ __launch_bounds__(256)
void gemm_kernel(const float* __restrict__ A, const float* __restrict__ Bm,
                 float* __restrict__ C, int M, int N, int K,
                 const float* __restrict__ bias, const float* __restrict__ rs) {
    __shared__ float As[16][65];
    __shared__ float Bs[16][65];
    int tid = threadIdx.x;
    int tx = tid & 15, ty = tid >> 4;
    int row0 = blockIdx.y * 64, col0 = blockIdx.x * 64;

    float acc[4][4];
    #pragma unroll
    for (int i = 0; i < 4; i++)
        #pragma unroll
        for (int j = 0; j < 4; j++) acc[i][j] = 0.f;

    for (int k0 = 0; k0 < K; k0 += 16) {
        // load A tile: 64 rows x 16 cols
        #pragma unroll
        for (int i = 0; i < 4; i++) {
            int lid = tid * 4 + i;
            int ar = lid >> 4, ac = lid & 15;
            As[ac][ar] = A[(size_t)(row0 + ar) * K + k0 + ac];
        }
        // load B tile: 16 (k) x 64 (n)
        #pragma unroll
        for (int i = 0; i < 4; i++) {
            int lid = tid + i * 256;
            if (!BT) {
                int br = lid >> 6, bc = lid & 63;
                int gn = col0 + bc;
                Bs[br][bc] = (gn < N) ? Bm[(size_t)(k0 + br) * N + gn] : 0.f;
            } else {
                int bn = lid >> 4, bk = lid & 15;
                int gn = col0 + bn;
                Bs[bk][bn] = (gn < N) ? Bm[(size_t)gn * K + k0 + bk] : 0.f;
            }
        }
        __syncthreads();
        #pragma unroll
        for (int kk = 0; kk < 16; kk++) {
            float a[4], b[4];
            #pragma unroll
            for (int i = 0; i < 4; i++) a[i] = As[kk][ty * 4 + i];
            #pragma unroll
            for (int j = 0; j < 4; j++) b[j] = Bs[kk][tx * 4 + j];
            #pragma unroll
            for (int i = 0; i < 4; i++)
                #pragma unroll
                for (int j = 0; j < 4; j++) acc[i][j] += a[i] * b[j];
        }
        __syncthreads();
    }

    #pragma unroll
    for (int i = 0; i < 4; i++) {
        int r = row0 + ty * 4 + i;
        #pragma unroll
        for (int j = 0; j < 4; j++) {
            int c = col0 + tx * 4 + j;
            if (c >= N) continue;
            size_t off = (size_t)r * N + c;
            float vv = acc[i][j];
            if (EPI == 0) {
                C[off] = vv;
            } else if (EPI == 1) {
                C[off] = geluf(vv + bias[c]);
            } else if (EPI == 2) {
                C[off] += vv + bias[c];
            } else {
                C[off] += rs[(size_t)r * EE] * vv;
            }
        }
    }
}

// ---------------------------------------------------------------------------
// Flash-style causal attention: one block per (b, h, q-row), 128 threads.
// q,k,v,o in [B,T,H,HD] layout (i.e. [N, D] with head-major columns).
__global__ __launch_bounds__(128)
void attn_kernel(const float* __restrict__ q, const float* __restrict__ k,
                 const float* __restrict__ v, float* __restrict__ o) {
    int qi = blockIdx.x, h = blockIdx.y, b = blockIdx.z;
    int tid = threadIdx.x; // 128
    const float scale = 0.125f; // 1/sqrt(64)

    __shared__ float qs[HD];
    __shared__ float ps[128];
    __shared__ float swm[4];
    __shared__ float sws[4];

    size_t qoff = ((size_t)(b * TT + qi) * HH + h) * HD;
    if (tid < HD) qs[tid] = q[qoff + tid];
    __syncthreads();

    float m = -1e30f, lsum = 0.f, acc = 0.f;
    int nk = qi + 1;

    for (int k0 = 0; k0 < nk; k0 += 128) {
        int j = k0 + tid;
        float s = -1e30f;
        if (j < nk) {
            const float* krow = k + ((size_t)(b * TT + j) * HH + h) * HD;
            float d = 0.f;
            #pragma unroll
            for (int dd = 0; dd < HD; dd++) d += qs[dd] * krow[dd];
            s = d * scale;
        }
        // block max
        float mv = s;
        #pragma unroll
        for (int off = 16; off > 0; off >>= 1)
            mv = fmaxf(mv, __shfl_xor_sync(0xffffffffu, mv, off));
        if ((tid & 31) == 0) swm[tid >> 5] = mv;
        __syncthreads();
        float cmax = fmaxf(fmaxf(swm[0], swm[1]), fmaxf(swm[2], swm[3]));
        float mnew = fmaxf(m, cmax);

        float p = (j < nk) ? __expf(s - mnew) : 0.f;
        ps[tid] = p;
        // block sum (sync inside also publishes ps)
        float sv = p;
        #pragma unroll
        for (int off = 16; off > 0; off >>= 1)
            sv += __shfl_xor_sync(0xffffffffu, sv, off);
        if ((tid & 31) == 0) sws[tid >> 5] = sv;
        __syncthreads();
        float psum = sws[0] + sws[1] + sws[2] + sws[3];

        float corr = __expf(m - mnew);
        lsum = lsum * corr + psum;

        if (tid < HD) {
            float a = acc * corr;
            int lim = min(128, nk - k0);
            for (int jj = 0; jj < lim; jj++) {
                a += ps[jj] * v[((size_t)(b * TT + k0 + jj) * HH + h) * HD + tid];
            }
            acc = a;
        }
        m = mnew;
        __syncthreads();
    }

    if (tid < HD)
        o[qoff + tid] = acc / lsum;
}

// ---------------------------------------------------------------------------
extern "C" void kernel_launch(void* const* d_in, const int* in_sizes, int n_in,
                              void* d_out, int out_size) {
    const int*   idx     = (const int*)  d_in[0];
    const float* wte     = (const float*)d_in[1];
    const float* wpe     = (const float*)d_in[2];
    const float* ln1_g   = (const float*)d_in[3];
    const float* ln1_b   = (const float*)d_in[4];
    const float* ln2_g   = (const float*)d_in[5];
    const float* ln2_b   = (const float*)d_in[6];
    const float* lnf_g   = (const float*)d_in[7];
    const float* lnf_b   = (const float*)d_in[8];
    const float* Wk      = (const float*)d_in[9];
    const float* Wv      = (const float*)d_in[10];
    const float* Wq      = (const float*)d_in[11];
    const float* Wo      = (const float*)d_in[12];
    const float* gate_w  = (const float*)d_in[13];
    const float* noise_w = (const float*)d_in[14];
    const float* fc_w    = (const float*)d_in[15];
    const float* fc_b    = (const float*)d_in[16];
    const float* proj_w  = (const float*)d_in[17];
    const float* proj_b  = (const float*)d_in[18];
    const float* noise   = (const float*)d_in[19];
    float* out = (float*)d_out;

    float *x, *ln, *kb, *vb, *qb, *ob, *coef, *h1;
    cudaGetSymbolAddress((void**)&x,    g_x);
    cudaGetSymbolAddress((void**)&ln,   g_ln);
    cudaGetSymbolAddress((void**)&kb,   g_k);
    cudaGetSymbolAddress((void**)&vb,   g_v);
    cudaGetSymbolAddress((void**)&qb,   g_q);
    cudaGetSymbolAddress((void**)&ob,   g_o);
    cudaGetSymbolAddress((void**)&coef, g_coef);
    cudaGetSymbolAddress((void**)&h1,   g_h1);

    const size_t DxD = (size_t)DD * DD;

    embed_kernel<<<NN, 256>>>(idx, wte, wpe, x);

    dim3 gDD(DD / 64, NN / 64);        // [2048 x 768] GEMM grid
    dim3 gFF(FF / 64, NN / 64);        // [2048 x 3072]
    dim3 gV((VV + 63) / 64, NN / 64);  // [2048 x 50257]
    dim3 gA(TT, HH, BB);               // attention

    for (int l = 0; l < LL; l++) {
        ln_kernel<<<NN, 256>>>(x, ln1_g + l * DD, ln1_b + l * DD, ln);
        gate_kernel<<<NN, 128>>>(ln, gate_w + (size_t)l * DD * EE,
                                 noise_w + (size_t)l * DD * EE,
                                 noise + (size_t)l * NN * EE, coef);
        gemm_kernel<0, false><<<gDD, 256>>>(ln, Wk + (size_t)l * DxD, kb,
                                            NN, DD, DD, nullptr, nullptr);
        gemm_kernel<0, false><<<gDD, 256>>>(ln, Wv + (size_t)l * DxD, vb,
                                            NN, DD, DD, nullptr, nullptr);
        for (int e = 0; e < EE; e++) {
            const float* wq = Wq + ((size_t)l * EE + e) * DxD;
            const float* wo = Wo + ((size_t)l * EE + e) * DxD;
            gemm_kernel<0, false><<<gDD, 256>>>(ln, wq, qb, NN, DD, DD,
                                                nullptr, nullptr);
            attn_kernel<<<gA, 128>>>(qb, kb, vb, ob);
            gemm_kernel<3, false><<<gDD, 256>>>(ob, wo, x, NN, DD, DD,
                                                nullptr, coef + e);
        }
        ln_kernel<<<NN, 256>>>(x, ln2_g + l * DD, ln2_b + l * DD, ln);
        gemm_kernel<1, false><<<gFF, 256>>>(ln, fc_w + (size_t)l * DD * FF, h1,
                                            NN, FF, DD, fc_b + (size_t)l * FF,
                                            nullptr);
        gemm_kernel<2, false><<<gDD, 256>>>(h1, proj_w + (size_t)l * FF * DD, x,
                                            NN, DD, FF, proj_b + (size_t)l * DD,
                                            nullptr);
    }

    ln_kernel<<<NN, 256>>>(x, lnf_g, lnf_b, ln);
    // logits = ln @ wte^T  (wte is [V, D] row-major -> BT variant)
    gemm_kernel<0, true><<<gV, 256>>>(ln, wte, out, NN, VV, DD,
                                      nullptr, nullptr);
}

// round 2
// speedup vs baseline: 4.6957x; 4.6957x over previous
#include <cuda_runtime.h>
#include <math.h>
#include <stdint.h>

// Problem constants
#define BB 2
#define TT 1024
#define DD 768
#define HH 12
#define EE 4
#define HD 64
#define NN 2048          // B*T
#define LL 2
#define VV 50257
#define FF 3072          // 4*D

// ---------------- scratch (static device arrays; float4 for 16B alignment) --
__device__ float4 g_x4[NN * DD / 4];
__device__ float4 g_ln4[NN * DD / 4];
__device__ float4 g_k4[NN * DD / 4];
__device__ float4 g_v4[NN * DD / 4];
__device__ float4 g_q4[NN * DD / 4];
__device__ float4 g_o4[NN * DD / 4];
__device__ float4 g_h14[NN * FF / 4];
__device__ float  g_coef[NN * EE];

// ---------------- f32x2 packed helpers ------------------------------------
__device__ __forceinline__ unsigned long long pk2(float lo, float hi) {
    unsigned long long r;
    asm("mov.b64 %0, {%1, %2};" : "=l"(r) : "f"(lo), "f"(hi));
    return r;
}
__device__ __forceinline__ void fma2(unsigned long long& d,
                                     unsigned long long a,
                                     unsigned long long b) {
    asm("fma.rn.f32x2 %0, %1, %2, %0;" : "+l"(d) : "l"(a), "l"(b));
}
__device__ __forceinline__ float2 up2(unsigned long long p) {
    float2 f;
    asm("mov.b64 {%0, %1}, %2;" : "=f"(f.x), "=f"(f.y) : "l"(p));
    return f;
}

// ---------------------------------------------------------------------------
__global__ void embed_kernel(const int* __restrict__ idx,
                             const float* __restrict__ wte,
                             const float* __restrict__ wpe,
                             float* __restrict__ x) {
    int n = blockIdx.x;
    int t = n % TT;
    int tok = idx[n];
    const float* we = wte + (size_t)tok * DD;
    const float* wp = wpe + (size_t)t * DD;
    float* xr = x + (size_t)n * DD;
    for (int d = threadIdx.x; d < DD; d += blockDim.x)
        xr[d] = we[d] + wp[d];
}

// ---------------------------------------------------------------------------
__global__ void ln_kernel(const float* __restrict__ x,
                          const float* __restrict__ g,
                          const float* __restrict__ b,
                          float* __restrict__ y) {
    int r = blockIdx.x;
    int tid = threadIdx.x;   // 256
    const float* xr = x + (size_t)r * DD;
    float v0 = xr[tid], v1 = xr[tid + 256], v2 = xr[tid + 512];

    __shared__ float red[8];
    float s = v0 + v1 + v2;
    #pragma unroll
    for (int o = 16; o > 0; o >>= 1) s += __shfl_xor_sync(0xffffffffu, s, o);
    if ((tid & 31) == 0) red[tid >> 5] = s;
    __syncthreads();
    float tot = 0.f;
    #pragma unroll
    for (int i = 0; i < 8; i++) tot += red[i];
    float mean = tot * (1.0f / DD);
    __syncthreads();

    float c0 = v0 - mean, c1 = v1 - mean, c2 = v2 - mean;
    float sq = c0 * c0 + c1 * c1 + c2 * c2;
    #pragma unroll
    for (int o = 16; o > 0; o >>= 1) sq += __shfl_xor_sync(0xffffffffu, sq, o);
    if ((tid & 31) == 0) red[tid >> 5] = sq;
    __syncthreads();
    float var = 0.f;
    #pragma unroll
    for (int i = 0; i < 8; i++) var += red[i];
    var *= (1.0f / DD);
    float rstd = rsqrtf(var + 1e-5f);

    float* yr = y + (size_t)r * DD;
    yr[tid]       = c0 * rstd * g[tid]       + b[tid];
    yr[tid + 256] = c1 * rstd * g[tid + 256] + b[tid + 256];
    yr[tid + 512] = c2 * rstd * g[tid + 512] + b[tid + 512];
}

// ---------------------------------------------------------------------------
__device__ __forceinline__ float softplusf(float x) {
    if (x > 20.f) return x;
    if (x < -20.f) return expf(x);
    return log1pf(expf(x));
}

__global__ void gate_kernel(const float* __restrict__ ln,
                            const float* __restrict__ gw,
                            const float* __restrict__ nw,
                            const float* __restrict__ noise,
                            float* __restrict__ coef) {
    int r = blockIdx.x;
    int tid = threadIdx.x; // 128
    const float* xr = ln + (size_t)r * DD;
    float acc[8] = {0.f, 0.f, 0.f, 0.f, 0.f, 0.f, 0.f, 0.f};
    for (int d = tid; d < DD; d += 128) {
        float xv = xr[d];
        #pragma unroll
        for (int e = 0; e < EE; e++) {
            acc[e]     += xv * gw[d * EE + e];
            acc[4 + e] += xv * nw[d * EE + e];
        }
    }
    __shared__ float part[8 * 128];
    #pragma unroll
    for (int e = 0; e < 8; e++) part[e * 128 + tid] = acc[e];
    __syncthreads();
    __shared__ float red[8];
    if (tid < 8) {
        float s = 0.f;
        for (int i = 0; i < 128; i++) s += part[tid * 128 + i];
        red[tid] = s;
    }
    __syncthreads();
    if (tid == 0) {
        float lg[4];
        #pragma unroll
        for (int e = 0; e < EE; e++)
            lg[e] = red[e] + noise[(size_t)r * EE + e] * softplusf(red[4 + e]);
        int i1 = 0;
        #pragma unroll
        for (int e = 1; e < EE; e++) if (lg[e] > lg[i1]) i1 = e;
        int i2 = -1;
        #pragma unroll
        for (int e = 0; e < EE; e++) {
            if (e == i1) continue;
            if (i2 < 0 || lg[e] > lg[i2]) i2 = e;
        }
        float m = lg[i1];
        float e1 = expf(lg[i1] - m), e2 = expf(lg[i2] - m);
        float inv = 1.f / (e1 + e2);
        float c[4] = {0.f, 0.f, 0.f, 0.f};
        c[i1] = e1 * inv;
        c[i2] = e2 * inv;
        #pragma unroll
        for (int e = 0; e < EE; e++) coef[(size_t)r * EE + e] = c[e];
    }
}

// ---------------------------------------------------------------------------
__device__ __forceinline__ float geluf(float x) {
    float inner = 0.7978845608028654f * (x + 0.044715f * x * x * x);
    return 0.5f * x * (1.0f + tanhf(inner));
}

// 128 x TN tiled GEMM with packed f32x2 FMAs.
// A:[M,K] row-major. B: [K,N] row-major (!BT) or [N,K] row-major (BT).
// EPI: 0: C=acc  1: C=gelu(acc+bias)  2: C+=acc+bias  3: C+=rs[r*EE]*acc
template <int EPI, bool BT, int TN>
__global__ __launch_bounds__(256, 2)
void gemm_t(const float* __restrict__ A, const float* __restrict__ Bm,
            float* __restrict__ C, int M, int N, int K,
            const float* __restrict__ bias, const float* __restrict__ rs) {
    constexpr int NH = TN / 64;
    __shared__ float As[16][136];
    __shared__ float Bs[16][TN + 8];
    const int tid = threadIdx.x;
    const int tx = tid & 15, ty = tid >> 4;
    const int row0 = blockIdx.y * 128, col0 = blockIdx.x * TN;

    unsigned long long acc[2][NH][2][4];
    #pragma unroll
    for (int rh = 0; rh < 2; rh++)
        #pragma unroll
        for (int ch = 0; ch < NH; ch++)
            #pragma unroll
            for (int i2 = 0; i2 < 2; i2++)
                #pragma unroll
                for (int j = 0; j < 4; j++) acc[rh][ch][i2][j] = 0ULL;

    for (int k0 = 0; k0 < K; k0 += 16) {
        // A tile: 128 rows x 16 k, transpose into As[k][m]
        #pragma unroll
        for (int i = 0; i < 2; i++) {
            int idx = tid + 256 * i;
            int r = idx >> 2, kq = idx & 3;
            float4 va = *(const float4*)(A + (size_t)(row0 + r) * K + k0 + kq * 4);
            As[kq * 4 + 0][r] = va.x;
            As[kq * 4 + 1][r] = va.y;
            As[kq * 4 + 2][r] = va.z;
            As[kq * 4 + 3][r] = va.w;
        }
        if (!BT) {
            #pragma unroll
            for (int i = 0; i < NH; i++) {
                int idx = tid + 256 * i;
                int kr = idx / (TN / 4), c4 = idx % (TN / 4);
                *(float4*)&Bs[kr][c4 * 4] =
                    *(const float4*)(Bm + (size_t)(k0 + kr) * N + col0 + c4 * 4);
            }
        } else {
            #pragma unroll
            for (int i = 0; i < NH; i++) {
                int idx = tid + 256 * i;
                int r = idx >> 2, kq = idx & 3;
                int gn = col0 + r;
                float4 vb = make_float4(0.f, 0.f, 0.f, 0.f);
                if (gn < N)
                    vb = *(const float4*)(Bm + (size_t)gn * K + k0 + kq * 4);
                Bs[kq * 4 + 0][r] = vb.x;
                Bs[kq * 4 + 1][r] = vb.y;
                Bs[kq * 4 + 2][r] = vb.z;
                Bs[kq * 4 + 3][r] = vb.w;
            }
        }
        __syncthreads();
        #pragma unroll
        for (int kk = 0; kk < 16; kk++) {
            unsigned long long pa[2][2], pb[NH][4];
            #pragma unroll
            for (int rh = 0; rh < 2; rh++) {
                float4 a = *(const float4*)&As[kk][rh * 64 + ty * 4];
                pa[rh][0] = pk2(a.x, a.y);
                pa[rh][1] = pk2(a.z, a.w);
            }
            #pragma unroll
            for (int ch = 0; ch < NH; ch++) {
                float4 b = *(const float4*)&Bs[kk][ch * 64 + tx * 4];
                pb[ch][0] = pk2(b.x, b.x);
                pb[ch][1] = pk2(b.y, b.y);
                pb[ch][2] = pk2(b.z, b.z);
                pb[ch][3] = pk2(b.w, b.w);
            }
            #pragma unroll
            for (int rh = 0; rh < 2; rh++)
                #pragma unroll
                for (int ch = 0; ch < NH; ch++)
                    #pragma unroll
                    for (int i2 = 0; i2 < 2; i2++)
                        #pragma unroll
                        for (int j = 0; j < 4; j++)
                            fma2(acc[rh][ch][i2][j], pa[rh][i2], pb[ch][j]);
        }
        __syncthreads();
    }

    #pragma unroll
    for (int rh = 0; rh < 2; rh++)
        #pragma unroll
        for (int i2 = 0; i2 < 2; i2++) {
            #pragma unroll
            for (int ch = 0; ch < NH; ch++)
                #pragma unroll
                for (int j = 0; j < 4; j++) {
                    int c = col0 + ch * 64 + tx * 4 + j;
                    if (c >= N) continue;
                    float2 f = up2(acc[rh][ch][i2][j]);
                    #pragma unroll
                    for (int ii = 0; ii < 2; ii++) {
                        int r = row0 + rh * 64 + ty * 4 + i2 * 2 + ii;
                        size_t off = (size_t)r * N + c;
                        float vv = (ii == 0) ? f.x : f.y;
                        if (EPI == 0) {
                            C[off] = vv;
                        } else if (EPI == 1) {
                            C[off] = geluf(vv + bias[c]);
                        } else if (EPI == 2) {
                            C[off] += vv + bias[c];
                        } else {
                            C[off] += rs[(size_t)r * EE] * vv;
                        }
                    }
                }
        }
}

// ---------------------------------------------------------------------------
// Tiled flash attention: 64 queries x 64 keys per block, 256 threads (16x16),
// 4x4 microtile, online softmax. q,k,v,o: [B,T,H,HD] = [N, 768] layout.
#define ATTN_SMEM (4 * 64 * 65 * 4)

__global__ __launch_bounds__(256)
void attn_tile_kernel(const float* __restrict__ q, const float* __restrict__ k,
                      const float* __restrict__ v, float* __restrict__ o) {
    extern __shared__ float sm[];
    float (*Qs)[65] = (float(*)[65])sm;
    float (*Ks)[65] = (float(*)[65])(sm + 64 * 65);
    float (*Vs)[65] = (float(*)[65])(sm + 2 * 64 * 65);
    float (*Ps)[65] = (float(*)[65])(sm + 3 * 64 * 65);

    const int tid = threadIdx.x;
    const int tx = tid & 15, ty = tid >> 4;
    const int q0 = blockIdx.x * 64, h = blockIdx.y, b = blockIdx.z;
    const size_t base = (size_t)b * TT * DD + (size_t)h * HD;

    #pragma unroll
    for (int i = 0; i < 4; i++) {
        int idx = tid + 256 * i;
        int r = idx >> 4, c4 = idx & 15;
        float4 vq = *(const float4*)(q + base + (size_t)(q0 + r) * DD + c4 * 4);
        Qs[r][c4 * 4 + 0] = vq.x; Qs[r][c4 * 4 + 1] = vq.y;
        Qs[r][c4 * 4 + 2] = vq.z; Qs[r][c4 * 4 + 3] = vq.w;
    }
    float m_[4], l_[4], acc[4][4];
    #pragma unroll
    for (int i = 0; i < 4; i++) {
        m_[i] = -1e30f; l_[i] = 0.f;
        #pragma unroll
        for (int j = 0; j < 4; j++) acc[i][j] = 0.f;
    }
    __syncthreads();

    int qrow[4];
    #pragma unroll
    for (int i = 0; i < 4; i++) qrow[i] = q0 + ty * 4 + i;

    for (int kt = 0; kt <= (int)blockIdx.x; kt++) {
        int k0t = kt * 64;
        #pragma unroll
        for (int i = 0; i < 4; i++) {
            int idx = tid + 256 * i;
            int r = idx >> 4, c4 = idx & 15;
            float4 vk = *(const float4*)(k + base + (size_t)(k0t + r) * DD + c4 * 4);
            Ks[r][c4 * 4 + 0] = vk.x; Ks[r][c4 * 4 + 1] = vk.y;
            Ks[r][c4 * 4 + 2] = vk.z; Ks[r][c4 * 4 + 3] = vk.w;
            float4 vv = *(const float4*)(v + base + (size_t)(k0t + r) * DD + c4 * 4);
            Vs[r][c4 * 4 + 0] = vv.x; Vs[r][c4 * 4 + 1] = vv.y;
            Vs[r][c4 * 4 + 2] = vv.z; Vs[r][c4 * 4 + 3] = vv.w;
        }
        __syncthreads();

        float s[4][4];
        #pragma unroll
        for (int i = 0; i < 4; i++)
            #pragma unroll
            for (int j = 0; j < 4; j++) s[i][j] = 0.f;

        #pragma unroll 8
        for (int d = 0; d < 64; d++) {
            float a0 = Qs[ty * 4 + 0][d], a1 = Qs[ty * 4 + 1][d];
            float a2 = Qs[ty * 4 + 2][d], a3 = Qs[ty * 4 + 3][d];
            float b0 = Ks[tx * 4 + 0][d], b1 = Ks[tx * 4 + 1][d];
            float b2 = Ks[tx * 4 + 2][d], b3 = Ks[tx * 4 + 3][d];
            s[0][0] += a0 * b0; s[0][1] += a0 * b1; s[0][2] += a0 * b2; s[0][3] += a0 * b3;
            s[1][0] += a1 * b0; s[1][1] += a1 * b1; s[1][2] += a1 * b2; s[1][3] += a1 * b3;
            s[2][0] += a2 * b0; s[2][1] += a2 * b1; s[2][2] += a2 * b2; s[2][3] += a2 * b3;
            s[3][0] += a3 * b0; s[3][1] += a3 * b1; s[3][2] += a3 * b2; s[3][3] += a3 * b3;
        }

        bool diag = (kt == (int)blockIdx.x);
        #pragma unroll
        for (int i = 0; i < 4; i++)
            #pragma unroll
            for (int j = 0; j < 4; j++) {
                float sv = s[i][j] * 0.125f;
                if (diag && (k0t + tx * 4 + j > qrow[i])) sv = -1e30f;
                s[i][j] = sv;
            }

        #pragma unroll
        for (int i = 0; i < 4; i++) {
            float rm = fmaxf(fmaxf(s[i][0], s[i][1]), fmaxf(s[i][2], s[i][3]));
            #pragma unroll
            for (int w = 1; w < 16; w <<= 1)
                rm = fmaxf(rm, __shfl_xor_sync(0xffffffffu, rm, w));
            float mn = fmaxf(m_[i], rm);
            float corr = __expf(m_[i] - mn);
            float rsum = 0.f;
            #pragma unroll
            for (int j = 0; j < 4; j++) {
                s[i][j] = __expf(s[i][j] - mn);
                rsum += s[i][j];
            }
            #pragma unroll
            for (int w = 1; w < 16; w <<= 1)
                rsum += __shfl_xor_sync(0xffffffffu, rsum, w);
            l_[i] = l_[i] * corr + rsum;
            m_[i] = mn;
            #pragma unroll
            for (int j = 0; j < 4; j++) acc[i][j] *= corr;
        }

        #pragma unroll
        for (int i = 0; i < 4; i++)
            #pragma unroll
            for (int j = 0; j < 4; j++)
                Ps[ty * 4 + i][tx * 4 + j] = s[i][j];
        __syncthreads();

        #pragma unroll 8
        for (int kk = 0; kk < 64; kk++) {
            float a0 = Ps[ty * 4 + 0][kk], a1 = Ps[ty * 4 + 1][kk];
            float a2 = Ps[ty * 4 + 2][kk], a3 = Ps[ty * 4 + 3][kk];
            float b0 = Vs[kk][tx * 4 + 0], b1 = Vs[kk][tx * 4 + 1];
            float b2 = Vs[kk][tx * 4 + 2], b3 = Vs[kk][tx * 4 + 3];
            acc[0][0] += a0 * b0; acc[0][1] += a0 * b1; acc[0][2] += a0 * b2; acc[0][3] += a0 * b3;
            acc[1][0] += a1 * b0; acc[1][1] += a1 * b1; acc[1][2] += a1 * b2; acc[1][3] += a1 * b3;
            acc[2][0] += a2 * b0; acc[2][1] += a2 * b1; acc[2][2] += a2 * b2; acc[2][3] += a2 * b3;
            acc[3][0] += a3 * b0; acc[3][1] += a3 * b1; acc[3][2] += a3 * b2; acc[3][3] += a3 * b3;
        }
        __syncthreads();
    }

    #pragma unroll
    for (int i = 0; i < 4; i++) {
        float inv = 1.f / l_[i];
        #pragma unroll
        for (int j = 0; j < 4; j++)
            o[base + (size_t)qrow[i] * DD + tx * 4 + j] = acc[i][j] * inv;
    }
}

// ---------------------------------------------------------------------------
extern "C" void kernel_launch(void* const* d_in, const int* in_sizes, int n_in,
                              void* d_out, int out_size) {
    const int*   idx     = (const int*)  d_in[0];
    const float* wte     = (const float*)d_in[1];
    const float* wpe     = (const float*)d_in[2];
    const float* ln1_g   = (const float*)d_in[3];
    const float* ln1_b   = (const float*)d_in[4];
    const float* ln2_g   = (const float*)d_in[5];
    const float* ln2_b   = (const float*)d_in[6];
    const float* lnf_g   = (const float*)d_in[7];
    const float* lnf_b   = (const float*)d_in[8];
    const float* Wk      = (const float*)d_in[9];
    const float* Wv      = (const float*)d_in[10];
    const float* Wq      = (const float*)d_in[11];
    const float* Wo      = (const float*)d_in[12];
    const float* gate_w  = (const float*)d_in[13];
    const float* noise_w = (const float*)d_in[14];
    const float* fc_w    = (const float*)d_in[15];
    const float* fc_b    = (const float*)d_in[16];
    const float* proj_w  = (const float*)d_in[17];
    const float* proj_b  = (const float*)d_in[18];
    const float* noise   = (const float*)d_in[19];
    float* out = (float*)d_out;

    float *x, *ln, *kb, *vb, *qb, *ob, *coef, *h1;
    cudaGetSymbolAddress((void**)&x,    g_x4);
    cudaGetSymbolAddress((void**)&ln,   g_ln4);
    cudaGetSymbolAddress((void**)&kb,   g_k4);
    cudaGetSymbolAddress((void**)&vb,   g_v4);
    cudaGetSymbolAddress((void**)&qb,   g_q4);
    cudaGetSymbolAddress((void**)&ob,   g_o4);
    cudaGetSymbolAddress((void**)&coef, g_coef);
    cudaGetSymbolAddress((void**)&h1,   g_h14);

    cudaFuncSetAttribute(attn_tile_kernel,
                         cudaFuncAttributeMaxDynamicSharedMemorySize, ATTN_SMEM);

    const size_t DxD = (size_t)DD * DD;

    embed_kernel<<<NN, 256>>>(idx, wte, wpe, x);

    dim3 gD64(DD / 64, NN / 128);          // 12 x 16
    dim3 gF128(FF / 128, NN / 128);        // 24 x 16
    dim3 gV128((VV + 127) / 128, NN / 128);// 393 x 16
    dim3 gA(TT / 64, HH, BB);              // 16 x 12 x 2

    for (int l = 0; l < LL; l++) {
        ln_kernel<<<NN, 256>>>(x, ln1_g + l * DD, ln1_b + l * DD, ln);
        gate_kernel<<<NN, 128>>>(ln, gate_w + (size_t)l * DD * EE,
                                 noise_w + (size_t)l * DD * EE,
                                 noise + (size_t)l * NN * EE, coef);
        gemm_t<0, false, 64><<<gD64, 256>>>(ln, Wk + (size_t)l * DxD, kb,
                                            NN, DD, DD, nullptr, nullptr);
        gemm_t<0, false, 64><<<gD64, 256>>>(ln, Wv + (size_t)l * DxD, vb,
                                            NN, DD, DD, nullptr, nullptr);
        for (int e = 0; e < EE; e++) {
            const float* wq = Wq + ((size_t)l * EE + e) * DxD;
            const float* wo = Wo + ((size_t)l * EE + e) * DxD;
            gemm_t<0, false, 64><<<gD64, 256>>>(ln, wq, qb, NN, DD, DD,
                                                nullptr, nullptr);
            attn_tile_kernel<<<gA, 256, ATTN_SMEM>>>(qb, kb, vb, ob);
            gemm_t<3, false, 64><<<gD64, 256>>>(ob, wo, x, NN, DD, DD,
                                                nullptr, coef + e);
        }
        ln_kernel<<<NN, 256>>>(x, ln2_g + l * DD, ln2_b + l * DD, ln);
        gemm_t<1, false, 128><<<gF128, 256>>>(ln, fc_w + (size_t)l * DD * FF, h1,
                                              NN, FF, DD, fc_b + (size_t)l * FF,
                                              nullptr);
        gemm_t<2, false, 64><<<gD64, 256>>>(h1, proj_w + (size_t)l * FF * DD, x,
                                            NN, DD, FF, proj_b + (size_t)l * DD,
                                            nullptr);
    }

    ln_kernel<<<NN, 256>>>(x, lnf_g, lnf_b, ln);
    gemm_t<0, true, 128><<<gV128, 256>>>(ln, wte, out, NN, VV, DD,
                                         nullptr, nullptr);
}

// round 4
// speedup vs baseline: 8.0943x; 1.7238x over previous
#include <cuda_runtime.h>
#include <cuda_bf16.h>
#include <math.h>
#include <stdint.h>

typedef __nv_bfloat16 bf16;
typedef unsigned long long u64;
typedef unsigned int u32;

#define BBATCH 2
#define TT 1024
#define DD 768
#define HH 12
#define EE 4
#define NN 2048
#define LL 2
#define VV 50257
#define FF 3072
#define KV2 1536

// ------------------- scratch (static device arrays) ------------------------
__device__ __align__(16) float g_x[NN * DD];
__device__ __align__(16) float g_lnf32[NN * DD];
__device__ __align__(16) bf16  g_lnHi[NN * DD];
__device__ __align__(16) bf16  g_lnLo[NN * DD];
__device__ __align__(16) float g_kv[NN * KV2];
__device__ __align__(16) float g_q[NN * FF];
__device__ __align__(16) bf16  g_obHi[NN * FF];
__device__ __align__(16) bf16  g_obLo[NN * FF];
__device__ __align__(16) bf16  g_h1Hi[NN * FF];
__device__ __align__(16) bf16  g_h1Lo[NN * FF];
__device__ float g_coef[NN * EE];

// transposed + split weights (B^T layout: [N][K] K-contiguous)
__device__ __align__(16) bf16 g_kvTHi[LL * KV2 * DD];
__device__ __align__(16) bf16 g_kvTLo[LL * KV2 * DD];
__device__ __align__(16) bf16 g_qTHi[LL * FF * DD];
__device__ __align__(16) bf16 g_qTLo[LL * FF * DD];
__device__ __align__(16) bf16 g_oTHi[LL * DD * FF];
__device__ __align__(16) bf16 g_oTLo[LL * DD * FF];
__device__ __align__(16) bf16 g_fcTHi[LL * FF * DD];
__device__ __align__(16) bf16 g_fcTLo[LL * FF * DD];
__device__ __align__(16) bf16 g_pjTHi[LL * DD * FF];
__device__ __align__(16) bf16 g_pjTLo[LL * DD * FF];
__device__ __align__(16) bf16 g_wteHi[VV * DD];
__device__ __align__(16) bf16 g_wteLo[VV * DD];

// ------------------- helpers ------------------------------------------------
__device__ __forceinline__ u64 pk2(float lo, float hi) {
    u64 r; asm("mov.b64 %0, {%1, %2};" : "=l"(r) : "f"(lo), "f"(hi)); return r;
}
__device__ __forceinline__ void fma2(u64& d, u64 a, u64 b) {
    asm("fma.rn.f32x2 %0, %1, %2, %0;" : "+l"(d) : "l"(a), "l"(b));
}
__device__ __forceinline__ void mul2(u64& d, u64 a) {
    asm("mul.rn.f32x2 %0, %0, %1;" : "+l"(d) : "l"(a));
}
__device__ __forceinline__ float2 up2(u64 p) {
    float2 f; asm("mov.b64 {%0, %1}, %2;" : "=f"(f.x), "=f"(f.y) : "l"(p)); return f;
}
__device__ __forceinline__ void split2(float v, bf16& h, bf16& l) {
    h = __float2bfloat16(v);
    l = __float2bfloat16(v - __bfloat162float(h));
}
__device__ __forceinline__ float geluf(float x) {
    float inner = 0.7978845608028654f * (x + 0.044715f * x * x * x);
    return 0.5f * x * (1.0f + tanhf(inner));
}
__device__ __forceinline__ u32 smem_u32(const void* p) {
    u32 a;
    asm("{ .reg .u64 t; cvta.to.shared.u64 t, %1; cvt.u32.u64 %0, t; }"
        : "=r"(a) : "l"(p));
    return a;
}

#define CP16(dst, src, n) \
    asm volatile("cp.async.cg.shared.global [%0], [%1], 16, %2;" \
                 :: "r"(dst), "l"(src), "r"(n) : "memory")
#define CP_COMMIT() asm volatile("cp.async.commit_group;" ::: "memory")
#define CP_WAIT1()  asm volatile("cp.async.wait_group 1;" ::: "memory")
#define CP_WAIT0()  asm volatile("cp.async.wait_group 0;" ::: "memory")

__device__ __forceinline__ void ldmx4(u32* r, u32 addr) {
    asm volatile("ldmatrix.sync.aligned.m8n8.x4.shared.b16 {%0,%1,%2,%3}, [%4];"
        : "=r"(r[0]), "=r"(r[1]), "=r"(r[2]), "=r"(r[3]) : "r"(addr));
}
__device__ __forceinline__ void mma16816(float* c, const u32* a, const u32* b) {
    asm volatile("mma.sync.aligned.m16n8k16.row.col.f32.bf16.bf16.f32 "
        "{%0,%1,%2,%3}, {%4,%5,%6,%7}, {%8,%9}, {%0,%1,%2,%3};"
        : "+f"(c[0]), "+f"(c[1]), "+f"(c[2]), "+f"(c[3])
        : "r"(a[0]), "r"(a[1]), "r"(a[2]), "r"(a[3]), "r"(b[0]), "r"(b[1]));
}

// ------------------- small kernels ------------------------------------------
__global__ void embed_kernel(const int* __restrict__ idx,
                             const float* __restrict__ wte,
                             const float* __restrict__ wpe,
                             float* __restrict__ x) {
    int n = blockIdx.x;
    int t = n % TT;
    int tok = idx[n];
    const float* we = wte + (size_t)tok * DD;
    const float* wp = wpe + (size_t)t * DD;
    float* xr = x + (size_t)n * DD;
    for (int d = threadIdx.x; d < DD; d += blockDim.x)
        xr[d] = we[d] + wp[d];
}

__global__ void ln_kernel(const float* __restrict__ x,
                          const float* __restrict__ g,
                          const float* __restrict__ b,
                          float* __restrict__ y,
                          bf16* __restrict__ yhi, bf16* __restrict__ ylo) {
    int r = blockIdx.x;
    int tid = threadIdx.x;   // 256
    const float* xr = x + (size_t)r * DD;
    float v0 = xr[tid], v1 = xr[tid + 256], v2 = xr[tid + 512];

    __shared__ float red[8];
    float s = v0 + v1 + v2;
    #pragma unroll
    for (int o = 16; o > 0; o >>= 1) s += __shfl_xor_sync(0xffffffffu, s, o);
    if ((tid & 31) == 0) red[tid >> 5] = s;
    __syncthreads();
    float tot = 0.f;
    #pragma unroll
    for (int i = 0; i < 8; i++) tot += red[i];
    float mean = tot * (1.0f / DD);
    __syncthreads();

    float c0 = v0 - mean, c1 = v1 - mean, c2 = v2 - mean;
    float sq = c0 * c0 + c1 * c1 + c2 * c2;
    #pragma unroll
    for (int o = 16; o > 0; o >>= 1) sq += __shfl_xor_sync(0xffffffffu, sq, o);
    if ((tid & 31) == 0) red[tid >> 5] = sq;
    __syncthreads();
    float var = 0.f;
    #pragma unroll
    for (int i = 0; i < 8; i++) var += red[i];
    var *= (1.0f / DD);
    float rstd = rsqrtf(var + 1e-5f);

    size_t base = (size_t)r * DD;
    #pragma unroll
    for (int p = 0; p < 3; p++) {
        int d = tid + p * 256;
        float cv = (p == 0 ? c0 : (p == 1 ? c1 : c2));
        float o = cv * rstd * g[d] + b[d];
        y[base + d] = o;
        bf16 hv, lv; split2(o, hv, lv);
        yhi[base + d] = hv; ylo[base + d] = lv;
    }
}

__device__ __forceinline__ float softplusf(float x) {
    if (x > 20.f) return x;
    if (x < -20.f) return expf(x);
    return log1pf(expf(x));
}

__global__ void gate_kernel(const float* __restrict__ ln,
                            const float* __restrict__ gw,
                            const float* __restrict__ nw,
                            const float* __restrict__ noise,
                            float* __restrict__ coef) {
    int r = blockIdx.x;
    int tid = threadIdx.x; // 128
    const float* xr = ln + (size_t)r * DD;
    float acc[8] = {0.f, 0.f, 0.f, 0.f, 0.f, 0.f, 0.f, 0.f};
    for (int d = tid; d < DD; d += 128) {
        float xv = xr[d];
        #pragma unroll
        for (int e = 0; e < EE; e++) {
            acc[e]     += xv * gw[d * EE + e];
            acc[4 + e] += xv * nw[d * EE + e];
        }
    }
    __shared__ float part[8 * 128];
    #pragma unroll
    for (int e = 0; e < 8; e++) part[e * 128 + tid] = acc[e];
    __syncthreads();
    __shared__ float red[8];
    if (tid < 8) {
        float s = 0.f;
        for (int i = 0; i < 128; i++) s += part[tid * 128 + i];
        red[tid] = s;
    }
    __syncthreads();
    if (tid == 0) {
        float lg[4];
        #pragma unroll
        for (int e = 0; e < EE; e++)
            lg[e] = red[e] + noise[(size_t)r * EE + e] * softplusf(red[4 + e]);
        int i1 = 0;
        #pragma unroll
        for (int e = 1; e < EE; e++) if (lg[e] > lg[i1]) i1 = e;
        int i2 = -1;
        #pragma unroll
        for (int e = 0; e < EE; e++) {
            if (e == i1) continue;
            if (i2 < 0 || lg[e] > lg[i2]) i2 = e;
        }
        float m = lg[i1];
        float e1 = expf(lg[i1] - m), e2 = expf(lg[i2] - m);
        float inv = 1.f / (e1 + e2);
        float c[4] = {0.f, 0.f, 0.f, 0.f};
        c[i1] = e1 * inv;
        c[i2] = e2 * inv;
        #pragma unroll
        for (int e = 0; e < EE; e++) coef[(size_t)r * EE + e] = c[e];
    }
}

// transpose fp32 [K,N] -> split bf16 [N, ld] (dst[n*ld + k])
__global__ void tr_split(const float* __restrict__ src, bf16* __restrict__ dhi,
                         bf16* __restrict__ dlo, int K, int N, int ld) {
    __shared__ float t[32][33];
    int n0 = blockIdx.x * 32, k0 = blockIdx.y * 32;
    int tx = threadIdx.x, ty = threadIdx.y; // 32x8
    #pragma unroll
    for (int i = 0; i < 4; i++)
        t[ty + 8 * i][tx] = src[(size_t)(k0 + ty + 8 * i) * N + n0 + tx];
    __syncthreads();
    #pragma unroll
    for (int i = 0; i < 4; i++) {
        float v = t[tx][ty + 8 * i];
        bf16 hv, lv; split2(v, hv, lv);
        size_t o = (size_t)(n0 + ty + 8 * i) * ld + k0 + tx;
        dhi[o] = hv; dlo[o] = lv;
    }
}

// elementwise fp32 -> split bf16 (for wte)
__global__ void split_k(const float* __restrict__ s, bf16* __restrict__ hi,
                        bf16* __restrict__ lo, int n4) {
    int i = blockIdx.x * 256 + threadIdx.x;
    if (i >= n4) return;
    float4 v = ((const float4*)s)[i];
    bf16 h0, l0, h1, l1, h2, l2, h3, l3;
    split2(v.x, h0, l0); split2(v.y, h1, l1);
    split2(v.z, h2, l2); split2(v.w, h3, l3);
    __nv_bfloat162* H = (__nv_bfloat162*)hi;
    __nv_bfloat162* L = (__nv_bfloat162*)lo;
    H[2 * i]     = __nv_bfloat162(h0, h1);
    H[2 * i + 1] = __nv_bfloat162(h2, h3);
    L[2 * i]     = __nv_bfloat162(l0, l1);
    L[2 * i + 1] = __nv_bfloat162(l2, l3);
}

// ------------------- mma.sync split-bf16 GEMM --------------------------------
// C[2048, N] = (Ahi+Alo)[2048, K] x (Bhi+Blo)^T, B stored [N][K] K-contig.
// 3 MMA passes: hi*hi + hi*lo + lo*hi.
// EPI 0: Cf = v   1: gelu(v + bias) -> Chi/Clo   2: Cf += v   3: Cf += v + bias
#define GLDS 40                 // smem row stride (bf16 elems), 80 bytes
#define GMAT (128 * GLDS * 2)   // 10240 bytes per matrix
#define GSTG (4 * GMAT)         // 40960 per stage
#define GSM_TOTAL (2 * GSTG)    // 81920

template <int EPI>
__global__ __launch_bounds__(256)
void mma_gemm(const bf16* __restrict__ Ahi, const bf16* __restrict__ Alo,
              const bf16* __restrict__ Bhi, const bf16* __restrict__ Blo,
              float* __restrict__ Cf, bf16* __restrict__ Chi, bf16* __restrict__ Clo,
              const float* __restrict__ bias, int N, int K) {
    extern __shared__ char smdyn[];
    const u32 sb = smem_u32(smdyn);
    const int tid = threadIdx.x, wid = tid >> 5, lane = tid & 31;
    const int row0 = blockIdx.x * 128, col0 = blockIdx.y * 128;
    const int warp_m = (wid & 3) * 32, warp_n = (wid >> 2) * 64;

    float c[2][8][4];
    #pragma unroll
    for (int mt = 0; mt < 2; mt++)
        #pragma unroll
        for (int nt = 0; nt < 8; nt++)
            #pragma unroll
            for (int i = 0; i < 4; i++) c[mt][nt][i] = 0.f;

    const int nch = K >> 5;

    // stage loader
    auto load_stage = [&](int s, int k0) {
        u32 st = sb + s * GSTG;
        #pragma unroll
        for (int i = 0; i < 2; i++) {
            int idx = tid + (i << 8);
            int r = idx >> 2, ch = idx & 3;
            u32 doff = (u32)(r * GLDS + ch * 8) * 2;
            size_t ga = (size_t)(row0 + r) * K + k0 + ch * 8;
            CP16(st + doff,        Ahi + ga, 16);
            CP16(st + GMAT + doff, Alo + ga, 16);
            int gn = col0 + r;
            int pr = (gn < N) ? 16 : 0;
            int gnc = (gn < N) ? gn : 0;
            size_t gb = (size_t)gnc * K + k0 + ch * 8;
            CP16(st + 2 * GMAT + doff, Bhi + gb, pr);
            CP16(st + 3 * GMAT + doff, Blo + gb, pr);
        }
        CP_COMMIT();
    };

    load_stage(0, 0);
    for (int kc = 0; kc < nch; kc++) {
        if (kc + 1 < nch) { load_stage((kc + 1) & 1, (kc + 1) << 5); CP_WAIT1(); }
        else CP_WAIT0();
        __syncthreads();

        u32 st = sb + (kc & 1) * GSTG;
        #pragma unroll
        for (int ks = 0; ks < 2; ks++) {
            u32 ah[2][4], al[2][4];
            #pragma unroll
            for (int mt = 0; mt < 2; mt++) {
                u32 ro = (u32)(warp_m + mt * 16 + (lane & 15)) * (GLDS * 2)
                       + (u32)(ks * 16 + ((lane >> 4) << 3)) * 2;
                ldmx4(ah[mt], st + ro);
                ldmx4(al[mt], st + GMAT + ro);
            }
            #pragma unroll
            for (int j = 0; j < 4; j++) {
                u32 bh[4], bl[4];
                u32 ro = (u32)(warp_n + j * 16 + ((lane >> 4) << 3) + (lane & 7)) * (GLDS * 2)
                       + (u32)(ks * 16 + (((lane >> 3) & 1) << 3)) * 2;
                ldmx4(bh, st + 2 * GMAT + ro);
                ldmx4(bl, st + 3 * GMAT + ro);
                #pragma unroll
                for (int mt = 0; mt < 2; mt++) {
                    mma16816(c[mt][2 * j],     ah[mt], bh);
                    mma16816(c[mt][2 * j],     ah[mt], bl);
                    mma16816(c[mt][2 * j],     al[mt], bh);
                    mma16816(c[mt][2 * j + 1], ah[mt], bh + 2);
                    mma16816(c[mt][2 * j + 1], ah[mt], bl + 2);
                    mma16816(c[mt][2 * j + 1], al[mt], bh + 2);
                }
            }
        }
        __syncthreads();
    }

    // epilogue: c0,c1 at row rb, cols cc,cc+1; c2,c3 at row rb+8
    #pragma unroll
    for (int mt = 0; mt < 2; mt++) {
        int rb = row0 + warp_m + mt * 16 + (lane >> 2);
        #pragma unroll
        for (int nt = 0; nt < 8; nt++) {
            int cc = col0 + warp_n + nt * 8 + (lane & 3) * 2;
            float* cr = c[mt][nt];
            #pragma unroll
            for (int h = 0; h < 2; h++) {
                int r = rb + h * 8;
                #pragma unroll
                for (int q = 0; q < 2; q++) {
                    int col = cc + q;
                    float v = cr[h * 2 + q];
                    size_t off = (size_t)r * N + col;
                    if (EPI == 0) {
                        if (col < N) Cf[off] = v;
                    } else if (EPI == 1) {
                        float gv = geluf(v + bias[col]);
                        bf16 hv, lv; split2(gv, hv, lv);
                        Chi[off] = hv; Clo[off] = lv;
                    } else if (EPI == 2) {
                        Cf[off] += v;
                    } else {
                        Cf[off] += v + bias[col];
                    }
                }
            }
        }
    }
}

// ------------------- attention ----------------------------------------------
// Batched over experts. grid = (T/64, H, B*E). Reads fp32 q [N,3072] and
// kv [N,1536]; writes coef-scaled split-bf16 ob [N,3072].
#define APAD 66
#define ATTN_SMEM (4 * 64 * APAD * 4)

__global__ __launch_bounds__(256)
void attn_kernel(const float* __restrict__ qb, const float* __restrict__ kvb,
                 const float* __restrict__ coef,
                 bf16* __restrict__ oHi, bf16* __restrict__ oLo) {
    extern __shared__ char smdyn[];
    float* sm = (float*)smdyn;
    float (*Qs)[APAD] = (float(*)[APAD])sm;
    float (*Ks)[APAD] = (float(*)[APAD])(sm + 64 * APAD);
    float (*Vs)[APAD] = (float(*)[APAD])(sm + 2 * 64 * APAD);
    float (*Ps)[APAD] = (float(*)[APAD])(sm + 3 * 64 * APAD);

    const int tid = threadIdx.x;
    const int tx = tid & 15, ty = tid >> 4;
    const int q0 = blockIdx.x * 64, hh = blockIdx.y;
    const int b = blockIdx.z >> 2, e = blockIdx.z & 3;

    #pragma unroll
    for (int i = 0; i < 4; i++) {
        int idx = tid + 256 * i;
        int r = idx >> 4, c4 = idx & 15;
        float4 vq = *(const float4*)(qb + (size_t)(b * TT + q0 + r) * FF
                                     + e * DD + hh * 64 + c4 * 4);
        Qs[r][c4 * 4 + 0] = vq.x; Qs[r][c4 * 4 + 1] = vq.y;
        Qs[r][c4 * 4 + 2] = vq.z; Qs[r][c4 * 4 + 3] = vq.w;
    }
    float m_[4], l_[4];
    u64 acc2[4][4];
    #pragma unroll
    for (int i = 0; i < 4; i++) {
        m_[i] = -1e30f; l_[i] = 0.f;
        #pragma unroll
        for (int j = 0; j < 4; j++) acc2[i][j] = pk2(0.f, 0.f);
    }
    __syncthreads();

    int qrow[4];
    #pragma unroll
    for (int i = 0; i < 4; i++) qrow[i] = q0 + ty * 4 + i;

    for (int kt = 0; kt <= (int)blockIdx.x; kt++) {
        int k0t = kt * 64;
        #pragma unroll
        for (int i = 0; i < 4; i++) {
            int idx = tid + 256 * i;
            int r = idx >> 4, c4 = idx & 15;
            size_t rb = (size_t)(b * TT + k0t + r) * KV2 + hh * 64 + c4 * 4;
            float4 vk = *(const float4*)(kvb + rb);
            Ks[r][c4 * 4 + 0] = vk.x; Ks[r][c4 * 4 + 1] = vk.y;
            Ks[r][c4 * 4 + 2] = vk.z; Ks[r][c4 * 4 + 3] = vk.w;
            float4 vv = *(const float4*)(kvb + rb + DD);
            Vs[r][c4 * 4 + 0] = vv.x; Vs[r][c4 * 4 + 1] = vv.y;
            Vs[r][c4 * 4 + 2] = vv.z; Vs[r][c4 * 4 + 3] = vv.w;
        }
        __syncthreads();

        u64 s2[4][4];
        #pragma unroll
        for (int i = 0; i < 4; i++)
            #pragma unroll
            for (int j = 0; j < 4; j++) s2[i][j] = pk2(0.f, 0.f);

        #pragma unroll 8
        for (int d = 0; d < 64; d += 2) {
            u64 pa[4], pb[4];
            #pragma unroll
            for (int i = 0; i < 4; i++) pa[i] = *(const u64*)&Qs[ty * 4 + i][d];
            #pragma unroll
            for (int j = 0; j < 4; j++) pb[j] = *(const u64*)&Ks[tx * 4 + j][d];
            #pragma unroll
            for (int i = 0; i < 4; i++)
                #pragma unroll
                for (int j = 0; j < 4; j++) fma2(s2[i][j], pa[i], pb[j]);
        }

        bool diag = (kt == (int)blockIdx.x);
        float s[4][4];
        #pragma unroll
        for (int i = 0; i < 4; i++)
            #pragma unroll
            for (int j = 0; j < 4; j++) {
                float2 f = up2(s2[i][j]);
                float sv = (f.x + f.y) * 0.125f;
                if (diag && (k0t + tx * 4 + j > qrow[i])) sv = -1e30f;
                s[i][j] = sv;
            }

        #pragma unroll
        for (int i = 0; i < 4; i++) {
            float rm = fmaxf(fmaxf(s[i][0], s[i][1]), fmaxf(s[i][2], s[i][3]));
            #pragma unroll
            for (int w = 1; w < 16; w <<= 1)
                rm = fmaxf(rm, __shfl_xor_sync(0xffffffffu, rm, w));
            float mn = fmaxf(m_[i], rm);
            float corr = __expf(m_[i] - mn);
            float rsum = 0.f;
            #pragma unroll
            for (int j = 0; j < 4; j++) {
                s[i][j] = __expf(s[i][j] - mn);
                rsum += s[i][j];
            }
            #pragma unroll
            for (int w = 1; w < 16; w <<= 1)
                rsum += __shfl_xor_sync(0xffffffffu, rsum, w);
            l_[i] = l_[i] * corr + rsum;
            m_[i] = mn;
            u64 pc = pk2(corr, corr);
            #pragma unroll
            for (int j = 0; j < 4; j++) mul2(acc2[i][j], pc);
        }

        #pragma unroll
        for (int i = 0; i < 4; i++)
            #pragma unroll
            for (int j = 0; j < 4; j++)
                Ps[ty * 4 + i][tx * 4 + j] = s[i][j];
        __syncthreads();

        #pragma unroll 8
        for (int kk = 0; kk < 64; kk += 2) {
            u64 pa[4], pb[4];
            #pragma unroll
            for (int i = 0; i < 4; i++) pa[i] = *(const u64*)&Ps[ty * 4 + i][kk];
            #pragma unroll
            for (int j = 0; j < 4; j++)
                pb[j] = pk2(Vs[kk][tx * 4 + j], Vs[kk + 1][tx * 4 + j]);
            #pragma unroll
            for (int i = 0; i < 4; i++)
                #pragma unroll
                for (int j = 0; j < 4; j++) fma2(acc2[i][j], pa[i], pb[j]);
        }
        __syncthreads();
    }

    #pragma unroll
    for (int i = 0; i < 4; i++) {
        size_t rg = (size_t)b * TT + qrow[i];
        float cf = coef[rg * EE + e];
        float inv = cf / l_[i];
        #pragma unroll
        for (int j = 0; j < 4; j++) {
            float2 f = up2(acc2[i][j]);
            float v = (f.x + f.y) * inv;
            bf16 hv, lv; split2(v, hv, lv);
            size_t off = rg * FF + (size_t)e * DD + hh * 64 + tx * 4 + j;
            oHi[off] = hv; oLo[off] = lv;
        }
    }
}

// ------------------- host ----------------------------------------------------
extern "C" void kernel_launch(void* const* d_in, const int* in_sizes, int n_in,
                              void* d_out, int out_size) {
    const int*   idx     = (const int*)  d_in[0];
    const float* wte     = (const float*)d_in[1];
    const float* wpe     = (const float*)d_in[2];
    const float* ln1_g   = (const float*)d_in[3];
    const float* ln1_b   = (const float*)d_in[4];
    const float* ln2_g   = (const float*)d_in[5];
    const float* ln2_b   = (const float*)d_in[6];
    const float* lnf_g   = (const float*)d_in[7];
    const float* lnf_b   = (const float*)d_in[8];
    const float* Wk      = (const float*)d_in[9];
    const float* Wv      = (const float*)d_in[10];
    const float* Wq      = (const float*)d_in[11];
    const float* Wo      = (const float*)d_in[12];
    const float* gate_w  = (const float*)d_in[13];
    const float* noise_w = (const float*)d_in[14];
    const float* fc_w    = (const float*)d_in[15];
    const float* fc_b    = (const float*)d_in[16];
    const float* proj_w  = (const float*)d_in[17];
    const float* proj_b  = (const float*)d_in[18];
    const float* noise   = (const float*)d_in[19];
    float* out = (float*)d_out;

    float *x, *lnf32, *kvb, *qb, *coef;
    bf16 *lnHi, *lnLo, *obHi, *obLo, *h1Hi, *h1Lo;
    bf16 *kvTH, *kvTL, *qTH, *qTL, *oTH, *oTL, *fcTH, *fcTL, *pjTH, *pjTL, *wteH, *wteL;
    cudaGetSymbolAddress((void**)&x,     g_x);
    cudaGetSymbolAddress((void**)&lnf32, g_lnf32);
    cudaGetSymbolAddress((void**)&kvb,   g_kv);
    cudaGetSymbolAddress((void**)&qb,    g_q);
    cudaGetSymbolAddress((void**)&coef,  g_coef);
    cudaGetSymbolAddress((void**)&lnHi,  g_lnHi);
    cudaGetSymbolAddress((void**)&lnLo,  g_lnLo);
    cudaGetSymbolAddress((void**)&obHi,  g_obHi);
    cudaGetSymbolAddress((void**)&obLo,  g_obLo);
    cudaGetSymbolAddress((void**)&h1Hi,  g_h1Hi);
    cudaGetSymbolAddress((void**)&h1Lo,  g_h1Lo);
    cudaGetSymbolAddress((void**)&kvTH,  g_kvTHi);
    cudaGetSymbolAddress((void**)&kvTL,  g_kvTLo);
    cudaGetSymbolAddress((void**)&qTH,   g_qTHi);
    cudaGetSymbolAddress((void**)&qTL,   g_qTLo);
    cudaGetSymbolAddress((void**)&oTH,   g_oTHi);
    cudaGetSymbolAddress((void**)&oTL,   g_oTLo);
    cudaGetSymbolAddress((void**)&fcTH,  g_fcTHi);
    cudaGetSymbolAddress((void**)&fcTL,  g_fcTLo);
    cudaGetSymbolAddress((void**)&pjTH,  g_pjTHi);
    cudaGetSymbolAddress((void**)&pjTL,  g_pjTLo);
    cudaGetSymbolAddress((void**)&wteH,  g_wteHi);
    cudaGetSymbolAddress((void**)&wteL,  g_wteLo);

    cudaFuncSetAttribute(mma_gemm<0>, cudaFuncAttributeMaxDynamicSharedMemorySize, GSM_TOTAL);
    cudaFuncSetAttribute(mma_gemm<1>, cudaFuncAttributeMaxDynamicSharedMemorySize, GSM_TOTAL);
    cudaFuncSetAttribute(mma_gemm<2>, cudaFuncAttributeMaxDynamicSharedMemorySize, GSM_TOTAL);
    cudaFuncSetAttribute(mma_gemm<3>, cudaFuncAttributeMaxDynamicSharedMemorySize, GSM_TOTAL);
    cudaFuncSetAttribute(attn_kernel, cudaFuncAttributeMaxDynamicSharedMemorySize, ATTN_SMEM);

    const size_t DxD = (size_t)DD * DD;
    dim3 trb(32, 8);
    dim3 trDD(DD / 32, DD / 32);
    dim3 trFD(FF / 32, DD / 32);   // src [768, 3072]
    dim3 trDF(DD / 32, FF / 32);   // src [3072, 768]

    // ---- weight prep ----
    {
        int n4 = VV * DD / 4;
        split_k<<<(n4 + 255) / 256, 256>>>(wte, wteH, wteL, n4);
        for (int l = 0; l < LL; l++) {
            tr_split<<<trDD, trb>>>(Wk + l * DxD, kvTH + (size_t)l * KV2 * DD,
                                    kvTL + (size_t)l * KV2 * DD, DD, DD, DD);
            tr_split<<<trDD, trb>>>(Wv + l * DxD,
                                    kvTH + (size_t)l * KV2 * DD + DxD,
                                    kvTL + (size_t)l * KV2 * DD + DxD, DD, DD, DD);
            for (int e = 0; e < EE; e++) {
                tr_split<<<trDD, trb>>>(Wq + ((size_t)l * EE + e) * DxD,
                                        qTH + (size_t)l * FF * DD + e * DxD,
                                        qTL + (size_t)l * FF * DD + e * DxD, DD, DD, DD);
                tr_split<<<trDD, trb>>>(Wo + ((size_t)l * EE + e) * DxD,
                                        oTH + (size_t)l * DD * FF + e * DD,
                                        oTL + (size_t)l * DD * FF + e * DD, DD, DD, FF);
            }
            tr_split<<<trFD, trb>>>(fc_w + (size_t)l * DD * FF,
                                    fcTH + (size_t)l * FF * DD,
                                    fcTL + (size_t)l * FF * DD, DD, FF, DD);
            tr_split<<<trDF, trb>>>(proj_w + (size_t)l * FF * DD,
                                    pjTH + (size_t)l * DD * FF,
                                    pjTL + (size_t)l * DD * FF, FF, DD, FF);
        }
    }

    embed_kernel<<<NN, 256>>>(idx, wte, wpe, x);

    // grid: x = row-blocks (fast), y = col-blocks (slow) -> B strip read once
    dim3 gKV(NN / 128, KV2 / 128);
    dim3 gQ(NN / 128, FF / 128);
    dim3 gO(NN / 128, DD / 128);
    dim3 gV(NN / 128, (VV + 127) / 128);
    dim3 gA(TT / 64, HH, BBATCH * EE);

    for (int l = 0; l < LL; l++) {
        ln_kernel<<<NN, 256>>>(x, ln1_g + l * DD, ln1_b + l * DD, lnf32, lnHi, lnLo);
        gate_kernel<<<NN, 128>>>(lnf32, gate_w + (size_t)l * DD * EE,
                                 noise_w + (size_t)l * DD * EE,
                                 noise + (size_t)l * NN * EE, coef);
        mma_gemm<0><<<gKV, 256, GSM_TOTAL>>>(lnHi, lnLo,
            kvTH + (size_t)l * KV2 * DD, kvTL + (size_t)l * KV2 * DD,
            kvb, nullptr, nullptr, nullptr, KV2, DD);
        mma_gemm<0><<<gQ, 256, GSM_TOTAL>>>(lnHi, lnLo,
            qTH + (size_t)l * FF * DD, qTL + (size_t)l * FF * DD,
            qb, nullptr, nullptr, nullptr, FF, DD);
        attn_kernel<<<gA, 256, ATTN_SMEM>>>(qb, kvb, coef, obHi, obLo);
        mma_gemm<2><<<gO, 256, GSM_TOTAL>>>(obHi, obLo,
            oTH + (size_t)l * DD * FF, oTL + (size_t)l * DD * FF,
            x, nullptr, nullptr, nullptr, DD, FF);
        ln_kernel<<<NN, 256>>>(x, ln2_g + l * DD, ln2_b + l * DD, lnf32, lnHi, lnLo);
        mma_gemm<1><<<gQ, 256, GSM_TOTAL>>>(lnHi, lnLo,
            fcTH + (size_t)l * FF * DD, fcTL + (size_t)l * FF * DD,
            nullptr, h1Hi, h1Lo, fc_b + (size_t)l * FF, FF, DD);
        mma_gemm<3><<<gO, 256, GSM_TOTAL>>>(h1Hi, h1Lo,
            pjTH + (size_t)l * DD * FF, pjTL + (size_t)l * DD * FF,
            x, nullptr, nullptr, proj_b + (size_t)l * DD, DD, FF);
    }

    ln_kernel<<<NN, 256>>>(x, lnf_g, lnf_b, lnf32, lnHi, lnLo);
    mma_gemm<0><<<gV, 256, GSM_TOTAL>>>(lnHi, lnLo, wteH, wteL,
                                        out, nullptr, nullptr, nullptr, VV, DD);
}

// round 5
// speedup vs baseline: 9.6118x; 1.1875x over previous
#include <cuda_runtime.h>
#include <cuda_bf16.h>
#include <math.h>
#include <stdint.h>

typedef __nv_bfloat16 bf16;
typedef unsigned long long u64;
typedef unsigned int u32;

#define BBATCH 2
#define TT 1024
#define DD 768
#define HH 12
#define EE 4
#define NN 2048
#define LL 2
#define VV 50257
#define FF 3072
#define KV2 1536

// ------------------- scratch (static device arrays) ------------------------
__device__ __align__(16) float g_x[NN * DD];
__device__ __align__(16) float g_lnf32[NN * DD];
__device__ __align__(16) bf16  g_lnHi[NN * DD];
__device__ __align__(16) bf16  g_lnLo[NN * DD];
__device__ __align__(16) float g_kv[NN * KV2];   // aliased as 2 bf16 planes
__device__ __align__(16) float g_q[NN * FF];     // aliased as 2 bf16 planes
__device__ __align__(16) bf16  g_obHi[NN * FF];
__device__ __align__(16) bf16  g_obLo[NN * FF];
__device__ __align__(16) bf16  g_h1Hi[NN * FF];
__device__ __align__(16) bf16  g_h1Lo[NN * FF];
__device__ float g_coef[NN * EE];

// transposed + split weights (B^T layout: [N][K] K-contiguous)
__device__ __align__(16) bf16 g_kvTHi[LL * KV2 * DD];
__device__ __align__(16) bf16 g_kvTLo[LL * KV2 * DD];
__device__ __align__(16) bf16 g_qTHi[LL * FF * DD];
__device__ __align__(16) bf16 g_qTLo[LL * FF * DD];
__device__ __align__(16) bf16 g_oTHi[LL * DD * FF];
__device__ __align__(16) bf16 g_oTLo[LL * DD * FF];
__device__ __align__(16) bf16 g_fcTHi[LL * FF * DD];
__device__ __align__(16) bf16 g_fcTLo[LL * FF * DD];
__device__ __align__(16) bf16 g_pjTHi[LL * DD * FF];
__device__ __align__(16) bf16 g_pjTLo[LL * DD * FF];
__device__ __align__(16) bf16 g_wteHi[VV * DD];
__device__ __align__(16) bf16 g_wteLo[VV * DD];

// ------------------- helpers ------------------------------------------------
__device__ __forceinline__ void split2(float v, bf16& h, bf16& l) {
    h = __float2bfloat16(v);
    l = __float2bfloat16(v - __bfloat162float(h));
}
__device__ __forceinline__ float geluf(float x) {
    float inner = 0.7978845608028654f * (x + 0.044715f * x * x * x);
    return 0.5f * x * (1.0f + tanhf(inner));
}
__device__ __forceinline__ u32 smem_u32(const void* p) {
    u32 a;
    asm("{ .reg .u64 t; cvta.to.shared.u64 t, %1; cvt.u32.u64 %0, t; }"
        : "=r"(a) : "l"(p));
    return a;
}

#define CP16(dst, src, n) \
    asm volatile("cp.async.cg.shared.global [%0], [%1], 16, %2;" \
                 :: "r"(dst), "l"(src), "r"(n) : "memory")
#define CP_COMMIT() asm volatile("cp.async.commit_group;" ::: "memory")
#define CP_WAIT1()  asm volatile("cp.async.wait_group 1;" ::: "memory")
#define CP_WAIT0()  asm volatile("cp.async.wait_group 0;" ::: "memory")

__device__ __forceinline__ void ldmx4(u32* r, u32 addr) {
    asm volatile("ldmatrix.sync.aligned.m8n8.x4.shared.b16 {%0,%1,%2,%3}, [%4];"
        : "=r"(r[0]), "=r"(r[1]), "=r"(r[2]), "=r"(r[3]) : "r"(addr));
}
__device__ __forceinline__ void ldmx4t(u32* r, u32 addr) {
    asm volatile("ldmatrix.sync.aligned.m8n8.x4.trans.shared.b16 {%0,%1,%2,%3}, [%4];"
        : "=r"(r[0]), "=r"(r[1]), "=r"(r[2]), "=r"(r[3]) : "r"(addr));
}
__device__ __forceinline__ void mma16816(float* c, const u32* a, const u32* b) {
    asm volatile("mma.sync.aligned.m16n8k16.row.col.f32.bf16.bf16.f32 "
        "{%0,%1,%2,%3}, {%4,%5,%6,%7}, {%8,%9}, {%0,%1,%2,%3};"
        : "+f"(c[0]), "+f"(c[1]), "+f"(c[2]), "+f"(c[3])
        : "r"(a[0]), "r"(a[1]), "r"(a[2]), "r"(a[3]), "r"(b[0]), "r"(b[1]));
}
__device__ __forceinline__ u32 pkbf(float a, float b) {
    __nv_bfloat162 h = __floats2bfloat162_rn(a, b);
    return *(u32*)&h;
}

// ------------------- small kernels ------------------------------------------
__global__ void embed_kernel(const int* __restrict__ idx,
                             const float* __restrict__ wte,
                             const float* __restrict__ wpe,
                             float* __restrict__ x) {
    int n = blockIdx.x;
    int t = n % TT;
    int tok = idx[n];
    const float* we = wte + (size_t)tok * DD;
    const float* wp = wpe + (size_t)t * DD;
    float* xr = x + (size_t)n * DD;
    for (int d = threadIdx.x; d < DD; d += blockDim.x)
        xr[d] = we[d] + wp[d];
}

__global__ void ln_kernel(const float* __restrict__ x,
                          const float* __restrict__ g,
                          const float* __restrict__ b,
                          float* __restrict__ y,
                          bf16* __restrict__ yhi, bf16* __restrict__ ylo) {
    int r = blockIdx.x;
    int tid = threadIdx.x;   // 256
    const float* xr = x + (size_t)r * DD;
    float v0 = xr[tid], v1 = xr[tid + 256], v2 = xr[tid + 512];

    __shared__ float red[8];
    float s = v0 + v1 + v2;
    #pragma unroll
    for (int o = 16; o > 0; o >>= 1) s += __shfl_xor_sync(0xffffffffu, s, o);
    if ((tid & 31) == 0) red[tid >> 5] = s;
    __syncthreads();
    float tot = 0.f;
    #pragma unroll
    for (int i = 0; i < 8; i++) tot += red[i];
    float mean = tot * (1.0f / DD);
    __syncthreads();

    float c0 = v0 - mean, c1 = v1 - mean, c2 = v2 - mean;
    float sq = c0 * c0 + c1 * c1 + c2 * c2;
    #pragma unroll
    for (int o = 16; o > 0; o >>= 1) sq += __shfl_xor_sync(0xffffffffu, sq, o);
    if ((tid & 31) == 0) red[tid >> 5] = sq;
    __syncthreads();
    float var = 0.f;
    #pragma unroll
    for (int i = 0; i < 8; i++) var += red[i];
    var *= (1.0f / DD);
    float rstd = rsqrtf(var + 1e-5f);

    size_t base = (size_t)r * DD;
    #pragma unroll
    for (int p = 0; p < 3; p++) {
        int d = tid + p * 256;
        float cv = (p == 0 ? c0 : (p == 1 ? c1 : c2));
        float o = cv * rstd * g[d] + b[d];
        y[base + d] = o;
        bf16 hv, lv; split2(o, hv, lv);
        yhi[base + d] = hv; ylo[base + d] = lv;
    }
}

__device__ __forceinline__ float softplusf(float x) {
    if (x > 20.f) return x;
    if (x < -20.f) return expf(x);
    return log1pf(expf(x));
}

__global__ void gate_kernel(const float* __restrict__ ln,
                            const float* __restrict__ gw,
                            const float* __restrict__ nw,
                            const float* __restrict__ noise,
                            float* __restrict__ coef) {
    int r = blockIdx.x;
    int tid = threadIdx.x; // 128
    const float* xr = ln + (size_t)r * DD;
    float acc[8] = {0.f, 0.f, 0.f, 0.f, 0.f, 0.f, 0.f, 0.f};
    for (int d = tid; d < DD; d += 128) {
        float xv = xr[d];
        #pragma unroll
        for (int e = 0; e < EE; e++) {
            acc[e]     += xv * gw[d * EE + e];
            acc[4 + e] += xv * nw[d * EE + e];
        }
    }
    __shared__ float part[8 * 128];
    #pragma unroll
    for (int e = 0; e < 8; e++) part[e * 128 + tid] = acc[e];
    __syncthreads();
    __shared__ float red[8];
    if (tid < 8) {
        float s = 0.f;
        for (int i = 0; i < 128; i++) s += part[tid * 128 + i];
        red[tid] = s;
    }
    __syncthreads();
    if (tid == 0) {
        float lg[4];
        #pragma unroll
        for (int e = 0; e < EE; e++)
            lg[e] = red[e] + noise[(size_t)r * EE + e] * softplusf(red[4 + e]);
        int i1 = 0;
        #pragma unroll
        for (int e = 1; e < EE; e++) if (lg[e] > lg[i1]) i1 = e;
        int i2 = -1;
        #pragma unroll
        for (int e = 0; e < EE; e++) {
            if (e == i1) continue;
            if (i2 < 0 || lg[e] > lg[i2]) i2 = e;
        }
        float m = lg[i1];
        float e1 = expf(lg[i1] - m), e2 = expf(lg[i2] - m);
        float inv = 1.f / (e1 + e2);
        float c[4] = {0.f, 0.f, 0.f, 0.f};
        c[i1] = e1 * inv;
        c[i2] = e2 * inv;
        #pragma unroll
        for (int e = 0; e < EE; e++) coef[(size_t)r * EE + e] = c[e];
    }
}

// transpose fp32 [K,N] -> split bf16 [N, ld] (dst[n*ld + k])
__global__ void tr_split(const float* __restrict__ src, bf16* __restrict__ dhi,
                         bf16* __restrict__ dlo, int K, int N, int ld) {
    __shared__ float t[32][33];
    int n0 = blockIdx.x * 32, k0 = blockIdx.y * 32;
    int tx = threadIdx.x, ty = threadIdx.y; // 32x8
    #pragma unroll
    for (int i = 0; i < 4; i++)
        t[ty + 8 * i][tx] = src[(size_t)(k0 + ty + 8 * i) * N + n0 + tx];
    __syncthreads();
    #pragma unroll
    for (int i = 0; i < 4; i++) {
        float v = t[tx][ty + 8 * i];
        bf16 hv, lv; split2(v, hv, lv);
        size_t o = (size_t)(n0 + ty + 8 * i) * ld + k0 + tx;
        dhi[o] = hv; dlo[o] = lv;
    }
}

// elementwise fp32 -> split bf16 (for wte)
__global__ void split_k(const float* __restrict__ s, bf16* __restrict__ hi,
                        bf16* __restrict__ lo, int n4) {
    int i = blockIdx.x * 256 + threadIdx.x;
    if (i >= n4) return;
    float4 v = ((const float4*)s)[i];
    bf16 h0, l0, h1, l1, h2, l2, h3, l3;
    split2(v.x, h0, l0); split2(v.y, h1, l1);
    split2(v.z, h2, l2); split2(v.w, h3, l3);
    __nv_bfloat162* H = (__nv_bfloat162*)hi;
    __nv_bfloat162* L = (__nv_bfloat162*)lo;
    H[2 * i]     = __nv_bfloat162(h0, h1);
    H[2 * i + 1] = __nv_bfloat162(h2, h3);
    L[2 * i]     = __nv_bfloat162(l0, l1);
    L[2 * i + 1] = __nv_bfloat162(l2, l3);
}

// ------------------- mma.sync split-bf16 GEMM --------------------------------
// C[2048, N] = (Ahi+Alo)[2048, K] x (Bhi+Blo)^T, B stored [N][K] K-contig.
// EPI 0: Cf=v  1: gelu(v+bias)->Chi/Clo  2: Cf+=v  3: Cf+=v+bias  4: v->Chi/Clo
#define GLDS 40                 // smem row stride (bf16 elems), 80 bytes
#define GMAT (128 * GLDS * 2)   // 10240 bytes per matrix
#define GSTG (4 * GMAT)         // 40960 per stage
#define GSM_TOTAL (2 * GSTG)    // 81920

template <int EPI>
__global__ __launch_bounds__(256)
void mma_gemm(const bf16* __restrict__ Ahi, const bf16* __restrict__ Alo,
              const bf16* __restrict__ Bhi, const bf16* __restrict__ Blo,
              float* __restrict__ Cf, bf16* __restrict__ Chi, bf16* __restrict__ Clo,
              const float* __restrict__ bias, int N, int K) {
    extern __shared__ char smdyn[];
    const u32 sb = smem_u32(smdyn);
    const int tid = threadIdx.x, wid = tid >> 5, lane = tid & 31;
    const int row0 = blockIdx.x * 128, col0 = blockIdx.y * 128;
    const int warp_m = (wid & 3) * 32, warp_n = (wid >> 2) * 64;

    float c[2][8][4];
    #pragma unroll
    for (int mt = 0; mt < 2; mt++)
        #pragma unroll
        for (int nt = 0; nt < 8; nt++)
            #pragma unroll
            for (int i = 0; i < 4; i++) c[mt][nt][i] = 0.f;

    const int nch = K >> 5;

    auto load_stage = [&](int s, int k0) {
        u32 st = sb + s * GSTG;
        #pragma unroll
        for (int i = 0; i < 2; i++) {
            int idx = tid + (i << 8);
            int r = idx >> 2, ch = idx & 3;
            u32 doff = (u32)(r * GLDS + ch * 8) * 2;
            size_t ga = (size_t)(row0 + r) * K + k0 + ch * 8;
            CP16(st + doff,        Ahi + ga, 16);
            CP16(st + GMAT + doff, Alo + ga, 16);
            int gn = col0 + r;
            int pr = (gn < N) ? 16 : 0;
            int gnc = (gn < N) ? gn : 0;
            size_t gb = (size_t)gnc * K + k0 + ch * 8;
            CP16(st + 2 * GMAT + doff, Bhi + gb, pr);
            CP16(st + 3 * GMAT + doff, Blo + gb, pr);
        }
        CP_COMMIT();
    };

    load_stage(0, 0);
    for (int kc = 0; kc < nch; kc++) {
        if (kc + 1 < nch) { load_stage((kc + 1) & 1, (kc + 1) << 5); CP_WAIT1(); }
        else CP_WAIT0();
        __syncthreads();

        u32 st = sb + (kc & 1) * GSTG;
        #pragma unroll
        for (int ks = 0; ks < 2; ks++) {
            u32 ah[2][4], al[2][4];
            #pragma unroll
            for (int mt = 0; mt < 2; mt++) {
                u32 ro = (u32)(warp_m + mt * 16 + (lane & 15)) * (GLDS * 2)
                       + (u32)(ks * 16 + ((lane >> 4) << 3)) * 2;
                ldmx4(ah[mt], st + ro);
                ldmx4(al[mt], st + GMAT + ro);
            }
            #pragma unroll
            for (int j = 0; j < 4; j++) {
                u32 bh[4], bl[4];
                u32 ro = (u32)(warp_n + j * 16 + ((lane >> 4) << 3) + (lane & 7)) * (GLDS * 2)
                       + (u32)(ks * 16 + (((lane >> 3) & 1) << 3)) * 2;
                ldmx4(bh, st + 2 * GMAT + ro);
                ldmx4(bl, st + 3 * GMAT + ro);
                #pragma unroll
                for (int mt = 0; mt < 2; mt++) {
                    mma16816(c[mt][2 * j],     ah[mt], bh);
                    mma16816(c[mt][2 * j],     ah[mt], bl);
                    mma16816(c[mt][2 * j],     al[mt], bh);
                    mma16816(c[mt][2 * j + 1], ah[mt], bh + 2);
                    mma16816(c[mt][2 * j + 1], ah[mt], bl + 2);
                    mma16816(c[mt][2 * j + 1], al[mt], bh + 2);
                }
            }
        }
        __syncthreads();
    }

    #pragma unroll
    for (int mt = 0; mt < 2; mt++) {
        int rb = row0 + warp_m + mt * 16 + (lane >> 2);
        #pragma unroll
        for (int nt = 0; nt < 8; nt++) {
            int cc = col0 + warp_n + nt * 8 + (lane & 3) * 2;
            float* cr = c[mt][nt];
            #pragma unroll
            for (int h = 0; h < 2; h++) {
                int r = rb + h * 8;
                #pragma unroll
                for (int q = 0; q < 2; q++) {
                    int col = cc + q;
                    float v = cr[h * 2 + q];
                    size_t off = (size_t)r * N + col;
                    if (EPI == 0) {
                        if (col < N) Cf[off] = v;
                    } else if (EPI == 1) {
                        float gv = geluf(v + bias[col]);
                        bf16 hv, lv; split2(gv, hv, lv);
                        Chi[off] = hv; Clo[off] = lv;
                    } else if (EPI == 2) {
                        Cf[off] += v;
                    } else if (EPI == 3) {
                        Cf[off] += v + bias[col];
                    } else {
                        bf16 hv, lv; split2(v, hv, lv);
                        Chi[off] = hv; Clo[off] = lv;
                    }
                }
            }
        }
    }
}

// ------------------- mma.sync flash attention --------------------------------
// grid = (T/128, H, B*E), 256 threads (8 warps x 16 q rows). Split-bf16 3-pass
// for QK^T and PV. Inputs: split-bf16 q [N,FF], kv [N,KV2]; output: coef-scaled
// split-bf16 ob [N,FF].
#define AST 72                          // smem row stride (bf16 elems)
#define AQB (128 * AST * 2)             // 18432 bytes (one Q matrix)
#define AKB (64 * AST * 2)              // 9216 bytes (one K/V matrix)
#define AKVSTG (4 * AKB)                // 36864 per stage
#define A_SMEM (2 * AQB + 2 * AKVSTG)   // 110592

__global__ __launch_bounds__(256)
void attn_mma(const bf16* __restrict__ qHi, const bf16* __restrict__ qLo,
              const bf16* __restrict__ kvHi, const bf16* __restrict__ kvLo,
              const float* __restrict__ coef,
              bf16* __restrict__ oHi, bf16* __restrict__ oLo) {
    extern __shared__ char smdyn[];
    const u32 sb = smem_u32(smdyn);
    const int tid = threadIdx.x, wid = tid >> 5, lane = tid & 31;
    const int q0 = blockIdx.x * 128, hh = blockIdx.y;
    const int b = blockIdx.z >> 2, e = blockIdx.z & 3;
    const u32 QH = sb, QL = sb + AQB;
    const size_t qcol = (size_t)e * DD + (size_t)hh * 64;

    // ---- issue Q loads + first KV stage (one cp.async group) ----
    #pragma unroll
    for (int i = 0; i < 4; i++) {
        int idx = tid + (i << 8);
        int r = idx >> 3, ch = idx & 7;
        size_t g = (size_t)(b * TT + q0 + r) * FF + qcol + ch * 8;
        u32 doff = (u32)(r * AST + ch * 8) * 2;
        CP16(QH + doff, qHi + g, 16);
        CP16(QL + doff, qLo + g, 16);
    }
    auto load_kv = [&](int s, int k0t) {
        u32 st = sb + 2 * AQB + s * AKVSTG;
        #pragma unroll
        for (int i = 0; i < 8; i++) {
            int idx = tid + (i << 8);
            int mat = idx >> 9;            // 0:KH 1:KL 2:VH 3:VL
            int r = (idx >> 3) & 63, ch = idx & 7;
            const bf16* src = (mat & 1) ? kvLo : kvHi;
            size_t g = (size_t)(b * TT + k0t + r) * KV2 + (size_t)(mat >> 1) * DD
                     + hh * 64 + ch * 8;
            CP16(st + mat * AKB + (u32)(r * AST + ch * 8) * 2, src + g, 16);
        }
        CP_COMMIT();
    };
    load_kv(0, 0);

    float o[8][4];
    #pragma unroll
    for (int nt = 0; nt < 8; nt++)
        #pragma unroll
        for (int i = 0; i < 4; i++) o[nt][i] = 0.f;
    float mrow[2] = {-1e30f, -1e30f}, lrow[2] = {0.f, 0.f};
    u32 qh[4][4], ql[4][4];

    const int nkt = blockIdx.x * 2 + 2;
    const int warp_r0 = q0 + wid * 16;
    const int rowg0 = warp_r0 + (lane >> 2), rowg1 = rowg0 + 8;

    for (int kt = 0; kt < nkt; kt++) {
        const int k0t = kt * 64;
        if (kt + 1 < nkt) { load_kv((kt + 1) & 1, k0t + 64); CP_WAIT1(); }
        else CP_WAIT0();
        __syncthreads();

        if (kt == 0) {  // hoist Q fragments into registers (smem now valid)
            #pragma unroll
            for (int ks = 0; ks < 4; ks++) {
                u32 ro = (u32)(wid * 16 + (lane & 15)) * (AST * 2)
                       + (u32)(ks * 16 + ((lane >> 4) << 3)) * 2;
                ldmx4(qh[ks], QH + ro);
                ldmx4(ql[ks], QL + ro);
            }
        }

        if (k0t <= warp_r0 + 15) {   // warp tile not fully masked
            const u32 KH = sb + 2 * AQB + (kt & 1) * AKVSTG;
            const u32 KL = KH + AKB, VH = KH + 2 * AKB, VL = KH + 3 * AKB;

            float s[8][4];
            #pragma unroll
            for (int nt = 0; nt < 8; nt++)
                #pragma unroll
                for (int i = 0; i < 4; i++) s[nt][i] = 0.f;

            // ---- S = Q K^T (3-pass split) ----
            #pragma unroll
            for (int ks = 0; ks < 4; ks++) {
                #pragma unroll
                for (int j = 0; j < 4; j++) {
                    u32 bh[4], bl[4];
                    u32 ro = (u32)(j * 16 + ((lane >> 4) << 3) + (lane & 7)) * (AST * 2)
                           + (u32)(ks * 16 + (((lane >> 3) & 1) << 3)) * 2;
                    ldmx4(bh, KH + ro);
                    ldmx4(bl, KL + ro);
                    mma16816(s[2 * j],     qh[ks], bh);
                    mma16816(s[2 * j],     qh[ks], bl);
                    mma16816(s[2 * j],     ql[ks], bh);
                    mma16816(s[2 * j + 1], qh[ks], bh + 2);
                    mma16816(s[2 * j + 1], qh[ks], bl + 2);
                    mma16816(s[2 * j + 1], ql[ks], bh + 2);
                }
            }

            // ---- scale + causal mask ----
            const bool diag = (k0t + 63 > warp_r0);
            #pragma unroll
            for (int nt = 0; nt < 8; nt++) {
                int cb = k0t + nt * 8 + (lane & 3) * 2;
                #pragma unroll
                for (int q = 0; q < 2; q++) {
                    int col = cb + q;
                    s[nt][q]     = (diag && col > rowg0) ? -1e30f : s[nt][q] * 0.125f;
                    s[nt][2 + q] = (diag && col > rowg1) ? -1e30f : s[nt][2 + q] * 0.125f;
                }
            }

            // ---- online softmax (rows rowg0 / rowg1) ----
            float ml0 = -1e30f, ml1 = -1e30f;
            #pragma unroll
            for (int nt = 0; nt < 8; nt++) {
                ml0 = fmaxf(ml0, fmaxf(s[nt][0], s[nt][1]));
                ml1 = fmaxf(ml1, fmaxf(s[nt][2], s[nt][3]));
            }
            ml0 = fmaxf(ml0, __shfl_xor_sync(0xffffffffu, ml0, 1));
            ml0 = fmaxf(ml0, __shfl_xor_sync(0xffffffffu, ml0, 2));
            ml1 = fmaxf(ml1, __shfl_xor_sync(0xffffffffu, ml1, 1));
            ml1 = fmaxf(ml1, __shfl_xor_sync(0xffffffffu, ml1, 2));
            float mn0 = fmaxf(mrow[0], ml0), mn1 = fmaxf(mrow[1], ml1);
            float cr0 = __expf(mrow[0] - mn0), cr1 = __expf(mrow[1] - mn1);
            float rs0 = 0.f, rs1 = 0.f;
            #pragma unroll
            for (int nt = 0; nt < 8; nt++) {
                s[nt][0] = __expf(s[nt][0] - mn0); rs0 += s[nt][0];
                s[nt][1] = __expf(s[nt][1] - mn0); rs0 += s[nt][1];
                s[nt][2] = __expf(s[nt][2] - mn1); rs1 += s[nt][2];
                s[nt][3] = __expf(s[nt][3] - mn1); rs1 += s[nt][3];
            }
            rs0 += __shfl_xor_sync(0xffffffffu, rs0, 1);
            rs0 += __shfl_xor_sync(0xffffffffu, rs0, 2);
            rs1 += __shfl_xor_sync(0xffffffffu, rs1, 1);
            rs1 += __shfl_xor_sync(0xffffffffu, rs1, 2);
            lrow[0] = lrow[0] * cr0 + rs0;
            lrow[1] = lrow[1] * cr1 + rs1;
            mrow[0] = mn0; mrow[1] = mn1;
            #pragma unroll
            for (int nt = 0; nt < 8; nt++) {
                o[nt][0] *= cr0; o[nt][1] *= cr0;
                o[nt][2] *= cr1; o[nt][3] *= cr1;
            }

            // ---- O += P V (3-pass split; P frags built from s) ----
            #pragma unroll
            for (int t = 0; t < 4; t++) {
                u32 pah[4], pal[4];
                #pragma unroll
                for (int half = 0; half < 2; half++) {   // s tiles 2t, 2t+1
                    float* sp = s[2 * t + half];
                    bf16 h0, l0, h1, l1, h2, l2, h3, l3;
                    split2(sp[0], h0, l0); split2(sp[1], h1, l1);
                    split2(sp[2], h2, l2); split2(sp[3], h3, l3);
                    pah[2 * half]     = pkbf(__bfloat162float(h0), __bfloat162float(h1));
                    pah[2 * half + 1] = pkbf(__bfloat162float(h2), __bfloat162float(h3));
                    pal[2 * half]     = pkbf(__bfloat162float(l0), __bfloat162float(l1));
                    pal[2 * half + 1] = pkbf(__bfloat162float(l2), __bfloat162float(l3));
                }
                // reorder: pah = {a0(k0-7 r), a1(k0-7 r+8), a2(k8-15 r), a3(k8-15 r+8)}
                u32 a_h[4] = {pah[0], pah[1], pah[2], pah[3]};
                u32 a_l[4] = {pal[0], pal[1], pal[2], pal[3]};
                #pragma unroll
                for (int j = 0; j < 4; j++) {
                    u32 vh[4], vl[4];
                    int m = lane >> 3;
                    u32 rowv = (u32)(t * 16 + ((m & 1) << 3) + (lane & 7));
                    u32 colv = (u32)(j * 16 + ((m >> 1) << 3));
                    u32 ro = (rowv * AST + colv) * 2;
                    ldmx4t(vh, VH + ro);
                    ldmx4t(vl, VL + ro);
                    mma16816(o[2 * j],     a_h, vh);
                    mma16816(o[2 * j],     a_h, vl);
                    mma16816(o[2 * j],     a_l, vh);
                    mma16816(o[2 * j + 1], a_h, vh + 2);
                    mma16816(o[2 * j + 1], a_h, vl + 2);
                    mma16816(o[2 * j + 1], a_l, vh + 2);
                }
            }
        }
        __syncthreads();
    }

    // ---- epilogue ----
    size_t rg0 = (size_t)b * TT + rowg0, rg1 = (size_t)b * TT + rowg1;
    float inv0 = coef[rg0 * EE + e] / lrow[0];
    float inv1 = coef[rg1 * EE + e] / lrow[1];
    #pragma unroll
    for (int nt = 0; nt < 8; nt++) {
        int cb = nt * 8 + (lane & 3) * 2;
        #pragma unroll
        for (int q = 0; q < 2; q++) {
            float v0 = o[nt][q] * inv0;
            float v1 = o[nt][2 + q] * inv1;
            bf16 h, l;
            split2(v0, h, l);
            oHi[rg0 * FF + qcol + cb + q] = h;
            oLo[rg0 * FF + qcol + cb + q] = l;
            split2(v1, h, l);
            oHi[rg1 * FF + qcol + cb + q] = h;
            oLo[rg1 * FF + qcol + cb + q] = l;
        }
    }
}

// ------------------- host ----------------------------------------------------
extern "C" void kernel_launch(void* const* d_in, const int* in_sizes, int n_in,
                              void* d_out, int out_size) {
    const int*   idx     = (const int*)  d_in[0];
    const float* wte     = (const float*)d_in[1];
    const float* wpe     = (const float*)d_in[2];
    const float* ln1_g   = (const float*)d_in[3];
    const float* ln1_b   = (const float*)d_in[4];
    const float* ln2_g   = (const float*)d_in[5];
    const float* ln2_b   = (const float*)d_in[6];
    const float* lnf_g   = (const float*)d_in[7];
    const float* lnf_b   = (const float*)d_in[8];
    const float* Wk      = (const float*)d_in[9];
    const float* Wv      = (const float*)d_in[10];
    const float* Wq      = (const float*)d_in[11];
    const float* Wo      = (const float*)d_in[12];
    const float* gate_w  = (const float*)d_in[13];
    const float* noise_w = (const float*)d_in[14];
    const float* fc_w    = (const float*)d_in[15];
    const float* fc_b    = (const float*)d_in[16];
    const float* proj_w  = (const float*)d_in[17];
    const float* proj_b  = (const float*)d_in[18];
    const float* noise   = (const float*)d_in[19];
    float* out = (float*)d_out;

    float *x, *lnf32, *kvb, *qb, *coef;
    bf16 *lnHi, *lnLo, *obHi, *obLo, *h1Hi, *h1Lo;
    bf16 *kvTH, *kvTL, *qTH, *qTL, *oTH, *oTL, *fcTH, *fcTL, *pjTH, *pjTL, *wteH, *wteL;
    cudaGetSymbolAddress((void**)&x,     g_x);
    cudaGetSymbolAddress((void**)&lnf32, g_lnf32);
    cudaGetSymbolAddress((void**)&kvb,   g_kv);
    cudaGetSymbolAddress((void**)&qb,    g_q);
    cudaGetSymbolAddress((void**)&coef,  g_coef);
    cudaGetSymbolAddress((void**)&lnHi,  g_lnHi);
    cudaGetSymbolAddress((void**)&lnLo,  g_lnLo);
    cudaGetSymbolAddress((void**)&obHi,  g_obHi);
    cudaGetSymbolAddress((void**)&obLo,  g_obLo);
    cudaGetSymbolAddress((void**)&h1Hi,  g_h1Hi);
    cudaGetSymbolAddress((void**)&h1Lo,  g_h1Lo);
    cudaGetSymbolAddress((void**)&kvTH,  g_kvTHi);
    cudaGetSymbolAddress((void**)&kvTL,  g_kvTLo);
    cudaGetSymbolAddress((void**)&qTH,   g_qTHi);
    cudaGetSymbolAddress((void**)&qTL,   g_qTLo);
    cudaGetSymbolAddress((void**)&oTH,   g_oTHi);
    cudaGetSymbolAddress((void**)&oTL,   g_oTLo);
    cudaGetSymbolAddress((void**)&fcTH,  g_fcTHi);
    cudaGetSymbolAddress((void**)&fcTL,  g_fcTLo);
    cudaGetSymbolAddress((void**)&pjTH,  g_pjTHi);
    cudaGetSymbolAddress((void**)&pjTL,  g_pjTLo);
    cudaGetSymbolAddress((void**)&wteH,  g_wteHi);
    cudaGetSymbolAddress((void**)&wteL,  g_wteLo);

    // alias fp32 scratch as split-bf16 planes
    bf16* kvHi = (bf16*)kvb;
    bf16* kvLo = kvHi + (size_t)NN * KV2;
    bf16* qHi  = (bf16*)qb;
    bf16* qLo  = qHi + (size_t)NN * FF;

    cudaFuncSetAttribute(mma_gemm<0>, cudaFuncAttributeMaxDynamicSharedMemorySize, GSM_TOTAL);
    cudaFuncSetAttribute(mma_gemm<1>, cudaFuncAttributeMaxDynamicSharedMemorySize, GSM_TOTAL);
    cudaFuncSetAttribute(mma_gemm<2>, cudaFuncAttributeMaxDynamicSharedMemorySize, GSM_TOTAL);
    cudaFuncSetAttribute(mma_gemm<3>, cudaFuncAttributeMaxDynamicSharedMemorySize, GSM_TOTAL);
    cudaFuncSetAttribute(mma_gemm<4>, cudaFuncAttributeMaxDynamicSharedMemorySize, GSM_TOTAL);
    cudaFuncSetAttribute(attn_mma,    cudaFuncAttributeMaxDynamicSharedMemorySize, A_SMEM);

    const size_t DxD = (size_t)DD * DD;
    dim3 trb(32, 8);
    dim3 trDD(DD / 32, DD / 32);
    dim3 trFD(FF / 32, DD / 32);
    dim3 trDF(DD / 32, FF / 32);

    // ---- weight prep ----
    {
        int n4 = VV * DD / 4;
        split_k<<<(n4 + 255) / 256, 256>>>(wte, wteH, wteL, n4);
        for (int l = 0; l < LL; l++) {
            tr_split<<<trDD, trb>>>(Wk + l * DxD, kvTH + (size_t)l * KV2 * DD,
                                    kvTL + (size_t)l * KV2 * DD, DD, DD, DD);
            tr_split<<<trDD, trb>>>(Wv + l * DxD,
                                    kvTH + (size_t)l * KV2 * DD + DxD,
                                    kvTL + (size_t)l * KV2 * DD + DxD, DD, DD, DD);
            for (int e = 0; e < EE; e++) {
                tr_split<<<trDD, trb>>>(Wq + ((size_t)l * EE + e) * DxD,
                                        qTH + (size_t)l * FF * DD + e * DxD,
                                        qTL + (size_t)l * FF * DD + e * DxD, DD, DD, DD);
                tr_split<<<trDD, trb>>>(Wo + ((size_t)l * EE + e) * DxD,
                                        oTH + (size_t)l * DD * FF + e * DD,
                                        oTL + (size_t)l * DD * FF + e * DD, DD, DD, FF);
            }
            tr_split<<<trFD, trb>>>(fc_w + (size_t)l * DD * FF,
                                    fcTH + (size_t)l * FF * DD,
                                    fcTL + (size_t)l * FF * DD, DD, FF, DD);
            tr_split<<<trDF, trb>>>(proj_w + (size_t)l * FF * DD,
                                    pjTH + (size_t)l * DD * FF,
                                    pjTL + (size_t)l * DD * FF, FF, DD, FF);
        }
    }

    embed_kernel<<<NN, 256>>>(idx, wte, wpe, x);

    dim3 gKV(NN / 128, KV2 / 128);
    dim3 gQ(NN / 128, FF / 128);
    dim3 gO(NN / 128, DD / 128);
    dim3 gV(NN / 128, (VV + 127) / 128);
    dim3 gA(TT / 128, HH, BBATCH * EE);

    for (int l = 0; l < LL; l++) {
        ln_kernel<<<NN, 256>>>(x, ln1_g + l * DD, ln1_b + l * DD, lnf32, lnHi, lnLo);
        gate_kernel<<<NN, 128>>>(lnf32, gate_w + (size_t)l * DD * EE,
                                 noise_w + (size_t)l * DD * EE,
                                 noise + (size_t)l * NN * EE, coef);
        mma_gemm<4><<<gKV, 256, GSM_TOTAL>>>(lnHi, lnLo,
            kvTH + (size_t)l * KV2 * DD, kvTL + (size_t)l * KV2 * DD,
            nullptr, kvHi, kvLo, nullptr, KV2, DD);
        mma_gemm<4><<<gQ, 256, GSM_TOTAL>>>(lnHi, lnLo,
            qTH + (size_t)l * FF * DD, qTL + (size_t)l * FF * DD,
            nullptr, qHi, qLo, nullptr, FF, DD);
        attn_mma<<<gA, 256, A_SMEM>>>(qHi, qLo, kvHi, kvLo, coef, obHi, obLo);
        mma_gemm<2><<<gO, 256, GSM_TOTAL>>>(obHi, obLo,
            oTH + (size_t)l * DD * FF, oTL + (size_t)l * DD * FF,
            x, nullptr, nullptr, nullptr, DD, FF);
        ln_kernel<<<NN, 256>>>(x, ln2_g + l * DD, ln2_b + l * DD, lnf32, lnHi, lnLo);
        mma_gemm<1><<<gQ, 256, GSM_TOTAL>>>(lnHi, lnLo,
            fcTH + (size_t)l * FF * DD, fcTL + (size_t)l * FF * DD,
            nullptr, h1Hi, h1Lo, fc_b + (size_t)l * FF, FF, DD);
        mma_gemm<3><<<gO, 256, GSM_TOTAL>>>(h1Hi, h1Lo,
            pjTH + (size_t)l * DD * FF, pjTL + (size_t)l * DD * FF,
            x, nullptr, nullptr, proj_b + (size_t)l * DD, DD, FF);
    }

    ln_kernel<<<NN, 256>>>(x, lnf_g, lnf_b, lnf32, lnHi, lnLo);
    mma_gemm<0><<<gV, 256, GSM_TOTAL>>>(lnHi, lnLo, wteH, wteL,
                                        out, nullptr, nullptr, nullptr, VV, DD);
}

// round 6
// speedup vs baseline: 10.5588x; 1.0985x over previous
#include <cuda_runtime.h>
#include <cuda_bf16.h>
#include <math.h>
#include <stdint.h>

typedef __nv_bfloat16 bf16;
typedef unsigned long long u64;
typedef unsigned int u32;

#define BBATCH 2
#define TT 1024
#define DD 768
#define HH 12
#define EE 4
#define NN 2048
#define LL 2
#define VV 50257
#define FF 3072
#define QKVW 4608      // K(768) + V(768) + Q(4*768)

// ------------------- scratch (static device arrays) ------------------------
__device__ __align__(16) float g_x[NN * DD];
__device__ __align__(16) bf16  g_lnHi[NN * DD];
__device__ __align__(16) bf16  g_lnLo[NN * DD];
__device__ __align__(16) bf16  g_qkvHi[NN * QKVW];
__device__ __align__(16) bf16  g_qkvLo[NN * QKVW];
__device__ __align__(16) bf16  g_obHi[NN * FF];
__device__ __align__(16) bf16  g_obLo[NN * FF];
__device__ __align__(16) bf16  g_h1Hi[NN * FF];
__device__ __align__(16) bf16  g_h1Lo[NN * FF];
__device__ __align__(16) float g_part[3 * NN * DD];
__device__ float g_coef[NN * EE];

// packed transposed+split weights
__device__ __align__(16) bf16 g_qkvTHi[LL * QKVW * DD];
__device__ __align__(16) bf16 g_qkvTLo[LL * QKVW * DD];
__device__ __align__(16) bf16 g_oTHi[LL * DD * FF];
__device__ __align__(16) bf16 g_oTLo[LL * DD * FF];
__device__ __align__(16) bf16 g_fcTHi[LL * FF * DD];
__device__ __align__(16) bf16 g_fcTLo[LL * FF * DD];
__device__ __align__(16) bf16 g_pjTHi[LL * DD * FF];
__device__ __align__(16) bf16 g_pjTLo[LL * DD * FF];
__device__ __align__(16) bf16 g_wteHi[VV * DD];
__device__ __align__(16) bf16 g_wteLo[VV * DD];

// ------------------- helpers ------------------------------------------------
__device__ __forceinline__ void split2(float v, bf16& h, bf16& l) {
    h = __float2bfloat16(v);
    l = __float2bfloat16(v - __bfloat162float(h));
}
__device__ __forceinline__ float geluf(float x) {
    float inner = 0.7978845608028654f * (x + 0.044715f * x * x * x);
    return 0.5f * x * (1.0f + tanhf(inner));
}
__device__ __forceinline__ u32 smem_u32(const void* p) {
    u32 a;
    asm("{ .reg .u64 t; cvta.to.shared.u64 t, %1; cvt.u32.u64 %0, t; }"
        : "=r"(a) : "l"(p));
    return a;
}

#define CP16(dst, src, n) \
    asm volatile("cp.async.cg.shared.global [%0], [%1], 16, %2;" \
                 :: "r"(dst), "l"(src), "r"(n) : "memory")
#define CP_COMMIT() asm volatile("cp.async.commit_group;" ::: "memory")
#define CP_WAIT1()  asm volatile("cp.async.wait_group 1;" ::: "memory")
#define CP_WAIT0()  asm volatile("cp.async.wait_group 0;" ::: "memory")

__device__ __forceinline__ void ldmx4(u32* r, u32 addr) {
    asm volatile("ldmatrix.sync.aligned.m8n8.x4.shared.b16 {%0,%1,%2,%3}, [%4];"
        : "=r"(r[0]), "=r"(r[1]), "=r"(r[2]), "=r"(r[3]) : "r"(addr));
}
__device__ __forceinline__ void ldmx4t(u32* r, u32 addr) {
    asm volatile("ldmatrix.sync.aligned.m8n8.x4.trans.shared.b16 {%0,%1,%2,%3}, [%4];"
        : "=r"(r[0]), "=r"(r[1]), "=r"(r[2]), "=r"(r[3]) : "r"(addr));
}
__device__ __forceinline__ void mma16816(float* c, const u32* a, const u32* b) {
    asm volatile("mma.sync.aligned.m16n8k16.row.col.f32.bf16.bf16.f32 "
        "{%0,%1,%2,%3}, {%4,%5,%6,%7}, {%8,%9}, {%0,%1,%2,%3};"
        : "+f"(c[0]), "+f"(c[1]), "+f"(c[2]), "+f"(c[3])
        : "r"(a[0]), "r"(a[1]), "r"(a[2]), "r"(a[3]), "r"(b[0]), "r"(b[1]));
}
__device__ __forceinline__ u32 pkbf(float a, float b) {
    __nv_bfloat162 h = __floats2bfloat162_rn(a, b);
    return *(u32*)&h;
}

// ------------------- small kernels ------------------------------------------
__global__ void embed_kernel(const int* __restrict__ idx,
                             const float* __restrict__ wte,
                             const float* __restrict__ wpe,
                             float* __restrict__ x) {
    int n = blockIdx.x;
    int t = n % TT;
    int tok = idx[n];
    const float* we = wte + (size_t)tok * DD;
    const float* wp = wpe + (size_t)t * DD;
    float* xr = x + (size_t)n * DD;
    for (int d = threadIdx.x; d < DD; d += blockDim.x)
        xr[d] = we[d] + wp[d];
}

__global__ void ln_kernel(const float* __restrict__ x,
                          const float* __restrict__ g,
                          const float* __restrict__ b,
                          bf16* __restrict__ yhi, bf16* __restrict__ ylo) {
    int r = blockIdx.x;
    int tid = threadIdx.x;   // 256
    const float* xr = x + (size_t)r * DD;
    float v0 = xr[tid], v1 = xr[tid + 256], v2 = xr[tid + 512];

    __shared__ float red[8];
    float s = v0 + v1 + v2;
    #pragma unroll
    for (int o = 16; o > 0; o >>= 1) s += __shfl_xor_sync(0xffffffffu, s, o);
    if ((tid & 31) == 0) red[tid >> 5] = s;
    __syncthreads();
    float tot = 0.f;
    #pragma unroll
    for (int i = 0; i < 8; i++) tot += red[i];
    float mean = tot * (1.0f / DD);
    __syncthreads();

    float c0 = v0 - mean, c1 = v1 - mean, c2 = v2 - mean;
    float sq = c0 * c0 + c1 * c1 + c2 * c2;
    #pragma unroll
    for (int o = 16; o > 0; o >>= 1) sq += __shfl_xor_sync(0xffffffffu, sq, o);
    if ((tid & 31) == 0) red[tid >> 5] = sq;
    __syncthreads();
    float var = 0.f;
    #pragma unroll
    for (int i = 0; i < 8; i++) var += red[i];
    var *= (1.0f / DD);
    float rstd = rsqrtf(var + 1e-5f);

    size_t base = (size_t)r * DD;
    #pragma unroll
    for (int p = 0; p < 3; p++) {
        int d = tid + p * 256;
        float cv = (p == 0 ? c0 : (p == 1 ? c1 : c2));
        float o = cv * rstd * g[d] + b[d];
        bf16 hv, lv; split2(o, hv, lv);
        yhi[base + d] = hv; ylo[base + d] = lv;
    }
}

__device__ __forceinline__ float softplusf(float x) {
    if (x > 20.f) return x;
    if (x < -20.f) return expf(x);
    return log1pf(expf(x));
}

__global__ void gate_kernel(const bf16* __restrict__ lnHi,
                            const bf16* __restrict__ lnLo,
                            const float* __restrict__ gw,
                            const float* __restrict__ nw,
                            const float* __restrict__ noise,
                            float* __restrict__ coef) {
    int r = blockIdx.x;
    int tid = threadIdx.x; // 128
    size_t rb = (size_t)r * DD;
    float acc[8] = {0.f, 0.f, 0.f, 0.f, 0.f, 0.f, 0.f, 0.f};
    for (int d = tid; d < DD; d += 128) {
        float xv = __bfloat162float(lnHi[rb + d]) + __bfloat162float(lnLo[rb + d]);
        #pragma unroll
        for (int e = 0; e < EE; e++) {
            acc[e]     += xv * gw[d * EE + e];
            acc[4 + e] += xv * nw[d * EE + e];
        }
    }
    __shared__ float part[8 * 128];
    #pragma unroll
    for (int e = 0; e < 8; e++) part[e * 128 + tid] = acc[e];
    __syncthreads();
    __shared__ float red[8];
    if (tid < 8) {
        float s = 0.f;
        for (int i = 0; i < 128; i++) s += part[tid * 128 + i];
        red[tid] = s;
    }
    __syncthreads();
    if (tid == 0) {
        float lg[4];
        #pragma unroll
        for (int e = 0; e < EE; e++)
            lg[e] = red[e] + noise[(size_t)r * EE + e] * softplusf(red[4 + e]);
        int i1 = 0;
        #pragma unroll
        for (int e = 1; e < EE; e++) if (lg[e] > lg[i1]) i1 = e;
        int i2 = -1;
        #pragma unroll
        for (int e = 0; e < EE; e++) {
            if (e == i1) continue;
            if (i2 < 0 || lg[e] > lg[i2]) i2 = e;
        }
        float m = lg[i1];
        float e1 = expf(lg[i1] - m), e2 = expf(lg[i2] - m);
        float inv = 1.f / (e1 + e2);
        float c[4] = {0.f, 0.f, 0.f, 0.f};
        c[i1] = e1 * inv;
        c[i2] = e2 * inv;
        #pragma unroll
        for (int e = 0; e < EE; e++) coef[(size_t)r * EE + e] = c[e];
    }
}

// batched transpose fp32 [K,N] -> split bf16 [N, ld], segment per blockIdx.z
#define TRMAX 20
struct TrTable {
    const float* src[TRMAX];
    bf16* dhi[TRMAX];
    bf16* dlo[TRMAX];
    int   srcN[TRMAX];   // src column count
    int   ld[TRMAX];     // dst row stride
};

__global__ void tr_multi(TrTable t) {
    __shared__ float tile[32][33];
    int z = blockIdx.z;
    const float* src = t.src[z];
    bf16* dhi = t.dhi[z];
    bf16* dlo = t.dlo[z];
    int N = t.srcN[z], ld = t.ld[z];
    int n0 = blockIdx.x * 32, k0 = blockIdx.y * 32;
    int tx = threadIdx.x, ty = threadIdx.y; // 32x8
    #pragma unroll
    for (int i = 0; i < 4; i++)
        tile[ty + 8 * i][tx] = src[(size_t)(k0 + ty + 8 * i) * N + n0 + tx];
    __syncthreads();
    #pragma unroll
    for (int i = 0; i < 4; i++) {
        float v = tile[tx][ty + 8 * i];
        bf16 hv, lv; split2(v, hv, lv);
        size_t o = (size_t)(n0 + ty + 8 * i) * ld + k0 + tx;
        dhi[o] = hv; dlo[o] = lv;
    }
}

// elementwise fp32 -> split bf16 (for wte)
__global__ void split_k(const float* __restrict__ s, bf16* __restrict__ hi,
                        bf16* __restrict__ lo, int n4) {
    int i = blockIdx.x * 256 + threadIdx.x;
    if (i >= n4) return;
    float4 v = ((const float4*)s)[i];
    bf16 h0, l0, h1, l1, h2, l2, h3, l3;
    split2(v.x, h0, l0); split2(v.y, h1, l1);
    split2(v.z, h2, l2); split2(v.w, h3, l3);
    __nv_bfloat162* H = (__nv_bfloat162*)hi;
    __nv_bfloat162* L = (__nv_bfloat162*)lo;
    H[2 * i]     = __nv_bfloat162(h0, h1);
    H[2 * i + 1] = __nv_bfloat162(h2, h3);
    L[2 * i]     = __nv_bfloat162(l0, l1);
    L[2 * i + 1] = __nv_bfloat162(l2, l3);
}

// x[r,:] += p0 + p1 + p2 (+bias)
__global__ void reduce3(const float* __restrict__ p,
                        const float* __restrict__ bias,
                        float* __restrict__ x) {
    int r = blockIdx.x;
    size_t rb = (size_t)r * DD;
    for (int i = threadIdx.x; i < DD; i += 256) {
        float v = p[rb + i] + p[(size_t)NN * DD + rb + i]
                + p[2 * (size_t)NN * DD + rb + i];
        if (bias) v += bias[i];
        x[rb + i] += v;
    }
}

// ------------------- mma.sync split-bf16 GEMM --------------------------------
// C[2048, N] = (Ahi+Alo) x (Bhi+Blo)^T, B stored [N][Kstride] K-contig.
// blockIdx.z selects a K-partition of length Kloop (split-K).
// EPI 0: Cf=v(guard N)  1: gelu(v+bias)->Chi/Clo  4: v->Chi/Clo
// EPI 5: Cf[z-plane] = v  (partial store, plane stride NN*DD)
#define GLDS 40
#define GMAT (128 * GLDS * 2)
#define GSTG (4 * GMAT)
#define GSM_TOTAL (2 * GSTG)

template <int EPI>
__global__ __launch_bounds__(256)
void mma_gemm(const bf16* __restrict__ Ahi, const bf16* __restrict__ Alo,
              const bf16* __restrict__ Bhi, const bf16* __restrict__ Blo,
              float* __restrict__ Cf, bf16* __restrict__ Chi, bf16* __restrict__ Clo,
              const float* __restrict__ bias, int N, int Kloop, int Kstride) {
    extern __shared__ char smdyn[];
    const u32 sb = smem_u32(smdyn);
    const int tid = threadIdx.x, wid = tid >> 5, lane = tid & 31;
    const int row0 = blockIdx.x * 128, col0 = blockIdx.y * 128;
    const int kbase = blockIdx.z * Kloop;
    const int warp_m = (wid & 3) * 32, warp_n = (wid >> 2) * 64;

    float c[2][8][4];
    #pragma unroll
    for (int mt = 0; mt < 2; mt++)
        #pragma unroll
        for (int nt = 0; nt < 8; nt++)
            #pragma unroll
            for (int i = 0; i < 4; i++) c[mt][nt][i] = 0.f;

    const int nch = Kloop >> 5;

    auto load_stage = [&](int s, int k0) {
        u32 st = sb + s * GSTG;
        #pragma unroll
        for (int i = 0; i < 2; i++) {
            int idx = tid + (i << 8);
            int r = idx >> 2, ch = idx & 3;
            u32 doff = (u32)(r * GLDS + ch * 8) * 2;
            size_t ga = (size_t)(row0 + r) * Kstride + kbase + k0 + ch * 8;
            CP16(st + doff,        Ahi + ga, 16);
            CP16(st + GMAT + doff, Alo + ga, 16);
            int gn = col0 + r;
            int pr = (gn < N) ? 16 : 0;
            int gnc = (gn < N) ? gn : 0;
            size_t gb = (size_t)gnc * Kstride + kbase + k0 + ch * 8;
            CP16(st + 2 * GMAT + doff, Bhi + gb, pr);
            CP16(st + 3 * GMAT + doff, Blo + gb, pr);
        }
        CP_COMMIT();
    };

    load_stage(0, 0);
    for (int kc = 0; kc < nch; kc++) {
        if (kc + 1 < nch) { load_stage((kc + 1) & 1, (kc + 1) << 5); CP_WAIT1(); }
        else CP_WAIT0();
        __syncthreads();

        u32 st = sb + (kc & 1) * GSTG;
        #pragma unroll
        for (int ks = 0; ks < 2; ks++) {
            u32 ah[2][4], al[2][4];
            #pragma unroll
            for (int mt = 0; mt < 2; mt++) {
                u32 ro = (u32)(warp_m + mt * 16 + (lane & 15)) * (GLDS * 2)
                       + (u32)(ks * 16 + ((lane >> 4) << 3)) * 2;
                ldmx4(ah[mt], st + ro);
                ldmx4(al[mt], st + GMAT + ro);
            }
            #pragma unroll
            for (int j = 0; j < 4; j++) {
                u32 bh[4], bl[4];
                u32 ro = (u32)(warp_n + j * 16 + ((lane >> 4) << 3) + (lane & 7)) * (GLDS * 2)
                       + (u32)(ks * 16 + (((lane >> 3) & 1) << 3)) * 2;
                ldmx4(bh, st + 2 * GMAT + ro);
                ldmx4(bl, st + 3 * GMAT + ro);
                #pragma unroll
                for (int mt = 0; mt < 2; mt++) {
                    mma16816(c[mt][2 * j],     ah[mt], bh);
                    mma16816(c[mt][2 * j],     ah[mt], bl);
                    mma16816(c[mt][2 * j],     al[mt], bh);
                    mma16816(c[mt][2 * j + 1], ah[mt], bh + 2);
                    mma16816(c[mt][2 * j + 1], ah[mt], bl + 2);
                    mma16816(c[mt][2 * j + 1], al[mt], bh + 2);
                }
            }
        }
        __syncthreads();
    }

    const size_t pplane = (size_t)blockIdx.z * NN * DD;
    #pragma unroll
    for (int mt = 0; mt < 2; mt++) {
        int rb = row0 + warp_m + mt * 16 + (lane >> 2);
        #pragma unroll
        for (int nt = 0; nt < 8; nt++) {
            int cc = col0 + warp_n + nt * 8 + (lane & 3) * 2;
            float* cr = c[mt][nt];
            #pragma unroll
            for (int h = 0; h < 2; h++) {
                int r = rb + h * 8;
                #pragma unroll
                for (int q = 0; q < 2; q++) {
                    int col = cc + q;
                    float v = cr[h * 2 + q];
                    size_t off = (size_t)r * N + col;
                    if (EPI == 0) {
                        if (col < N) Cf[off] = v;
                    } else if (EPI == 1) {
                        float gv = geluf(v + bias[col]);
                        bf16 hv, lv; split2(gv, hv, lv);
                        Chi[off] = hv; Clo[off] = lv;
                    } else if (EPI == 4) {
                        bf16 hv, lv; split2(v, hv, lv);
                        Chi[off] = hv; Clo[off] = lv;
                    } else {  // 5
                        Cf[pplane + off] = v;
                    }
                }
            }
        }
    }
}

// ------------------- mma.sync flash attention --------------------------------
// grid = (T/128, H, B*E). Reads merged split-bf16 qkv [N, QKVW]:
// cols [hh*64] = K head, [768+hh*64] = V head, [1536+e*768+hh*64] = Q head/e.
#define AST 72
#define AQB (128 * AST * 2)
#define AKB (64 * AST * 2)
#define AKVSTG (4 * AKB)
#define A_SMEM (2 * AQB + 2 * AKVSTG)

__global__ __launch_bounds__(256)
void attn_mma(const bf16* __restrict__ qkvHi, const bf16* __restrict__ qkvLo,
              const float* __restrict__ coef,
              bf16* __restrict__ oHi, bf16* __restrict__ oLo) {
    extern __shared__ char smdyn[];
    const u32 sb = smem_u32(smdyn);
    const int tid = threadIdx.x, wid = tid >> 5, lane = tid & 31;
    const int q0 = blockIdx.x * 128, hh = blockIdx.y;
    const int b = blockIdx.z >> 2, e = blockIdx.z & 3;
    const u32 QH = sb, QL = sb + AQB;
    const size_t qcol = 1536 + (size_t)e * DD + (size_t)hh * 64;

    #pragma unroll
    for (int i = 0; i < 4; i++) {
        int idx = tid + (i << 8);
        int r = idx >> 3, ch = idx & 7;
        size_t g = (size_t)(b * TT + q0 + r) * QKVW + qcol + ch * 8;
        u32 doff = (u32)(r * AST + ch * 8) * 2;
        CP16(QH + doff, qkvHi + g, 16);
        CP16(QL + doff, qkvLo + g, 16);
    }
    auto load_kv = [&](int s, int k0t) {
        u32 st = sb + 2 * AQB + s * AKVSTG;
        #pragma unroll
        for (int i = 0; i < 8; i++) {
            int idx = tid + (i << 8);
            int mat = idx >> 9;            // 0:KH 1:KL 2:VH 3:VL
            int r = (idx >> 3) & 63, ch = idx & 7;
            const bf16* src = (mat & 1) ? qkvLo : qkvHi;
            size_t g = (size_t)(b * TT + k0t + r) * QKVW + (size_t)(mat >> 1) * DD
                     + hh * 64 + ch * 8;
            CP16(st + mat * AKB + (u32)(r * AST + ch * 8) * 2, src + g, 16);
        }
        CP_COMMIT();
    };
    load_kv(0, 0);

    float o[8][4];
    #pragma unroll
    for (int nt = 0; nt < 8; nt++)
        #pragma unroll
        for (int i = 0; i < 4; i++) o[nt][i] = 0.f;
    float mrow[2] = {-1e30f, -1e30f}, lrow[2] = {0.f, 0.f};
    u32 qh[4][4], ql[4][4];

    const int nkt = blockIdx.x * 2 + 2;
    const int warp_r0 = q0 + wid * 16;
    const int rowg0 = warp_r0 + (lane >> 2), rowg1 = rowg0 + 8;

    for (int kt = 0; kt < nkt; kt++) {
        const int k0t = kt * 64;
        if (kt + 1 < nkt) { load_kv((kt + 1) & 1, k0t + 64); CP_WAIT1(); }
        else CP_WAIT0();
        __syncthreads();

        if (kt == 0) {
            #pragma unroll
            for (int ks = 0; ks < 4; ks++) {
                u32 ro = (u32)(wid * 16 + (lane & 15)) * (AST * 2)
                       + (u32)(ks * 16 + ((lane >> 4) << 3)) * 2;
                ldmx4(qh[ks], QH + ro);
                ldmx4(ql[ks], QL + ro);
            }
        }

        if (k0t <= warp_r0 + 15) {
            const u32 KH = sb + 2 * AQB + (kt & 1) * AKVSTG;
            const u32 KL = KH + AKB, VH = KH + 2 * AKB, VL = KH + 3 * AKB;

            float s[8][4];
            #pragma unroll
            for (int nt = 0; nt < 8; nt++)
                #pragma unroll
                for (int i = 0; i < 4; i++) s[nt][i] = 0.f;

            #pragma unroll
            for (int ks = 0; ks < 4; ks++) {
                #pragma unroll
                for (int j = 0; j < 4; j++) {
                    u32 bh[4], bl[4];
                    u32 ro = (u32)(j * 16 + ((lane >> 4) << 3) + (lane & 7)) * (AST * 2)
                           + (u32)(ks * 16 + (((lane >> 3) & 1) << 3)) * 2;
                    ldmx4(bh, KH + ro);
                    ldmx4(bl, KL + ro);
                    mma16816(s[2 * j],     qh[ks], bh);
                    mma16816(s[2 * j],     qh[ks], bl);
                    mma16816(s[2 * j],     ql[ks], bh);
                    mma16816(s[2 * j + 1], qh[ks], bh + 2);
                    mma16816(s[2 * j + 1], qh[ks], bl + 2);
                    mma16816(s[2 * j + 1], ql[ks], bh + 2);
                }
            }

            const bool diag = (k0t + 63 > warp_r0);
            #pragma unroll
            for (int nt = 0; nt < 8; nt++) {
                int cb = k0t + nt * 8 + (lane & 3) * 2;
                #pragma unroll
                for (int q = 0; q < 2; q++) {
                    int col = cb + q;
                    s[nt][q]     = (diag && col > rowg0) ? -1e30f : s[nt][q] * 0.125f;
                    s[nt][2 + q] = (diag && col > rowg1) ? -1e30f : s[nt][2 + q] * 0.125f;
                }
            }

            float ml0 = -1e30f, ml1 = -1e30f;
            #pragma unroll
            for (int nt = 0; nt < 8; nt++) {
                ml0 = fmaxf(ml0, fmaxf(s[nt][0], s[nt][1]));
                ml1 = fmaxf(ml1, fmaxf(s[nt][2], s[nt][3]));
            }
            ml0 = fmaxf(ml0, __shfl_xor_sync(0xffffffffu, ml0, 1));
            ml0 = fmaxf(ml0, __shfl_xor_sync(0xffffffffu, ml0, 2));
            ml1 = fmaxf(ml1, __shfl_xor_sync(0xffffffffu, ml1, 1));
            ml1 = fmaxf(ml1, __shfl_xor_sync(0xffffffffu, ml1, 2));
            float mn0 = fmaxf(mrow[0], ml0), mn1 = fmaxf(mrow[1], ml1);
            float cr0 = __expf(mrow[0] - mn0), cr1 = __expf(mrow[1] - mn1);
            float rs0 = 0.f, rs1 = 0.f;
            #pragma unroll
            for (int nt = 0; nt < 8; nt++) {
                s[nt][0] = __expf(s[nt][0] - mn0); rs0 += s[nt][0];
                s[nt][1] = __expf(s[nt][1] - mn0); rs0 += s[nt][1];
                s[nt][2] = __expf(s[nt][2] - mn1); rs1 += s[nt][2];
                s[nt][3] = __expf(s[nt][3] - mn1); rs1 += s[nt][3];
            }
            rs0 += __shfl_xor_sync(0xffffffffu, rs0, 1);
            rs0 += __shfl_xor_sync(0xffffffffu, rs0, 2);
            rs1 += __shfl_xor_sync(0xffffffffu, rs1, 1);
            rs1 += __shfl_xor_sync(0xffffffffu, rs1, 2);
            lrow[0] = lrow[0] * cr0 + rs0;
            lrow[1] = lrow[1] * cr1 + rs1;
            mrow[0] = mn0; mrow[1] = mn1;
            #pragma unroll
            for (int nt = 0; nt < 8; nt++) {
                o[nt][0] *= cr0; o[nt][1] *= cr0;
                o[nt][2] *= cr1; o[nt][3] *= cr1;
            }

            #pragma unroll
            for (int t = 0; t < 4; t++) {
                u32 a_h[4], a_l[4];
                #pragma unroll
                for (int half = 0; half < 2; half++) {
                    float* sp = s[2 * t + half];
                    bf16 h0, l0, h1, l1, h2, l2, h3, l3;
                    split2(sp[0], h0, l0); split2(sp[1], h1, l1);
                    split2(sp[2], h2, l2); split2(sp[3], h3, l3);
                    a_h[2 * half]     = pkbf(__bfloat162float(h0), __bfloat162float(h1));
                    a_h[2 * half + 1] = pkbf(__bfloat162float(h2), __bfloat162float(h3));
                    a_l[2 * half]     = pkbf(__bfloat162float(l0), __bfloat162float(l1));
                    a_l[2 * half + 1] = pkbf(__bfloat162float(l2), __bfloat162float(l3));
                }
                #pragma unroll
                for (int j = 0; j < 4; j++) {
                    u32 vh[4], vl[4];
                    int m = lane >> 3;
                    u32 rowv = (u32)(t * 16 + ((m & 1) << 3) + (lane & 7));
                    u32 colv = (u32)(j * 16 + ((m >> 1) << 3));
                    u32 ro = (rowv * AST + colv) * 2;
                    ldmx4t(vh, VH + ro);
                    ldmx4t(vl, VL + ro);
                    mma16816(o[2 * j],     a_h, vh);
                    mma16816(o[2 * j],     a_h, vl);
                    mma16816(o[2 * j],     a_l, vh);
                    mma16816(o[2 * j + 1], a_h, vh + 2);
                    mma16816(o[2 * j + 1], a_h, vl + 2);
                    mma16816(o[2 * j + 1], a_l, vh + 2);
                }
            }
        }
        __syncthreads();
    }

    size_t rg0 = (size_t)b * TT + rowg0, rg1 = (size_t)b * TT + rowg1;
    float inv0 = coef[rg0 * EE + e] / lrow[0];
    float inv1 = coef[rg1 * EE + e] / lrow[1];
    const size_t ocol = (size_t)e * DD + (size_t)hh * 64;
    #pragma unroll
    for (int nt = 0; nt < 8; nt++) {
        int cb = nt * 8 + (lane & 3) * 2;
        #pragma unroll
        for (int q = 0; q < 2; q++) {
            float v0 = o[nt][q] * inv0;
            float v1 = o[nt][2 + q] * inv1;
            bf16 h, l;
            split2(v0, h, l);
            oHi[rg0 * FF + ocol + cb + q] = h;
            oLo[rg0 * FF + ocol + cb + q] = l;
            split2(v1, h, l);
            oHi[rg1 * FF + ocol + cb + q] = h;
            oLo[rg1 * FF + ocol + cb + q] = l;
        }
    }
}

// ------------------- host ----------------------------------------------------
extern "C" void kernel_launch(void* const* d_in, const int* in_sizes, int n_in,
                              void* d_out, int out_size) {
    const int*   idx     = (const int*)  d_in[0];
    const float* wte     = (const float*)d_in[1];
    const float* wpe     = (const float*)d_in[2];
    const float* ln1_g   = (const float*)d_in[3];
    const float* ln1_b   = (const float*)d_in[4];
    const float* ln2_g   = (const float*)d_in[5];
    const float* ln2_b   = (const float*)d_in[6];
    const float* lnf_g   = (const float*)d_in[7];
    const float* lnf_b   = (const float*)d_in[8];
    const float* Wk      = (const float*)d_in[9];
    const float* Wv      = (const float*)d_in[10];
    const float* Wq      = (const float*)d_in[11];
    const float* Wo      = (const float*)d_in[12];
    const float* gate_w  = (const float*)d_in[13];
    const float* noise_w = (const float*)d_in[14];
    const float* fc_w    = (const float*)d_in[15];
    const float* fc_b    = (const float*)d_in[16];
    const float* proj_w  = (const float*)d_in[17];
    const float* proj_b  = (const float*)d_in[18];
    const float* noise   = (const float*)d_in[19];
    float* out = (float*)d_out;

    float *x, *coef, *part;
    bf16 *lnHi, *lnLo, *qkvHi, *qkvLo, *obHi, *obLo, *h1Hi, *h1Lo;
    bf16 *qkvTH, *qkvTL, *oTH, *oTL, *fcTH, *fcTL, *pjTH, *pjTL, *wteH, *wteL;
    cudaGetSymbolAddress((void**)&x,     g_x);
    cudaGetSymbolAddress((void**)&coef,  g_coef);
    cudaGetSymbolAddress((void**)&part,  g_part);
    cudaGetSymbolAddress((void**)&lnHi,  g_lnHi);
    cudaGetSymbolAddress((void**)&lnLo,  g_lnLo);
    cudaGetSymbolAddress((void**)&qkvHi, g_qkvHi);
    cudaGetSymbolAddress((void**)&qkvLo, g_qkvLo);
    cudaGetSymbolAddress((void**)&obHi,  g_obHi);
    cudaGetSymbolAddress((void**)&obLo,  g_obLo);
    cudaGetSymbolAddress((void**)&h1Hi,  g_h1Hi);
    cudaGetSymbolAddress((void**)&h1Lo,  g_h1Lo);
    cudaGetSymbolAddress((void**)&qkvTH, g_qkvTHi);
    cudaGetSymbolAddress((void**)&qkvTL, g_qkvTLo);
    cudaGetSymbolAddress((void**)&oTH,   g_oTHi);
    cudaGetSymbolAddress((void**)&oTL,   g_oTLo);
    cudaGetSymbolAddress((void**)&fcTH,  g_fcTHi);
    cudaGetSymbolAddress((void**)&fcTL,  g_fcTLo);
    cudaGetSymbolAddress((void**)&pjTH,  g_pjTHi);
    cudaGetSymbolAddress((void**)&pjTL,  g_pjTLo);
    cudaGetSymbolAddress((void**)&wteH,  g_wteHi);
    cudaGetSymbolAddress((void**)&wteL,  g_wteLo);

    cudaFuncSetAttribute(mma_gemm<0>, cudaFuncAttributeMaxDynamicSharedMemorySize, GSM_TOTAL);
    cudaFuncSetAttribute(mma_gemm<1>, cudaFuncAttributeMaxDynamicSharedMemorySize, GSM_TOTAL);
    cudaFuncSetAttribute(mma_gemm<4>, cudaFuncAttributeMaxDynamicSharedMemorySize, GSM_TOTAL);
    cudaFuncSetAttribute(mma_gemm<5>, cudaFuncAttributeMaxDynamicSharedMemorySize, GSM_TOTAL);
    cudaFuncSetAttribute(attn_mma,    cudaFuncAttributeMaxDynamicSharedMemorySize, A_SMEM);

    const size_t DxD = (size_t)DD * DD;

    // ---- build transpose tables ----
    TrTable tDD = {}, tFC = {}, tPJ = {};
    int nDD = 0;
    for (int l = 0; l < LL; l++) {
        // Wk -> qkvT rows [0,768)
        tDD.src[nDD] = Wk + l * DxD;
        tDD.dhi[nDD] = qkvTH + ((size_t)l * QKVW + 0) * DD;
        tDD.dlo[nDD] = qkvTL + ((size_t)l * QKVW + 0) * DD;
        tDD.srcN[nDD] = DD; tDD.ld[nDD] = DD; nDD++;
        // Wv -> rows [768,1536)
        tDD.src[nDD] = Wv + l * DxD;
        tDD.dhi[nDD] = qkvTH + ((size_t)l * QKVW + DD) * DD;
        tDD.dlo[nDD] = qkvTL + ((size_t)l * QKVW + DD) * DD;
        tDD.srcN[nDD] = DD; tDD.ld[nDD] = DD; nDD++;
        for (int e = 0; e < EE; e++) {
            // Wq[e] -> rows [1536+e*768, ...)
            tDD.src[nDD] = Wq + ((size_t)l * EE + e) * DxD;
            tDD.dhi[nDD] = qkvTH + ((size_t)l * QKVW + 2 * DD + e * DD) * DD;
            tDD.dlo[nDD] = qkvTL + ((size_t)l * QKVW + 2 * DD + e * DD) * DD;
            tDD.srcN[nDD] = DD; tDD.ld[nDD] = DD; nDD++;
            // Wo[e] -> oT cols e*DD, ld FF
            tDD.src[nDD] = Wo + ((size_t)l * EE + e) * DxD;
            tDD.dhi[nDD] = oTH + (size_t)l * DD * FF + e * DD;
            tDD.dlo[nDD] = oTL + (size_t)l * DD * FF + e * DD;
            tDD.srcN[nDD] = DD; tDD.ld[nDD] = FF; nDD++;
        }
    }
    for (int l = 0; l < LL; l++) {
        tFC.src[l] = fc_w + (size_t)l * DD * FF;
        tFC.dhi[l] = fcTH + (size_t)l * FF * DD;
        tFC.dlo[l] = fcTL + (size_t)l * FF * DD;
        tFC.srcN[l] = FF; tFC.ld[l] = DD;
        tPJ.src[l] = proj_w + (size_t)l * FF * DD;
        tPJ.dhi[l] = pjTH + (size_t)l * DD * FF;
        tPJ.dlo[l] = pjTL + (size_t)l * DD * FF;
        tPJ.srcN[l] = DD; tPJ.ld[l] = FF;
    }

    dim3 trb(32, 8);
    // launch order tuned so ncu (-s 5) lands on the QKV mma_gemm
    tr_multi<<<dim3(DD / 32, DD / 32, nDD), trb>>>(tDD);        // 0
    tr_multi<<<dim3(FF / 32, DD / 32, LL), trb>>>(tFC);         // 1
    embed_kernel<<<NN, 256>>>(idx, wte, wpe, x);                // 2
    tr_multi<<<dim3(DD / 32, FF / 32, LL), trb>>>(tPJ);         // 3

    dim3 gQKV(NN / 128, QKVW / 128);
    dim3 gFC(NN / 128, FF / 128);
    dim3 gSP(NN / 128, DD / 128, 3);
    dim3 gV(NN / 128, (VV + 127) / 128);
    dim3 gA(TT / 128, HH, BBATCH * EE);

    for (int l = 0; l < LL; l++) {
        ln_kernel<<<NN, 256>>>(x, ln1_g + l * DD, ln1_b + l * DD, lnHi, lnLo);
        mma_gemm<4><<<gQKV, 256, GSM_TOTAL>>>(lnHi, lnLo,
            qkvTH + (size_t)l * QKVW * DD, qkvTL + (size_t)l * QKVW * DD,
            nullptr, qkvHi, qkvLo, nullptr, QKVW, DD, DD);
        gate_kernel<<<NN, 128>>>(lnHi, lnLo, gate_w + (size_t)l * DD * EE,
                                 noise_w + (size_t)l * DD * EE,
                                 noise + (size_t)l * NN * EE, coef);
        attn_mma<<<gA, 256, A_SMEM>>>(qkvHi, qkvLo, coef, obHi, obLo);
        mma_gemm<5><<<gSP, 256, GSM_TOTAL>>>(obHi, obLo,
            oTH + (size_t)l * DD * FF, oTL + (size_t)l * DD * FF,
            part, nullptr, nullptr, nullptr, DD, 1024, FF);
        reduce3<<<NN, 256>>>(part, nullptr, x);
        ln_kernel<<<NN, 256>>>(x, ln2_g + l * DD, ln2_b + l * DD, lnHi, lnLo);
        mma_gemm<1><<<gFC, 256, GSM_TOTAL>>>(lnHi, lnLo,
            fcTH + (size_t)l * FF * DD, fcTL + (size_t)l * FF * DD,
            nullptr, h1Hi, h1Lo, fc_b + (size_t)l * FF, FF, DD, DD);
        mma_gemm<5><<<gSP, 256, GSM_TOTAL>>>(h1Hi, h1Lo,
            pjTH + (size_t)l * DD * FF, pjTL + (size_t)l * DD * FF,
            part, nullptr, nullptr, nullptr, DD, 1024, FF);
        reduce3<<<NN, 256>>>(part, proj_b + (size_t)l * DD, x);
    }

    {
        int n4 = VV * DD / 4;
        split_k<<<(n4 + 255) / 256, 256>>>(wte, wteH, wteL, n4);
    }
    ln_kernel<<<NN, 256>>>(x, lnf_g, lnf_b, lnHi, lnLo);
    mma_gemm<0><<<gV, 256, GSM_TOTAL>>>(lnHi, lnLo, wteH, wteL,
                                        out, nullptr, nullptr, nullptr,
                                        VV, DD, DD);
}

// round 7
// speedup vs baseline: 13.3104x; 1.2606x over previous
#include <cuda_runtime.h>
#include <cuda_bf16.h>
#include <cuda_fp16.h>
#include <math.h>
#include <stdint.h>

typedef __nv_bfloat16 bf16;
typedef __half f16;
typedef unsigned long long u64;
typedef unsigned int u32;

#define BBATCH 2
#define TT 1024
#define DD 768
#define HH 12
#define EE 4
#define NN 2048
#define LL 2
#define VV 50257
#define FF 3072
#define QKVW 4608      // K(768) + V(768) + Q(4*768)

// ------------------- scratch (static device arrays) ------------------------
__device__ __align__(16) float g_x[NN * DD];
__device__ __align__(16) bf16  g_lnHi[NN * DD];   // final LN aliases as f16
__device__ __align__(16) bf16  g_lnLo[NN * DD];
__device__ __align__(16) bf16  g_qkvHi[NN * QKVW];
__device__ __align__(16) bf16  g_qkvLo[NN * QKVW];
__device__ __align__(16) bf16  g_obHi[NN * FF];
__device__ __align__(16) bf16  g_obLo[NN * FF];
__device__ __align__(16) bf16  g_h1Hi[NN * FF];
__device__ __align__(16) bf16  g_h1Lo[NN * FF];
__device__ __align__(16) float g_part[3 * NN * DD];
__device__ float g_coef[NN * EE];

// packed transposed+split weights
__device__ __align__(16) bf16 g_qkvTHi[LL * QKVW * DD];
__device__ __align__(16) bf16 g_qkvTLo[LL * QKVW * DD];
__device__ __align__(16) bf16 g_oTHi[LL * DD * FF];
__device__ __align__(16) bf16 g_oTLo[LL * DD * FF];
__device__ __align__(16) bf16 g_fcTHi[LL * FF * DD];
__device__ __align__(16) bf16 g_fcTLo[LL * FF * DD];
__device__ __align__(16) bf16 g_pjTHi[LL * DD * FF];
__device__ __align__(16) bf16 g_pjTLo[LL * DD * FF];
__device__ __align__(16) f16  g_wteHi[VV * DD];   // fp16 for lm_head
__device__ __align__(16) f16  g_wteLo[VV * DD];

// ------------------- helpers ------------------------------------------------
__device__ __forceinline__ void split2(float v, bf16& h, bf16& l) {
    h = __float2bfloat16(v);
    l = __float2bfloat16(v - __bfloat162float(h));
}
__device__ __forceinline__ void split2h(float v, f16& h, f16& l) {
    h = __float2half(v);
    l = __float2half(v - __half2float(h));
}
__device__ __forceinline__ float geluf(float x) {
    float inner = 0.7978845608028654f * (x + 0.044715f * x * x * x);
    return 0.5f * x * (1.0f + tanhf(inner));
}
__device__ __forceinline__ u32 smem_u32(const void* p) {
    u32 a;
    asm("{ .reg .u64 t; cvta.to.shared.u64 t, %1; cvt.u32.u64 %0, t; }"
        : "=r"(a) : "l"(p));
    return a;
}

#define CP16(dst, src, n) \
    asm volatile("cp.async.cg.shared.global [%0], [%1], 16, %2;" \
                 :: "r"(dst), "l"(src), "r"(n) : "memory")
#define CP_COMMIT() asm volatile("cp.async.commit_group;" ::: "memory")
#define CP_WAIT1()  asm volatile("cp.async.wait_group 1;" ::: "memory")
#define CP_WAIT0()  asm volatile("cp.async.wait_group 0;" ::: "memory")

__device__ __forceinline__ void ldmx4(u32* r, u32 addr) {
    asm volatile("ldmatrix.sync.aligned.m8n8.x4.shared.b16 {%0,%1,%2,%3}, [%4];"
        : "=r"(r[0]), "=r"(r[1]), "=r"(r[2]), "=r"(r[3]) : "r"(addr));
}
__device__ __forceinline__ void ldmx4t(u32* r, u32 addr) {
    asm volatile("ldmatrix.sync.aligned.m8n8.x4.trans.shared.b16 {%0,%1,%2,%3}, [%4];"
        : "=r"(r[0]), "=r"(r[1]), "=r"(r[2]), "=r"(r[3]) : "r"(addr));
}
__device__ __forceinline__ void mma16816(float* c, const u32* a, const u32* b) {
    asm volatile("mma.sync.aligned.m16n8k16.row.col.f32.bf16.bf16.f32 "
        "{%0,%1,%2,%3}, {%4,%5,%6,%7}, {%8,%9}, {%0,%1,%2,%3};"
        : "+f"(c[0]), "+f"(c[1]), "+f"(c[2]), "+f"(c[3])
        : "r"(a[0]), "r"(a[1]), "r"(a[2]), "r"(a[3]), "r"(b[0]), "r"(b[1]));
}
__device__ __forceinline__ void mma16816h(float* c, const u32* a, const u32* b) {
    asm volatile("mma.sync.aligned.m16n8k16.row.col.f32.f16.f16.f32 "
        "{%0,%1,%2,%3}, {%4,%5,%6,%7}, {%8,%9}, {%0,%1,%2,%3};"
        : "+f"(c[0]), "+f"(c[1]), "+f"(c[2]), "+f"(c[3])
        : "r"(a[0]), "r"(a[1]), "r"(a[2]), "r"(a[3]), "r"(b[0]), "r"(b[1]));
}
__device__ __forceinline__ u32 pkbf(float a, float b) {
    __nv_bfloat162 h = __floats2bfloat162_rn(a, b);
    return *(u32*)&h;
}

// ------------------- small kernels ------------------------------------------
__global__ void embed_kernel(const int* __restrict__ idx,
                             const float* __restrict__ wte,
                             const float* __restrict__ wpe,
                             float* __restrict__ x) {
    int n = blockIdx.x;
    int t = n % TT;
    int tok = idx[n];
    const float* we = wte + (size_t)tok * DD;
    const float* wp = wpe + (size_t)t * DD;
    float* xr = x + (size_t)n * DD;
    for (int d = threadIdx.x; d < DD; d += blockDim.x)
        xr[d] = we[d] + wp[d];
}

// shared LN reduction: returns mean/rstd via pointers
__device__ __forceinline__ void ln_stats(const float* xr, int tid,
                                         float v0, float v1, float v2,
                                         float& mean, float& rstd) {
    __shared__ float red[8];
    float s = v0 + v1 + v2;
    #pragma unroll
    for (int o = 16; o > 0; o >>= 1) s += __shfl_xor_sync(0xffffffffu, s, o);
    if ((tid & 31) == 0) red[tid >> 5] = s;
    __syncthreads();
    float tot = 0.f;
    #pragma unroll
    for (int i = 0; i < 8; i++) tot += red[i];
    mean = tot * (1.0f / DD);
    __syncthreads();
    float c0 = v0 - mean, c1 = v1 - mean, c2 = v2 - mean;
    float sq = c0 * c0 + c1 * c1 + c2 * c2;
    #pragma unroll
    for (int o = 16; o > 0; o >>= 1) sq += __shfl_xor_sync(0xffffffffu, sq, o);
    if ((tid & 31) == 0) red[tid >> 5] = sq;
    __syncthreads();
    float var = 0.f;
    #pragma unroll
    for (int i = 0; i < 8; i++) var += red[i];
    var *= (1.0f / DD);
    rstd = rsqrtf(var + 1e-5f);
}

__global__ void ln_kernel(const float* __restrict__ x,
                          const float* __restrict__ g,
                          const float* __restrict__ b,
                          bf16* __restrict__ yhi, bf16* __restrict__ ylo) {
    int r = blockIdx.x;
    int tid = threadIdx.x;   // 256
    const float* xr = x + (size_t)r * DD;
    float v0 = xr[tid], v1 = xr[tid + 256], v2 = xr[tid + 512];
    float mean, rstd;
    ln_stats(xr, tid, v0, v1, v2, mean, rstd);

    size_t base = (size_t)r * DD;
    #pragma unroll
    for (int p = 0; p < 3; p++) {
        int d = tid + p * 256;
        float cv = (p == 0 ? v0 : (p == 1 ? v1 : v2)) - mean;
        float o = cv * rstd * g[d] + b[d];
        bf16 hv, lv; split2(o, hv, lv);
        yhi[base + d] = hv; ylo[base + d] = lv;
    }
}

// LN writing a single fp16 plane (for lm_head A operand)
__global__ void ln16_kernel(const float* __restrict__ x,
                            const float* __restrict__ g,
                            const float* __restrict__ b,
                            f16* __restrict__ y) {
    int r = blockIdx.x;
    int tid = threadIdx.x;
    const float* xr = x + (size_t)r * DD;
    float v0 = xr[tid], v1 = xr[tid + 256], v2 = xr[tid + 512];
    float mean, rstd;
    ln_stats(xr, tid, v0, v1, v2, mean, rstd);

    size_t base = (size_t)r * DD;
    #pragma unroll
    for (int p = 0; p < 3; p++) {
        int d = tid + p * 256;
        float cv = (p == 0 ? v0 : (p == 1 ? v1 : v2)) - mean;
        y[base + d] = __float2half(cv * rstd * g[d] + b[d]);
    }
}

__device__ __forceinline__ float softplusf(float x) {
    if (x > 20.f) return x;
    if (x < -20.f) return expf(x);
    return log1pf(expf(x));
}

__global__ void gate_kernel(const bf16* __restrict__ lnHi,
                            const bf16* __restrict__ lnLo,
                            const float* __restrict__ gw,
                            const float* __restrict__ nw,
                            const float* __restrict__ noise,
                            float* __restrict__ coef) {
    int r = blockIdx.x;
    int tid = threadIdx.x; // 128
    size_t rb = (size_t)r * DD;
    float acc[8] = {0.f, 0.f, 0.f, 0.f, 0.f, 0.f, 0.f, 0.f};
    for (int d = tid; d < DD; d += 128) {
        float xv = __bfloat162float(lnHi[rb + d]) + __bfloat162float(lnLo[rb + d]);
        #pragma unroll
        for (int e = 0; e < EE; e++) {
            acc[e]     += xv * gw[d * EE + e];
            acc[4 + e] += xv * nw[d * EE + e];
        }
    }
    __shared__ float part[8 * 128];
    #pragma unroll
    for (int e = 0; e < 8; e++) part[e * 128 + tid] = acc[e];
    __syncthreads();
    __shared__ float red[8];
    if (tid < 8) {
        float s = 0.f;
        for (int i = 0; i < 128; i++) s += part[tid * 128 + i];
        red[tid] = s;
    }
    __syncthreads();
    if (tid == 0) {
        float lg[4];
        #pragma unroll
        for (int e = 0; e < EE; e++)
            lg[e] = red[e] + noise[(size_t)r * EE + e] * softplusf(red[4 + e]);
        int i1 = 0;
        #pragma unroll
        for (int e = 1; e < EE; e++) if (lg[e] > lg[i1]) i1 = e;
        int i2 = -1;
        #pragma unroll
        for (int e = 0; e < EE; e++) {
            if (e == i1) continue;
            if (i2 < 0 || lg[e] > lg[i2]) i2 = e;
        }
        float m = lg[i1];
        float e1 = expf(lg[i1] - m), e2 = expf(lg[i2] - m);
        float inv = 1.f / (e1 + e2);
        float c[4] = {0.f, 0.f, 0.f, 0.f};
        c[i1] = e1 * inv;
        c[i2] = e2 * inv;
        #pragma unroll
        for (int e = 0; e < EE; e++) coef[(size_t)r * EE + e] = c[e];
    }
}

// batched transpose fp32 [K,N] -> split bf16 [N, ld], segment per blockIdx.z
#define TRMAX 20
struct TrTable {
    const float* src[TRMAX];
    bf16* dhi[TRMAX];
    bf16* dlo[TRMAX];
    int   srcN[TRMAX];
    int   ld[TRMAX];
};

__global__ void tr_multi(TrTable t) {
    __shared__ float tile[32][33];
    int z = blockIdx.z;
    const float* src = t.src[z];
    bf16* dhi = t.dhi[z];
    bf16* dlo = t.dlo[z];
    int N = t.srcN[z], ld = t.ld[z];
    int n0 = blockIdx.x * 32, k0 = blockIdx.y * 32;
    int tx = threadIdx.x, ty = threadIdx.y; // 32x8
    #pragma unroll
    for (int i = 0; i < 4; i++)
        tile[ty + 8 * i][tx] = src[(size_t)(k0 + ty + 8 * i) * N + n0 + tx];
    __syncthreads();
    #pragma unroll
    for (int i = 0; i < 4; i++) {
        float v = tile[tx][ty + 8 * i];
        bf16 hv, lv; split2(v, hv, lv);
        size_t o = (size_t)(n0 + ty + 8 * i) * ld + k0 + tx;
        dhi[o] = hv; dlo[o] = lv;
    }
}

// elementwise fp32 -> split fp16 (for wte / lm_head)
__global__ void splitH_k(const float* __restrict__ s, f16* __restrict__ hi,
                         f16* __restrict__ lo, int n4) {
    int i = blockIdx.x * 256 + threadIdx.x;
    if (i >= n4) return;
    float4 v = ((const float4*)s)[i];
    f16 h0, l0, h1, l1, h2, l2, h3, l3;
    split2h(v.x, h0, l0); split2h(v.y, h1, l1);
    split2h(v.z, h2, l2); split2h(v.w, h3, l3);
    __half2* H = (__half2*)hi;
    __half2* L = (__half2*)lo;
    H[2 * i]     = __half2(h0, h1);
    H[2 * i + 1] = __half2(h2, h3);
    L[2 * i]     = __half2(l0, l1);
    L[2 * i + 1] = __half2(l2, l3);
}

// x[r,:] += p0 + p1 + p2 (+bias)
__global__ void reduce3(const float* __restrict__ p,
                        const float* __restrict__ bias,
                        float* __restrict__ x) {
    int r = blockIdx.x;
    size_t rb = (size_t)r * DD;
    for (int i = threadIdx.x; i < DD; i += 256) {
        float v = p[rb + i] + p[(size_t)NN * DD + rb + i]
                + p[2 * (size_t)NN * DD + rb + i];
        if (bias) v += bias[i];
        x[rb + i] += v;
    }
}

// ------------------- mma.sync split-bf16 GEMM (3-pass) -----------------------
#define GLDS 40
#define GMAT (128 * GLDS * 2)
#define GSTG (4 * GMAT)
#define GSM_TOTAL (2 * GSTG)

template <int EPI>
__global__ __launch_bounds__(256)
void mma_gemm(const bf16* __restrict__ Ahi, const bf16* __restrict__ Alo,
              const bf16* __restrict__ Bhi, const bf16* __restrict__ Blo,
              float* __restrict__ Cf, bf16* __restrict__ Chi, bf16* __restrict__ Clo,
              const float* __restrict__ bias, int N, int Kloop, int Kstride) {
    extern __shared__ char smdyn[];
    const u32 sb = smem_u32(smdyn);
    const int tid = threadIdx.x, wid = tid >> 5, lane = tid & 31;
    const int row0 = blockIdx.x * 128, col0 = blockIdx.y * 128;
    const int kbase = blockIdx.z * Kloop;
    const int warp_m = (wid & 3) * 32, warp_n = (wid >> 2) * 64;

    float c[2][8][4];
    #pragma unroll
    for (int mt = 0; mt < 2; mt++)
        #pragma unroll
        for (int nt = 0; nt < 8; nt++)
            #pragma unroll
            for (int i = 0; i < 4; i++) c[mt][nt][i] = 0.f;

    const int nch = Kloop >> 5;

    auto load_stage = [&](int s, int k0) {
        u32 st = sb + s * GSTG;
        #pragma unroll
        for (int i = 0; i < 2; i++) {
            int idx = tid + (i << 8);
            int r = idx >> 2, ch = idx & 3;
            u32 doff = (u32)(r * GLDS + ch * 8) * 2;
            size_t ga = (size_t)(row0 + r) * Kstride + kbase + k0 + ch * 8;
            CP16(st + doff,        Ahi + ga, 16);
            CP16(st + GMAT + doff, Alo + ga, 16);
            int gn = col0 + r;
            int pr = (gn < N) ? 16 : 0;
            int gnc = (gn < N) ? gn : 0;
            size_t gb = (size_t)gnc * Kstride + kbase + k0 + ch * 8;
            CP16(st + 2 * GMAT + doff, Bhi + gb, pr);
            CP16(st + 3 * GMAT + doff, Blo + gb, pr);
        }
        CP_COMMIT();
    };

    load_stage(0, 0);
    for (int kc = 0; kc < nch; kc++) {
        if (kc + 1 < nch) { load_stage((kc + 1) & 1, (kc + 1) << 5); CP_WAIT1(); }
        else CP_WAIT0();
        __syncthreads();

        u32 st = sb + (kc & 1) * GSTG;
        #pragma unroll
        for (int ks = 0; ks < 2; ks++) {
            u32 ah[2][4], al[2][4];
            #pragma unroll
            for (int mt = 0; mt < 2; mt++) {
                u32 ro = (u32)(warp_m + mt * 16 + (lane & 15)) * (GLDS * 2)
                       + (u32)(ks * 16 + ((lane >> 4) << 3)) * 2;
                ldmx4(ah[mt], st + ro);
                ldmx4(al[mt], st + GMAT + ro);
            }
            #pragma unroll
            for (int j = 0; j < 4; j++) {
                u32 bh[4], bl[4];
                u32 ro = (u32)(warp_n + j * 16 + ((lane >> 4) << 3) + (lane & 7)) * (GLDS * 2)
                       + (u32)(ks * 16 + (((lane >> 3) & 1) << 3)) * 2;
                ldmx4(bh, st + 2 * GMAT + ro);
                ldmx4(bl, st + 3 * GMAT + ro);
                #pragma unroll
                for (int mt = 0; mt < 2; mt++) {
                    mma16816(c[mt][2 * j],     ah[mt], bh);
                    mma16816(c[mt][2 * j],     ah[mt], bl);
                    mma16816(c[mt][2 * j],     al[mt], bh);
                    mma16816(c[mt][2 * j + 1], ah[mt], bh + 2);
                    mma16816(c[mt][2 * j + 1], ah[mt], bl + 2);
                    mma16816(c[mt][2 * j + 1], al[mt], bh + 2);
                }
            }
        }
        __syncthreads();
    }

    const size_t pplane = (size_t)blockIdx.z * NN * DD;
    #pragma unroll
    for (int mt = 0; mt < 2; mt++) {
        int rb = row0 + warp_m + mt * 16 + (lane >> 2);
        #pragma unroll
        for (int nt = 0; nt < 8; nt++) {
            int cc = col0 + warp_n + nt * 8 + (lane & 3) * 2;
            float* cr = c[mt][nt];
            #pragma unroll
            for (int h = 0; h < 2; h++) {
                int r = rb + h * 8;
                #pragma unroll
                for (int q = 0; q < 2; q++) {
                    int col = cc + q;
                    float v = cr[h * 2 + q];
                    size_t off = (size_t)r * N + col;
                    if (EPI == 1) {
                        float gv = geluf(v + bias[col]);
                        bf16 hv, lv; split2(gv, hv, lv);
                        Chi[off] = hv; Clo[off] = lv;
                    } else if (EPI == 4) {
                        bf16 hv, lv; split2(v, hv, lv);
                        Chi[off] = hv; Clo[off] = lv;
                    } else {  // 5
                        Cf[pplane + off] = v;
                    }
                }
            }
        }
    }
}

// ------------------- fp16 2-pass GEMM (lm_head) ------------------------------
// C[2048, N] = A(f16) x (Bh + Bl)^T.  A single plane; B hi/lo fp16.
#define LSTG (3 * GMAT)
#define LSM_TOTAL (2 * LSTG)

__global__ __launch_bounds__(256)
void mma_gemm_lm(const f16* __restrict__ A,
                 const f16* __restrict__ Bh, const f16* __restrict__ Bl,
                 float* __restrict__ Cf, int N, int K) {
    extern __shared__ char smdyn[];
    const u32 sb = smem_u32(smdyn);
    const int tid = threadIdx.x, wid = tid >> 5, lane = tid & 31;
    const int row0 = blockIdx.x * 128, col0 = blockIdx.y * 128;
    const int warp_m = (wid & 3) * 32, warp_n = (wid >> 2) * 64;

    float c[2][8][4];
    #pragma unroll
    for (int mt = 0; mt < 2; mt++)
        #pragma unroll
        for (int nt = 0; nt < 8; nt++)
            #pragma unroll
            for (int i = 0; i < 4; i++) c[mt][nt][i] = 0.f;

    const int nch = K >> 5;

    auto load_stage = [&](int s, int k0) {
        u32 st = sb + s * LSTG;
        #pragma unroll
        for (int i = 0; i < 2; i++) {
            int idx = tid + (i << 8);
            int r = idx >> 2, ch = idx & 3;
            u32 doff = (u32)(r * GLDS + ch * 8) * 2;
            size_t ga = (size_t)(row0 + r) * K + k0 + ch * 8;
            CP16(st + doff, A + ga, 16);
            int gn = col0 + r;
            int pr = (gn < N) ? 16 : 0;
            int gnc = (gn < N) ? gn : 0;
            size_t gb = (size_t)gnc * K + k0 + ch * 8;
            CP16(st + GMAT + doff,     Bh + gb, pr);
            CP16(st + 2 * GMAT + doff, Bl + gb, pr);
        }
        CP_COMMIT();
    };

    load_stage(0, 0);
    for (int kc = 0; kc < nch; kc++) {
        if (kc + 1 < nch) { load_stage((kc + 1) & 1, (kc + 1) << 5); CP_WAIT1(); }
        else CP_WAIT0();
        __syncthreads();

        u32 st = sb + (kc & 1) * LSTG;
        #pragma unroll
        for (int ks = 0; ks < 2; ks++) {
            u32 ah[2][4];
            #pragma unroll
            for (int mt = 0; mt < 2; mt++) {
                u32 ro = (u32)(warp_m + mt * 16 + (lane & 15)) * (GLDS * 2)
                       + (u32)(ks * 16 + ((lane >> 4) << 3)) * 2;
                ldmx4(ah[mt], st + ro);
            }
            #pragma unroll
            for (int j = 0; j < 4; j++) {
                u32 bh[4], bl[4];
                u32 ro = (u32)(warp_n + j * 16 + ((lane >> 4) << 3) + (lane & 7)) * (GLDS * 2)
                       + (u32)(ks * 16 + (((lane >> 3) & 1) << 3)) * 2;
                ldmx4(bh, st + GMAT + ro);
                ldmx4(bl, st + 2 * GMAT + ro);
                #pragma unroll
                for (int mt = 0; mt < 2; mt++) {
                    mma16816h(c[mt][2 * j],     ah[mt], bh);
                    mma16816h(c[mt][2 * j],     ah[mt], bl);
                    mma16816h(c[mt][2 * j + 1], ah[mt], bh + 2);
                    mma16816h(c[mt][2 * j + 1], ah[mt], bl + 2);
                }
            }
        }
        __syncthreads();
    }

    #pragma unroll
    for (int mt = 0; mt < 2; mt++) {
        int rb = row0 + warp_m + mt * 16 + (lane >> 2);
        #pragma unroll
        for (int nt = 0; nt < 8; nt++) {
            int cc = col0 + warp_n + nt * 8 + (lane & 3) * 2;
            float* cr = c[mt][nt];
            #pragma unroll
            for (int h = 0; h < 2; h++) {
                int r = rb + h * 8;
                #pragma unroll
                for (int q = 0; q < 2; q++) {
                    int col = cc + q;
                    if (col < N) Cf[(size_t)r * N + col] = cr[h * 2 + q];
                }
            }
        }
    }
}

// ------------------- mma.sync flash attention --------------------------------
#define AST 72
#define AQB (128 * AST * 2)
#define AKB (64 * AST * 2)
#define AKVSTG (4 * AKB)
#define A_SMEM (2 * AQB + 2 * AKVSTG)

__global__ __launch_bounds__(256)
void attn_mma(const bf16* __restrict__ qkvHi, const bf16* __restrict__ qkvLo,
              const float* __restrict__ coef,
              bf16* __restrict__ oHi, bf16* __restrict__ oLo) {
    extern __shared__ char smdyn[];
    const u32 sb = smem_u32(smdyn);
    const int tid = threadIdx.x, wid = tid >> 5, lane = tid & 31;
    const int q0 = blockIdx.x * 128, hh = blockIdx.y;
    const int b = blockIdx.z >> 2, e = blockIdx.z & 3;
    const u32 QH = sb, QL = sb + AQB;
    const size_t qcol = 1536 + (size_t)e * DD + (size_t)hh * 64;

    #pragma unroll
    for (int i = 0; i < 4; i++) {
        int idx = tid + (i << 8);
        int r = idx >> 3, ch = idx & 7;
        size_t g = (size_t)(b * TT + q0 + r) * QKVW + qcol + ch * 8;
        u32 doff = (u32)(r * AST + ch * 8) * 2;
        CP16(QH + doff, qkvHi + g, 16);
        CP16(QL + doff, qkvLo + g, 16);
    }
    auto load_kv = [&](int s, int k0t) {
        u32 st = sb + 2 * AQB + s * AKVSTG;
        #pragma unroll
        for (int i = 0; i < 8; i++) {
            int idx = tid + (i << 8);
            int mat = idx >> 9;
            int r = (idx >> 3) & 63, ch = idx & 7;
            const bf16* src = (mat & 1) ? qkvLo : qkvHi;
            size_t g = (size_t)(b * TT + k0t + r) * QKVW + (size_t)(mat >> 1) * DD
                     + hh * 64 + ch * 8;
            CP16(st + mat * AKB + (u32)(r * AST + ch * 8) * 2, src + g, 16);
        }
        CP_COMMIT();
    };
    load_kv(0, 0);

    float o[8][4];
    #pragma unroll
    for (int nt = 0; nt < 8; nt++)
        #pragma unroll
        for (int i = 0; i < 4; i++) o[nt][i] = 0.f;
    float mrow[2] = {-1e30f, -1e30f}, lrow[2] = {0.f, 0.f};
    u32 qh[4][4], ql[4][4];

    const int nkt = blockIdx.x * 2 + 2;
    const int warp_r0 = q0 + wid * 16;
    const int rowg0 = warp_r0 + (lane >> 2), rowg1 = rowg0 + 8;

    for (int kt = 0; kt < nkt; kt++) {
        const int k0t = kt * 64;
        if (kt + 1 < nkt) { load_kv((kt + 1) & 1, k0t + 64); CP_WAIT1(); }
        else CP_WAIT0();
        __syncthreads();

        if (kt == 0) {
            #pragma unroll
            for (int ks = 0; ks < 4; ks++) {
                u32 ro = (u32)(wid * 16 + (lane & 15)) * (AST * 2)
                       + (u32)(ks * 16 + ((lane >> 4) << 3)) * 2;
                ldmx4(qh[ks], QH + ro);
                ldmx4(ql[ks], QL + ro);
            }
        }

        if (k0t <= warp_r0 + 15) {
            const u32 KH = sb + 2 * AQB + (kt & 1) * AKVSTG;
            const u32 KL = KH + AKB, VH = KH + 2 * AKB, VL = KH + 3 * AKB;

            float s[8][4];
            #pragma unroll
            for (int nt = 0; nt < 8; nt++)
                #pragma unroll
                for (int i = 0; i < 4; i++) s[nt][i] = 0.f;

            #pragma unroll
            for (int ks = 0; ks < 4; ks++) {
                #pragma unroll
                for (int j = 0; j < 4; j++) {
                    u32 bh[4], bl[4];
                    u32 ro = (u32)(j * 16 + ((lane >> 4) << 3) + (lane & 7)) * (AST * 2)
                           + (u32)(ks * 16 + (((lane >> 3) & 1) << 3)) * 2;
                    ldmx4(bh, KH + ro);
                    ldmx4(bl, KL + ro);
                    mma16816(s[2 * j],     qh[ks], bh);
                    mma16816(s[2 * j],     qh[ks], bl);
                    mma16816(s[2 * j],     ql[ks], bh);
                    mma16816(s[2 * j + 1], qh[ks], bh + 2);
                    mma16816(s[2 * j + 1], qh[ks], bl + 2);
                    mma16816(s[2 * j + 1], ql[ks], bh + 2);
                }
            }

            const bool diag = (k0t + 63 > warp_r0);
            #pragma unroll
            for (int nt = 0; nt < 8; nt++) {
                int cb = k0t + nt * 8 + (lane & 3) * 2;
                #pragma unroll
                for (int q = 0; q < 2; q++) {
                    int col = cb + q;
                    s[nt][q]     = (diag && col > rowg0) ? -1e30f : s[nt][q] * 0.125f;
                    s[nt][2 + q] = (diag && col > rowg1) ? -1e30f : s[nt][2 + q] * 0.125f;
                }
            }

            float ml0 = -1e30f, ml1 = -1e30f;
            #pragma unroll
            for (int nt = 0; nt < 8; nt++) {
                ml0 = fmaxf(ml0, fmaxf(s[nt][0], s[nt][1]));
                ml1 = fmaxf(ml1, fmaxf(s[nt][2], s[nt][3]));
            }
            ml0 = fmaxf(ml0, __shfl_xor_sync(0xffffffffu, ml0, 1));
            ml0 = fmaxf(ml0, __shfl_xor_sync(0xffffffffu, ml0, 2));
            ml1 = fmaxf(ml1, __shfl_xor_sync(0xffffffffu, ml1, 1));
            ml1 = fmaxf(ml1, __shfl_xor_sync(0xffffffffu, ml1, 2));
            float mn0 = fmaxf(mrow[0], ml0), mn1 = fmaxf(mrow[1], ml1);
            float cr0 = __expf(mrow[0] - mn0), cr1 = __expf(mrow[1] - mn1);
            float rs0 = 0.f, rs1 = 0.f;
            #pragma unroll
            for (int nt = 0; nt < 8; nt++) {
                s[nt][0] = __expf(s[nt][0] - mn0); rs0 += s[nt][0];
                s[nt][1] = __expf(s[nt][1] - mn0); rs0 += s[nt][1];
                s[nt][2] = __expf(s[nt][2] - mn1); rs1 += s[nt][2];
                s[nt][3] = __expf(s[nt][3] - mn1); rs1 += s[nt][3];
            }
            rs0 += __shfl_xor_sync(0xffffffffu, rs0, 1);
            rs0 += __shfl_xor_sync(0xffffffffu, rs0, 2);
            rs1 += __shfl_xor_sync(0xffffffffu, rs1, 1);
            rs1 += __shfl_xor_sync(0xffffffffu, rs1, 2);
            lrow[0] = lrow[0] * cr0 + rs0;
            lrow[1] = lrow[1] * cr1 + rs1;
            mrow[0] = mn0; mrow[1] = mn1;
            #pragma unroll
            for (int nt = 0; nt < 8; nt++) {
                o[nt][0] *= cr0; o[nt][1] *= cr0;
                o[nt][2] *= cr1; o[nt][3] *= cr1;
            }

            #pragma unroll
            for (int t = 0; t < 4; t++) {
                u32 a_h[4], a_l[4];
                #pragma unroll
                for (int half = 0; half < 2; half++) {
                    float* sp = s[2 * t + half];
                    bf16 h0, l0, h1, l1, h2, l2, h3, l3;
                    split2(sp[0], h0, l0); split2(sp[1], h1, l1);
                    split2(sp[2], h2, l2); split2(sp[3], h3, l3);
                    a_h[2 * half]     = pkbf(__bfloat162float(h0), __bfloat162float(h1));
                    a_h[2 * half + 1] = pkbf(__bfloat162float(h2), __bfloat162float(h3));
                    a_l[2 * half]     = pkbf(__bfloat162float(l0), __bfloat162float(l1));
                    a_l[2 * half + 1] = pkbf(__bfloat162float(l2), __bfloat162float(l3));
                }
                #pragma unroll
                for (int j = 0; j < 4; j++) {
                    u32 vh[4], vl[4];
                    int m = lane >> 3;
                    u32 rowv = (u32)(t * 16 + ((m & 1) << 3) + (lane & 7));
                    u32 colv = (u32)(j * 16 + ((m >> 1) << 3));
                    u32 ro = (rowv * AST + colv) * 2;
                    ldmx4t(vh, VH + ro);
                    ldmx4t(vl, VL + ro);
                    mma16816(o[2 * j],     a_h, vh);
                    mma16816(o[2 * j],     a_h, vl);
                    mma16816(o[2 * j],     a_l, vh);
                    mma16816(o[2 * j + 1], a_h, vh + 2);
                    mma16816(o[2 * j + 1], a_h, vl + 2);
                    mma16816(o[2 * j + 1], a_l, vh + 2);
                }
            }
        }
        __syncthreads();
    }

    size_t rg0 = (size_t)b * TT + rowg0, rg1 = (size_t)b * TT + rowg1;
    float inv0 = coef[rg0 * EE + e] / lrow[0];
    float inv1 = coef[rg1 * EE + e] / lrow[1];
    const size_t ocol = (size_t)e * DD + (size_t)hh * 64;
    #pragma unroll
    for (int nt = 0; nt < 8; nt++) {
        int cb = nt * 8 + (lane & 3) * 2;
        #pragma unroll
        for (int q = 0; q < 2; q++) {
            float v0 = o[nt][q] * inv0;
            float v1 = o[nt][2 + q] * inv1;
            bf16 h, l;
            split2(v0, h, l);
            oHi[rg0 * FF + ocol + cb + q] = h;
            oLo[rg0 * FF + ocol + cb + q] = l;
            split2(v1, h, l);
            oHi[rg1 * FF + ocol + cb + q] = h;
            oLo[rg1 * FF + ocol + cb + q] = l;
        }
    }
}

// ------------------- host ----------------------------------------------------
extern "C" void kernel_launch(void* const* d_in, const int* in_sizes, int n_in,
                              void* d_out, int out_size) {
    const int*   idx     = (const int*)  d_in[0];
    const float* wte     = (const float*)d_in[1];
    const float* wpe     = (const float*)d_in[2];
    const float* ln1_g   = (const float*)d_in[3];
    const float* ln1_b   = (const float*)d_in[4];
    const float* ln2_g   = (const float*)d_in[5];
    const float* ln2_b   = (const float*)d_in[6];
    const float* lnf_g   = (const float*)d_in[7];
    const float* lnf_b   = (const float*)d_in[8];
    const float* Wk      = (const float*)d_in[9];
    const float* Wv      = (const float*)d_in[10];
    const float* Wq      = (const float*)d_in[11];
    const float* Wo      = (const float*)d_in[12];
    const float* gate_w  = (const float*)d_in[13];
    const float* noise_w = (const float*)d_in[14];
    const float* fc_w    = (const float*)d_in[15];
    const float* fc_b    = (const float*)d_in[16];
    const float* proj_w  = (const float*)d_in[17];
    const float* proj_b  = (const float*)d_in[18];
    const float* noise   = (const float*)d_in[19];
    float* out = (float*)d_out;

    float *x, *coef, *part;
    bf16 *lnHi, *lnLo, *qkvHi, *qkvLo, *obHi, *obLo, *h1Hi, *h1Lo;
    bf16 *qkvTH, *qkvTL, *oTH, *oTL, *fcTH, *fcTL, *pjTH, *pjTL;
    f16 *wteH, *wteL;
    cudaGetSymbolAddress((void**)&x,     g_x);
    cudaGetSymbolAddress((void**)&coef,  g_coef);
    cudaGetSymbolAddress((void**)&part,  g_part);
    cudaGetSymbolAddress((void**)&lnHi,  g_lnHi);
    cudaGetSymbolAddress((void**)&lnLo,  g_lnLo);
    cudaGetSymbolAddress((void**)&qkvHi, g_qkvHi);
    cudaGetSymbolAddress((void**)&qkvLo, g_qkvLo);
    cudaGetSymbolAddress((void**)&obHi,  g_obHi);
    cudaGetSymbolAddress((void**)&obLo,  g_obLo);
    cudaGetSymbolAddress((void**)&h1Hi,  g_h1Hi);
    cudaGetSymbolAddress((void**)&h1Lo,  g_h1Lo);
    cudaGetSymbolAddress((void**)&qkvTH, g_qkvTHi);
    cudaGetSymbolAddress((void**)&qkvTL, g_qkvTLo);
    cudaGetSymbolAddress((void**)&oTH,   g_oTHi);
    cudaGetSymbolAddress((void**)&oTL,   g_oTLo);
    cudaGetSymbolAddress((void**)&fcTH,  g_fcTHi);
    cudaGetSymbolAddress((void**)&fcTL,  g_fcTLo);
    cudaGetSymbolAddress((void**)&pjTH,  g_pjTHi);
    cudaGetSymbolAddress((void**)&pjTL,  g_pjTLo);
    cudaGetSymbolAddress((void**)&wteH,  g_wteHi);
    cudaGetSymbolAddress((void**)&wteL,  g_wteLo);

    cudaFuncSetAttribute(mma_gemm<1>, cudaFuncAttributeMaxDynamicSharedMemorySize, GSM_TOTAL);
    cudaFuncSetAttribute(mma_gemm<4>, cudaFuncAttributeMaxDynamicSharedMemorySize, GSM_TOTAL);
    cudaFuncSetAttribute(mma_gemm<5>, cudaFuncAttributeMaxDynamicSharedMemorySize, GSM_TOTAL);
    cudaFuncSetAttribute(mma_gemm_lm, cudaFuncAttributeMaxDynamicSharedMemorySize, LSM_TOTAL);
    cudaFuncSetAttribute(attn_mma,    cudaFuncAttributeMaxDynamicSharedMemorySize, A_SMEM);

    const size_t DxD = (size_t)DD * DD;

    // ---- build transpose tables ----
    TrTable tDD = {}, tFC = {}, tPJ = {};
    int nDD = 0;
    for (int l = 0; l < LL; l++) {
        tDD.src[nDD] = Wk + l * DxD;
        tDD.dhi[nDD] = qkvTH + ((size_t)l * QKVW + 0) * DD;
        tDD.dlo[nDD] = qkvTL + ((size_t)l * QKVW + 0) * DD;
        tDD.srcN[nDD] = DD; tDD.ld[nDD] = DD; nDD++;
        tDD.src[nDD] = Wv + l * DxD;
        tDD.dhi[nDD] = qkvTH + ((size_t)l * QKVW + DD) * DD;
        tDD.dlo[nDD] = qkvTL + ((size_t)l * QKVW + DD) * DD;
        tDD.srcN[nDD] = DD; tDD.ld[nDD] = DD; nDD++;
        for (int e = 0; e < EE; e++) {
            tDD.src[nDD] = Wq + ((size_t)l * EE + e) * DxD;
            tDD.dhi[nDD] = qkvTH + ((size_t)l * QKVW + 2 * DD + e * DD) * DD;
            tDD.dlo[nDD] = qkvTL + ((size_t)l * QKVW + 2 * DD + e * DD) * DD;
            tDD.srcN[nDD] = DD; tDD.ld[nDD] = DD; nDD++;
            tDD.src[nDD] = Wo + ((size_t)l * EE + e) * DxD;
            tDD.dhi[nDD] = oTH + (size_t)l * DD * FF + e * DD;
            tDD.dlo[nDD] = oTL + (size_t)l * DD * FF + e * DD;
            tDD.srcN[nDD] = DD; tDD.ld[nDD] = FF; nDD++;
        }
    }
    for (int l = 0; l < LL; l++) {
        tFC.src[l] = fc_w + (size_t)l * DD * FF;
        tFC.dhi[l] = fcTH + (size_t)l * FF * DD;
        tFC.dlo[l] = fcTL + (size_t)l * FF * DD;
        tFC.srcN[l] = FF; tFC.ld[l] = DD;
        tPJ.src[l] = proj_w + (size_t)l * FF * DD;
        tPJ.dhi[l] = pjTH + (size_t)l * DD * FF;
        tPJ.dlo[l] = pjTL + (size_t)l * DD * FF;
        tPJ.srcN[l] = DD; tPJ.ld[l] = FF;
    }

    dim3 trb(32, 8);
    tr_multi<<<dim3(DD / 32, DD / 32, nDD), trb>>>(tDD);
    tr_multi<<<dim3(FF / 32, DD / 32, LL), trb>>>(tFC);
    embed_kernel<<<NN, 256>>>(idx, wte, wpe, x);
    tr_multi<<<dim3(DD / 32, FF / 32, LL), trb>>>(tPJ);

    dim3 gQKV(NN / 128, QKVW / 128);
    dim3 gFC(NN / 128, FF / 128);
    dim3 gSP(NN / 128, DD / 128, 3);
    dim3 gV(NN / 128, (VV + 127) / 128);
    dim3 gA(TT / 128, HH, BBATCH * EE);

    for (int l = 0; l < LL; l++) {
        ln_kernel<<<NN, 256>>>(x, ln1_g + l * DD, ln1_b + l * DD, lnHi, lnLo);
        mma_gemm<4><<<gQKV, 256, GSM_TOTAL>>>(lnHi, lnLo,
            qkvTH + (size_t)l * QKVW * DD, qkvTL + (size_t)l * QKVW * DD,
            nullptr, qkvHi, qkvLo, nullptr, QKVW, DD, DD);
        gate_kernel<<<NN, 128>>>(lnHi, lnLo, gate_w + (size_t)l * DD * EE,
                                 noise_w + (size_t)l * DD * EE,
                                 noise + (size_t)l * NN * EE, coef);
        attn_mma<<<gA, 256, A_SMEM>>>(qkvHi, qkvLo, coef, obHi, obLo);
        mma_gemm<5><<<gSP, 256, GSM_TOTAL>>>(obHi, obLo,
            oTH + (size_t)l * DD * FF, oTL + (size_t)l * DD * FF,
            part, nullptr, nullptr, nullptr, DD, 1024, FF);
        reduce3<<<NN, 256>>>(part, nullptr, x);
        ln_kernel<<<NN, 256>>>(x, ln2_g + l * DD, ln2_b + l * DD, lnHi, lnLo);
        mma_gemm<1><<<gFC, 256, GSM_TOTAL>>>(lnHi, lnLo,
            fcTH + (size_t)l * FF * DD, fcTL + (size_t)l * FF * DD,
            nullptr, h1Hi, h1Lo, fc_b + (size_t)l * FF, FF, DD, DD);
        mma_gemm<5><<<gSP, 256, GSM_TOTAL>>>(h1Hi, h1Lo,
            pjTH + (size_t)l * DD * FF, pjTL + (size_t)l * DD * FF,
            part, nullptr, nullptr, nullptr, DD, 1024, FF);
        reduce3<<<NN, 256>>>(part, proj_b + (size_t)l * DD, x);
    }

    {
        int n4 = VV * DD / 4;
        splitH_k<<<(n4 + 255) / 256, 256>>>(wte, wteH, wteL, n4);
    }
    ln16_kernel<<<NN, 256>>>(x, lnf_g, lnf_b, (f16*)lnHi);
    mma_gemm_lm<<<gV, 256, LSM_TOTAL>>>((f16*)lnHi, wteH, wteL,
                                        out, VV, DD);
}

// round 8
// speedup vs baseline: 21.2584x; 1.5971x over previous
#include <cuda_runtime.h>
#include <cuda_bf16.h>
#include <cuda_fp16.h>
#include <math.h>
#include <stdint.h>

typedef __half f16;
typedef unsigned long long u64;
typedef unsigned int u32;

#define BBATCH 2
#define TT 1024
#define DD 768
#define HH 12
#define EE 4
#define NN 2048
#define LL 2
#define VV 50257
#define FF 3072
#define QKVW 4608      // K(768) + V(768) + Q(4*768)

// ------------------- scratch (static device arrays) ------------------------
__device__ __align__(16) float g_x[NN * DD];
__device__ __align__(16) f16   g_ln16[NN * DD];
__device__ __align__(16) f16   g_qkv16[NN * QKVW];
__device__ __align__(16) f16   g_ob16[NN * FF];
__device__ __align__(16) f16   g_h116[NN * FF];
__device__ __align__(16) float g_part[3 * NN * DD];
__device__ float g_coef[NN * EE];

// packed transposed+split fp16 weights (hi+lo)
__device__ __align__(16) f16 g_qkvTHi[LL * QKVW * DD];
__device__ __align__(16) f16 g_qkvTLo[LL * QKVW * DD];
__device__ __align__(16) f16 g_oTHi[LL * DD * FF];
__device__ __align__(16) f16 g_oTLo[LL * DD * FF];
__device__ __align__(16) f16 g_fcTHi[LL * FF * DD];
__device__ __align__(16) f16 g_fcTLo[LL * FF * DD];
__device__ __align__(16) f16 g_pjTHi[LL * DD * FF];
__device__ __align__(16) f16 g_pjTLo[LL * DD * FF];
__device__ __align__(16) f16 g_wteH[VV * DD];      // single plane for lm_head

// ------------------- helpers ------------------------------------------------
__device__ __forceinline__ void split2h(float v, f16& h, f16& l) {
    h = __float2half(v);
    l = __float2half(v - __half2float(h));
}
__device__ __forceinline__ float geluf(float x) {
    float inner = 0.7978845608028654f * (x + 0.044715f * x * x * x);
    return 0.5f * x * (1.0f + tanhf(inner));
}
__device__ __forceinline__ u32 smem_u32(const void* p) {
    u32 a;
    asm("{ .reg .u64 t; cvta.to.shared.u64 t, %1; cvt.u32.u64 %0, t; }"
        : "=r"(a) : "l"(p));
    return a;
}

#define CP16(dst, src, n) \
    asm volatile("cp.async.cg.shared.global [%0], [%1], 16, %2;" \
                 :: "r"(dst), "l"(src), "r"(n) : "memory")
#define CP_COMMIT() asm volatile("cp.async.commit_group;" ::: "memory")
#define CP_WAIT1()  asm volatile("cp.async.wait_group 1;" ::: "memory")
#define CP_WAIT0()  asm volatile("cp.async.wait_group 0;" ::: "memory")

__device__ __forceinline__ void ldmx4(u32* r, u32 addr) {
    asm volatile("ldmatrix.sync.aligned.m8n8.x4.shared.b16 {%0,%1,%2,%3}, [%4];"
        : "=r"(r[0]), "=r"(r[1]), "=r"(r[2]), "=r"(r[3]) : "r"(addr));
}
__device__ __forceinline__ void ldmx4t(u32* r, u32 addr) {
    asm volatile("ldmatrix.sync.aligned.m8n8.x4.trans.shared.b16 {%0,%1,%2,%3}, [%4];"
        : "=r"(r[0]), "=r"(r[1]), "=r"(r[2]), "=r"(r[3]) : "r"(addr));
}
__device__ __forceinline__ void mma16816h(float* c, const u32* a, const u32* b) {
    asm volatile("mma.sync.aligned.m16n8k16.row.col.f32.f16.f16.f32 "
        "{%0,%1,%2,%3}, {%4,%5,%6,%7}, {%8,%9}, {%0,%1,%2,%3};"
        : "+f"(c[0]), "+f"(c[1]), "+f"(c[2]), "+f"(c[3])
        : "r"(a[0]), "r"(a[1]), "r"(a[2]), "r"(a[3]), "r"(b[0]), "r"(b[1]));
}
__device__ __forceinline__ u32 pkhf(float a, float b) {
    __half2 h = __floats2half2_rn(a, b);
    return *(u32*)&h;
}

// ------------------- small kernels ------------------------------------------
__global__ void embed_kernel(const int* __restrict__ idx,
                             const float* __restrict__ wte,
                             const float* __restrict__ wpe,
                             float* __restrict__ x) {
    int n = blockIdx.x;
    int t = n % TT;
    int tok = idx[n];
    const float* we = wte + (size_t)tok * DD;
    const float* wp = wpe + (size_t)t * DD;
    float* xr = x + (size_t)n * DD;
    for (int d = threadIdx.x; d < DD; d += blockDim.x)
        xr[d] = we[d] + wp[d];
}

// LayerNorm -> single fp16 plane
__global__ void ln16_kernel(const float* __restrict__ x,
                            const float* __restrict__ g,
                            const float* __restrict__ b,
                            f16* __restrict__ y) {
    int r = blockIdx.x;
    int tid = threadIdx.x;   // 256
    const float* xr = x + (size_t)r * DD;
    float v0 = xr[tid], v1 = xr[tid + 256], v2 = xr[tid + 512];

    __shared__ float red[8];
    float s = v0 + v1 + v2;
    #pragma unroll
    for (int o = 16; o > 0; o >>= 1) s += __shfl_xor_sync(0xffffffffu, s, o);
    if ((tid & 31) == 0) red[tid >> 5] = s;
    __syncthreads();
    float tot = 0.f;
    #pragma unroll
    for (int i = 0; i < 8; i++) tot += red[i];
    float mean = tot * (1.0f / DD);
    __syncthreads();
    float c0 = v0 - mean, c1 = v1 - mean, c2 = v2 - mean;
    float sq = c0 * c0 + c1 * c1 + c2 * c2;
    #pragma unroll
    for (int o = 16; o > 0; o >>= 1) sq += __shfl_xor_sync(0xffffffffu, sq, o);
    if ((tid & 31) == 0) red[tid >> 5] = sq;
    __syncthreads();
    float var = 0.f;
    #pragma unroll
    for (int i = 0; i < 8; i++) var += red[i];
    var *= (1.0f / DD);
    float rstd = rsqrtf(var + 1e-5f);

    size_t base = (size_t)r * DD;
    y[base + tid]       = __float2half(c0 * rstd * g[tid]       + b[tid]);
    y[base + tid + 256] = __float2half(c1 * rstd * g[tid + 256] + b[tid + 256]);
    y[base + tid + 512] = __float2half(c2 * rstd * g[tid + 512] + b[tid + 512]);
}

__device__ __forceinline__ float softplusf(float x) {
    if (x > 20.f) return x;
    if (x < -20.f) return expf(x);
    return log1pf(expf(x));
}

// Gate: fp32-exact — reads residual x and applies LN inline (avoids fp16
// quantization flipping near-tied top-2 selections).
__global__ void gate_kernel(const float* __restrict__ x,
                            const float* __restrict__ lng,
                            const float* __restrict__ lnb,
                            const float* __restrict__ gw,
                            const float* __restrict__ nw,
                            const float* __restrict__ noise,
                            float* __restrict__ coef) {
    int r = blockIdx.x;
    int tid = threadIdx.x; // 128
    const float* xr = x + (size_t)r * DD;
    float v[6];
    #pragma unroll
    for (int i = 0; i < 6; i++) v[i] = xr[tid + i * 128];

    __shared__ float red[4];
    float s = 0.f;
    #pragma unroll
    for (int i = 0; i < 6; i++) s += v[i];
    #pragma unroll
    for (int o = 16; o > 0; o >>= 1) s += __shfl_xor_sync(0xffffffffu, s, o);
    if ((tid & 31) == 0) red[tid >> 5] = s;
    __syncthreads();
    float mean = (red[0] + red[1] + red[2] + red[3]) * (1.0f / DD);
    __syncthreads();
    float sq = 0.f;
    #pragma unroll
    for (int i = 0; i < 6; i++) { float c = v[i] - mean; sq += c * c; }
    #pragma unroll
    for (int o = 16; o > 0; o >>= 1) sq += __shfl_xor_sync(0xffffffffu, sq, o);
    if ((tid & 31) == 0) red[tid >> 5] = sq;
    __syncthreads();
    float rstd = rsqrtf((red[0] + red[1] + red[2] + red[3]) * (1.0f / DD) + 1e-5f);

    float acc[8] = {0.f, 0.f, 0.f, 0.f, 0.f, 0.f, 0.f, 0.f};
    #pragma unroll
    for (int i = 0; i < 6; i++) {
        int d = tid + i * 128;
        float xv = (v[i] - mean) * rstd * lng[d] + lnb[d];
        #pragma unroll
        for (int e = 0; e < EE; e++) {
            acc[e]     += xv * gw[d * EE + e];
            acc[4 + e] += xv * nw[d * EE + e];
        }
    }
    __shared__ float part[8 * 128];
    #pragma unroll
    for (int e = 0; e < 8; e++) part[e * 128 + tid] = acc[e];
    __syncthreads();
    __shared__ float red8[8];
    if (tid < 8) {
        float t = 0.f;
        for (int i = 0; i < 128; i++) t += part[tid * 128 + i];
        red8[tid] = t;
    }
    __syncthreads();
    if (tid == 0) {
        float lg[4];
        #pragma unroll
        for (int e = 0; e < EE; e++)
            lg[e] = red8[e] + noise[(size_t)r * EE + e] * softplusf(red8[4 + e]);
        int i1 = 0;
        #pragma unroll
        for (int e = 1; e < EE; e++) if (lg[e] > lg[i1]) i1 = e;
        int i2 = -1;
        #pragma unroll
        for (int e = 0; e < EE; e++) {
            if (e == i1) continue;
            if (i2 < 0 || lg[e] > lg[i2]) i2 = e;
        }
        float m = lg[i1];
        float e1 = expf(lg[i1] - m), e2 = expf(lg[i2] - m);
        float inv = 1.f / (e1 + e2);
        float c[4] = {0.f, 0.f, 0.f, 0.f};
        c[i1] = e1 * inv;
        c[i2] = e2 * inv;
        #pragma unroll
        for (int e = 0; e < EE; e++) coef[(size_t)r * EE + e] = c[e];
    }
}

// batched transpose fp32 [K,N] -> split fp16 [N, ld]
#define TRMAX 20
struct TrTable {
    const float* src[TRMAX];
    f16* dhi[TRMAX];
    f16* dlo[TRMAX];
    int  srcN[TRMAX];
    int  ld[TRMAX];
};

__global__ void tr_multi(TrTable t) {
    __shared__ float tile[32][33];
    int z = blockIdx.z;
    const float* src = t.src[z];
    f16* dhi = t.dhi[z];
    f16* dlo = t.dlo[z];
    int N = t.srcN[z], ld = t.ld[z];
    int n0 = blockIdx.x * 32, k0 = blockIdx.y * 32;
    int tx = threadIdx.x, ty = threadIdx.y; // 32x8
    #pragma unroll
    for (int i = 0; i < 4; i++)
        tile[ty + 8 * i][tx] = src[(size_t)(k0 + ty + 8 * i) * N + n0 + tx];
    __syncthreads();
    #pragma unroll
    for (int i = 0; i < 4; i++) {
        float v = tile[tx][ty + 8 * i];
        f16 hv, lv; split2h(v, hv, lv);
        size_t o = (size_t)(n0 + ty + 8 * i) * ld + k0 + tx;
        dhi[o] = hv; dlo[o] = lv;
    }
}

// fp32 -> fp16 single plane (wte)
__global__ void conv16(const float* __restrict__ s, f16* __restrict__ d, int n4) {
    int i = blockIdx.x * 256 + threadIdx.x;
    if (i >= n4) return;
    float4 v = ((const float4*)s)[i];
    __half2* D = (__half2*)d;
    D[2 * i]     = __floats2half2_rn(v.x, v.y);
    D[2 * i + 1] = __floats2half2_rn(v.z, v.w);
}

// x[r,:] += p0 + p1 + p2 (+bias)
__global__ void reduce3(const float* __restrict__ p,
                        const float* __restrict__ bias,
                        float* __restrict__ x) {
    int r = blockIdx.x;
    size_t rb = (size_t)r * DD;
    for (int i = threadIdx.x; i < DD; i += 256) {
        float v = p[rb + i] + p[(size_t)NN * DD + rb + i]
                + p[2 * (size_t)NN * DD + rb + i];
        if (bias) v += bias[i];
        x[rb + i] += v;
    }
}

// ------------------- unified fp16 mma GEMM -----------------------------------
// C[2048, N] = A(f16) x B^T, B = Bh (+ Bl when NPASS==2), [N][Kstride] K-contig.
// blockIdx.z selects K-partition (split-K) of length Kloop.
// EPI 0: Cf=v (guard N)   1: gelu(v+bias)->C16   4: v->C16
// EPI 5: Cf[z-plane]=v (partial, plane stride NN*DD)
#define GLDS 40
#define GMAT (128 * GLDS * 2)

template <int EPI, int NPASS>
__global__ __launch_bounds__(256)
void mma_gemm(const f16* __restrict__ A,
              const f16* __restrict__ Bh, const f16* __restrict__ Bl,
              float* __restrict__ Cf, f16* __restrict__ C16,
              const float* __restrict__ bias, int N, int Kloop, int Kstride) {
    constexpr int NMAT = 1 + NPASS;
    constexpr int STG = NMAT * GMAT;
    extern __shared__ char smdyn[];
    const u32 sb = smem_u32(smdyn);
    const int tid = threadIdx.x, wid = tid >> 5, lane = tid & 31;
    const int row0 = blockIdx.x * 128, col0 = blockIdx.y * 128;
    const int kbase = blockIdx.z * Kloop;
    const int warp_m = (wid & 3) * 32, warp_n = (wid >> 2) * 64;

    float c[2][8][4];
    #pragma unroll
    for (int mt = 0; mt < 2; mt++)
        #pragma unroll
        for (int nt = 0; nt < 8; nt++)
            #pragma unroll
            for (int i = 0; i < 4; i++) c[mt][nt][i] = 0.f;

    const int nch = Kloop >> 5;

    auto load_stage = [&](int s, int k0) {
        u32 st = sb + s * STG;
        #pragma unroll
        for (int i = 0; i < 2; i++) {
            int idx = tid + (i << 8);
            int r = idx >> 2, ch = idx & 3;
            u32 doff = (u32)(r * GLDS + ch * 8) * 2;
            size_t ga = (size_t)(row0 + r) * Kstride + kbase + k0 + ch * 8;
            CP16(st + doff, A + ga, 16);
            int gn = col0 + r;
            int pr = (gn < N) ? 16 : 0;
            int gnc = (gn < N) ? gn : 0;
            size_t gb = (size_t)gnc * Kstride + kbase + k0 + ch * 8;
            CP16(st + GMAT + doff, Bh + gb, pr);
            if (NPASS == 2) CP16(st + 2 * GMAT + doff, Bl + gb, pr);
        }
        CP_COMMIT();
    };

    load_stage(0, 0);
    for (int kc = 0; kc < nch; kc++) {
        if (kc + 1 < nch) { load_stage((kc + 1) & 1, (kc + 1) << 5); CP_WAIT1(); }
        else CP_WAIT0();
        __syncthreads();

        u32 st = sb + (kc & 1) * STG;
        #pragma unroll
        for (int ks = 0; ks < 2; ks++) {
            u32 ah[2][4];
            #pragma unroll
            for (int mt = 0; mt < 2; mt++) {
                u32 ro = (u32)(warp_m + mt * 16 + (lane & 15)) * (GLDS * 2)
                       + (u32)(ks * 16 + ((lane >> 4) << 3)) * 2;
                ldmx4(ah[mt], st + ro);
            }
            #pragma unroll
            for (int j = 0; j < 4; j++) {
                u32 bh[4], bl[4];
                u32 ro = (u32)(warp_n + j * 16 + ((lane >> 4) << 3) + (lane & 7)) * (GLDS * 2)
                       + (u32)(ks * 16 + (((lane >> 3) & 1) << 3)) * 2;
                ldmx4(bh, st + GMAT + ro);
                if (NPASS == 2) ldmx4(bl, st + 2 * GMAT + ro);
                #pragma unroll
                for (int mt = 0; mt < 2; mt++) {
                    mma16816h(c[mt][2 * j], ah[mt], bh);
                    if (NPASS == 2) mma16816h(c[mt][2 * j], ah[mt], bl);
                    mma16816h(c[mt][2 * j + 1], ah[mt], bh + 2);
                    if (NPASS == 2) mma16816h(c[mt][2 * j + 1], ah[mt], bl + 2);
                }
            }
        }
        __syncthreads();
    }

    const size_t pplane = (size_t)blockIdx.z * NN * DD;
    #pragma unroll
    for (int mt = 0; mt < 2; mt++) {
        int rb = row0 + warp_m + mt * 16 + (lane >> 2);
        #pragma unroll
        for (int nt = 0; nt < 8; nt++) {
            int cc = col0 + warp_n + nt * 8 + (lane & 3) * 2;
            float* cr = c[mt][nt];
            #pragma unroll
            for (int h = 0; h < 2; h++) {
                int r = rb + h * 8;
                #pragma unroll
                for (int q = 0; q < 2; q++) {
                    int col = cc + q;
                    float v = cr[h * 2 + q];
                    size_t off = (size_t)r * N + col;
                    if (EPI == 0) {
                        if (col < N) Cf[off] = v;
                    } else if (EPI == 1) {
                        C16[off] = __float2half(geluf(v + bias[col]));
                    } else if (EPI == 4) {
                        C16[off] = __float2half(v);
                    } else {  // 5
                        Cf[pplane + off] = v;
                    }
                }
            }
        }
    }
}

// ------------------- fp16 single-pass flash attention ------------------------
// grid = (T/128, H, B*E). qkv16 [N, QKVW]: cols [hh*64]=K, [768+hh*64]=V,
// [1536+e*768+hh*64]=Q. Output: coef-scaled fp16 ob16 [N, FF].
#define AST 72
#define AQB (128 * AST * 2)        // 18432 (Q)
#define AKB (64 * AST * 2)         // 9216 (K or V)
#define AKVSTG (2 * AKB)           // 18432 per stage
#define A_SMEM (AQB + 2 * AKVSTG)  // 55296

__global__ __launch_bounds__(256)
void attn_mma(const f16* __restrict__ qkv, const float* __restrict__ coef,
              f16* __restrict__ ob) {
    extern __shared__ char smdyn[];
    const u32 sb = smem_u32(smdyn);
    const int tid = threadIdx.x, wid = tid >> 5, lane = tid & 31;
    const int q0 = blockIdx.x * 128, hh = blockIdx.y;
    const int b = blockIdx.z >> 2, e = blockIdx.z & 3;
    const u32 QH = sb;
    const size_t qcol = 1536 + (size_t)e * DD + (size_t)hh * 64;

    #pragma unroll
    for (int i = 0; i < 4; i++) {
        int idx = tid + (i << 8);
        int r = idx >> 3, ch = idx & 7;
        size_t g = (size_t)(b * TT + q0 + r) * QKVW + qcol + ch * 8;
        CP16(QH + (u32)(r * AST + ch * 8) * 2, qkv + g, 16);
    }
    auto load_kv = [&](int s, int k0t) {
        u32 st = sb + AQB + s * AKVSTG;
        #pragma unroll
        for (int i = 0; i < 4; i++) {
            int idx = tid + (i << 8);
            int mat = idx >> 9;            // 0:K 1:V
            int r = (idx >> 3) & 63, ch = idx & 7;
            size_t g = (size_t)(b * TT + k0t + r) * QKVW + (size_t)mat * DD
                     + hh * 64 + ch * 8;
            CP16(st + mat * AKB + (u32)(r * AST + ch * 8) * 2, qkv + g, 16);
        }
        CP_COMMIT();
    };
    load_kv(0, 0);

    float o[8][4];
    #pragma unroll
    for (int nt = 0; nt < 8; nt++)
        #pragma unroll
        for (int i = 0; i < 4; i++) o[nt][i] = 0.f;
    float mrow[2] = {-1e30f, -1e30f}, lrow[2] = {0.f, 0.f};
    u32 qh[4][4];

    const int nkt = blockIdx.x * 2 + 2;
    const int warp_r0 = q0 + wid * 16;
    const int rowg0 = warp_r0 + (lane >> 2), rowg1 = rowg0 + 8;

    for (int kt = 0; kt < nkt; kt++) {
        const int k0t = kt * 64;
        if (kt + 1 < nkt) { load_kv((kt + 1) & 1, k0t + 64); CP_WAIT1(); }
        else CP_WAIT0();
        __syncthreads();

        if (kt == 0) {
            #pragma unroll
            for (int ks = 0; ks < 4; ks++) {
                u32 ro = (u32)(wid * 16 + (lane & 15)) * (AST * 2)
                       + (u32)(ks * 16 + ((lane >> 4) << 3)) * 2;
                ldmx4(qh[ks], QH + ro);
            }
        }

        if (k0t <= warp_r0 + 15) {
            const u32 KH = sb + AQB + (kt & 1) * AKVSTG;
            const u32 VH = KH + AKB;

            float s[8][4];
            #pragma unroll
            for (int nt = 0; nt < 8; nt++)
                #pragma unroll
                for (int i = 0; i < 4; i++) s[nt][i] = 0.f;

            #pragma unroll
            for (int ks = 0; ks < 4; ks++) {
                #pragma unroll
                for (int j = 0; j < 4; j++) {
                    u32 bh[4];
                    u32 ro = (u32)(j * 16 + ((lane >> 4) << 3) + (lane & 7)) * (AST * 2)
                           + (u32)(ks * 16 + (((lane >> 3) & 1) << 3)) * 2;
                    ldmx4(bh, KH + ro);
                    mma16816h(s[2 * j],     qh[ks], bh);
                    mma16816h(s[2 * j + 1], qh[ks], bh + 2);
                }
            }

            const bool diag = (k0t + 63 > warp_r0);
            #pragma unroll
            for (int nt = 0; nt < 8; nt++) {
                int cb = k0t + nt * 8 + (lane & 3) * 2;
                #pragma unroll
                for (int q = 0; q < 2; q++) {
                    int col = cb + q;
                    s[nt][q]     = (diag && col > rowg0) ? -1e30f : s[nt][q] * 0.125f;
                    s[nt][2 + q] = (diag && col > rowg1) ? -1e30f : s[nt][2 + q] * 0.125f;
                }
            }

            float ml0 = -1e30f, ml1 = -1e30f;
            #pragma unroll
            for (int nt = 0; nt < 8; nt++) {
                ml0 = fmaxf(ml0, fmaxf(s[nt][0], s[nt][1]));
                ml1 = fmaxf(ml1, fmaxf(s[nt][2], s[nt][3]));
            }
            ml0 = fmaxf(ml0, __shfl_xor_sync(0xffffffffu, ml0, 1));
            ml0 = fmaxf(ml0, __shfl_xor_sync(0xffffffffu, ml0, 2));
            ml1 = fmaxf(ml1, __shfl_xor_sync(0xffffffffu, ml1, 1));
            ml1 = fmaxf(ml1, __shfl_xor_sync(0xffffffffu, ml1, 2));
            float mn0 = fmaxf(mrow[0], ml0), mn1 = fmaxf(mrow[1], ml1);
            float cr0 = __expf(mrow[0] - mn0), cr1 = __expf(mrow[1] - mn1);
            float rs0 = 0.f, rs1 = 0.f;
            #pragma unroll
            for (int nt = 0; nt < 8; nt++) {
                s[nt][0] = __expf(s[nt][0] - mn0); rs0 += s[nt][0];
                s[nt][1] = __expf(s[nt][1] - mn0); rs0 += s[nt][1];
                s[nt][2] = __expf(s[nt][2] - mn1); rs1 += s[nt][2];
                s[nt][3] = __expf(s[nt][3] - mn1); rs1 += s[nt][3];
            }
            rs0 += __shfl_xor_sync(0xffffffffu, rs0, 1);
            rs0 += __shfl_xor_sync(0xffffffffu, rs0, 2);
            rs1 += __shfl_xor_sync(0xffffffffu, rs1, 1);
            rs1 += __shfl_xor_sync(0xffffffffu, rs1, 2);
            lrow[0] = lrow[0] * cr0 + rs0;
            lrow[1] = lrow[1] * cr1 + rs1;
            mrow[0] = mn0; mrow[1] = mn1;
            #pragma unroll
            for (int nt = 0; nt < 8; nt++) {
                o[nt][0] *= cr0; o[nt][1] *= cr0;
                o[nt][2] *= cr1; o[nt][3] *= cr1;
            }

            #pragma unroll
            for (int t = 0; t < 4; t++) {
                u32 a_h[4];
                #pragma unroll
                for (int half = 0; half < 2; half++) {
                    float* sp = s[2 * t + half];
                    a_h[2 * half]     = pkhf(sp[0], sp[1]);
                    a_h[2 * half + 1] = pkhf(sp[2], sp[3]);
                }
                #pragma unroll
                for (int j = 0; j < 4; j++) {
                    u32 vh[4];
                    int m = lane >> 3;
                    u32 rowv = (u32)(t * 16 + ((m & 1) << 3) + (lane & 7));
                    u32 colv = (u32)(j * 16 + ((m >> 1) << 3));
                    ldmx4t(vh, VH + (rowv * AST + colv) * 2);
                    mma16816h(o[2 * j],     a_h, vh);
                    mma16816h(o[2 * j + 1], a_h, vh + 2);
                }
            }
        }
        __syncthreads();
    }

    size_t rg0 = (size_t)b * TT + rowg0, rg1 = (size_t)b * TT + rowg1;
    float inv0 = coef[rg0 * EE + e] / lrow[0];
    float inv1 = coef[rg1 * EE + e] / lrow[1];
    const size_t ocol = (size_t)e * DD + (size_t)hh * 64;
    #pragma unroll
    for (int nt = 0; nt < 8; nt++) {
        int cb = nt * 8 + (lane & 3) * 2;
        #pragma unroll
        for (int q = 0; q < 2; q++) {
            ob[rg0 * FF + ocol + cb + q] = __float2half(o[nt][q] * inv0);
            ob[rg1 * FF + ocol + cb + q] = __float2half(o[nt][2 + q] * inv1);
        }
    }
}

// ------------------- host ----------------------------------------------------
extern "C" void kernel_launch(void* const* d_in, const int* in_sizes, int n_in,
                              void* d_out, int out_size) {
    const int*   idx     = (const int*)  d_in[0];
    const float* wte     = (const float*)d_in[1];
    const float* wpe     = (const float*)d_in[2];
    const float* ln1_g   = (const float*)d_in[3];
    const float* ln1_b   = (const float*)d_in[4];
    const float* ln2_g   = (const float*)d_in[5];
    const float* ln2_b   = (const float*)d_in[6];
    const float* lnf_g   = (const float*)d_in[7];
    const float* lnf_b   = (const float*)d_in[8];
    const float* Wk      = (const float*)d_in[9];
    const float* Wv      = (const float*)d_in[10];
    const float* Wq      = (const float*)d_in[11];
    const float* Wo      = (const float*)d_in[12];
    const float* gate_w  = (const float*)d_in[13];
    const float* noise_w = (const float*)d_in[14];
    const float* fc_w    = (const float*)d_in[15];
    const float* fc_b    = (const float*)d_in[16];
    const float* proj_w  = (const float*)d_in[17];
    const float* proj_b  = (const float*)d_in[18];
    const float* noise   = (const float*)d_in[19];
    float* out = (float*)d_out;

    float *x, *coef, *part;
    f16 *ln16, *qkv16, *ob16, *h116;
    f16 *qkvTH, *qkvTL, *oTH, *oTL, *fcTH, *fcTL, *pjTH, *pjTL, *wteH;
    cudaGetSymbolAddress((void**)&x,     g_x);
    cudaGetSymbolAddress((void**)&coef,  g_coef);
    cudaGetSymbolAddress((void**)&part,  g_part);
    cudaGetSymbolAddress((void**)&ln16,  g_ln16);
    cudaGetSymbolAddress((void**)&qkv16, g_qkv16);
    cudaGetSymbolAddress((void**)&ob16,  g_ob16);
    cudaGetSymbolAddress((void**)&h116,  g_h116);
    cudaGetSymbolAddress((void**)&qkvTH, g_qkvTHi);
    cudaGetSymbolAddress((void**)&qkvTL, g_qkvTLo);
    cudaGetSymbolAddress((void**)&oTH,   g_oTHi);
    cudaGetSymbolAddress((void**)&oTL,   g_oTLo);
    cudaGetSymbolAddress((void**)&fcTH,  g_fcTHi);
    cudaGetSymbolAddress((void**)&fcTL,  g_fcTLo);
    cudaGetSymbolAddress((void**)&pjTH,  g_pjTHi);
    cudaGetSymbolAddress((void**)&pjTL,  g_pjTLo);
    cudaGetSymbolAddress((void**)&wteH,  g_wteH);

    const int SM2 = 2 * 3 * GMAT;   // NPASS=2 stages
    const int SM1 = 2 * 2 * GMAT;   // NPASS=1 stages
    cudaFuncSetAttribute(mma_gemm<4, 2>, cudaFuncAttributeMaxDynamicSharedMemorySize, SM2);
    cudaFuncSetAttribute(mma_gemm<1, 2>, cudaFuncAttributeMaxDynamicSharedMemorySize, SM2);
    cudaFuncSetAttribute(mma_gemm<5, 2>, cudaFuncAttributeMaxDynamicSharedMemorySize, SM2);
    cudaFuncSetAttribute(mma_gemm<0, 1>, cudaFuncAttributeMaxDynamicSharedMemorySize, SM1);
    cudaFuncSetAttribute(attn_mma, cudaFuncAttributeMaxDynamicSharedMemorySize, A_SMEM);

    const size_t DxD = (size_t)DD * DD;

    // ---- build transpose tables ----
    TrTable tDD = {}, tFC = {}, tPJ = {};
    int nDD = 0;
    for (int l = 0; l < LL; l++) {
        tDD.src[nDD] = Wk + l * DxD;
        tDD.dhi[nDD] = qkvTH + ((size_t)l * QKVW + 0) * DD;
        tDD.dlo[nDD] = qkvTL + ((size_t)l * QKVW + 0) * DD;
        tDD.srcN[nDD] = DD; tDD.ld[nDD] = DD; nDD++;
        tDD.src[nDD] = Wv + l * DxD;
        tDD.dhi[nDD] = qkvTH + ((size_t)l * QKVW + DD) * DD;
        tDD.dlo[nDD] = qkvTL + ((size_t)l * QKVW + DD) * DD;
        tDD.srcN[nDD] = DD; tDD.ld[nDD] = DD; nDD++;
        for (int e = 0; e < EE; e++) {
            tDD.src[nDD] = Wq + ((size_t)l * EE + e) * DxD;
            tDD.dhi[nDD] = qkvTH + ((size_t)l * QKVW + 2 * DD + e * DD) * DD;
            tDD.dlo[nDD] = qkvTL + ((size_t)l * QKVW + 2 * DD + e * DD) * DD;
            tDD.srcN[nDD] = DD; tDD.ld[nDD] = DD; nDD++;
            tDD.src[nDD] = Wo + ((size_t)l * EE + e) * DxD;
            tDD.dhi[nDD] = oTH + (size_t)l * DD * FF + e * DD;
            tDD.dlo[nDD] = oTL + (size_t)l * DD * FF + e * DD;
            tDD.srcN[nDD] = DD; tDD.ld[nDD] = FF; nDD++;
        }
    }
    for (int l = 0; l < LL; l++) {
        tFC.src[l] = fc_w + (size_t)l * DD * FF;
        tFC.dhi[l] = fcTH + (size_t)l * FF * DD;
        tFC.dlo[l] = fcTL + (size_t)l * FF * DD;
        tFC.srcN[l] = FF; tFC.ld[l] = DD;
        tPJ.src[l] = proj_w + (size_t)l * FF * DD;
        tPJ.dhi[l] = pjTH + (size_t)l * DD * FF;
        tPJ.dlo[l] = pjTL + (size_t)l * DD * FF;
        tPJ.srcN[l] = DD; tPJ.ld[l] = FF;
    }

    dim3 trb(32, 8);
    tr_multi<<<dim3(DD / 32, DD / 32, nDD), trb>>>(tDD);
    tr_multi<<<dim3(FF / 32, DD / 32, LL), trb>>>(tFC);
    embed_kernel<<<NN, 256>>>(idx, wte, wpe, x);
    tr_multi<<<dim3(DD / 32, FF / 32, LL), trb>>>(tPJ);

    dim3 gQKV(NN / 128, QKVW / 128);
    dim3 gFC(NN / 128, FF / 128);
    dim3 gSP(NN / 128, DD / 128, 3);
    dim3 gV(NN / 128, (VV + 127) / 128);
    dim3 gA(TT / 128, HH, BBATCH * EE);

    for (int l = 0; l < LL; l++) {
        ln16_kernel<<<NN, 256>>>(x, ln1_g + l * DD, ln1_b + l * DD, ln16);
        mma_gemm<4, 2><<<gQKV, 256, SM2>>>(ln16,
            qkvTH + (size_t)l * QKVW * DD, qkvTL + (size_t)l * QKVW * DD,
            nullptr, qkv16, nullptr, QKVW, DD, DD);
        gate_kernel<<<NN, 128>>>(x, ln1_g + l * DD, ln1_b + l * DD,
                                 gate_w + (size_t)l * DD * EE,
                                 noise_w + (size_t)l * DD * EE,
                                 noise + (size_t)l * NN * EE, coef);
        attn_mma<<<gA, 256, A_SMEM>>>(qkv16, coef, ob16);
        mma_gemm<5, 2><<<gSP, 256, SM2>>>(ob16,
            oTH + (size_t)l * DD * FF, oTL + (size_t)l * DD * FF,
            part, nullptr, nullptr, DD, 1024, FF);
        reduce3<<<NN, 256>>>(part, nullptr, x);
        ln16_kernel<<<NN, 256>>>(x, ln2_g + l * DD, ln2_b + l * DD, ln16);
        mma_gemm<1, 2><<<gFC, 256, SM2>>>(ln16,
            fcTH + (size_t)l * FF * DD, fcTL + (size_t)l * FF * DD,
            nullptr, h116, fc_b + (size_t)l * FF, FF, DD, DD);
        mma_gemm<5, 2><<<gSP, 256, SM2>>>(h116,
            pjTH + (size_t)l * DD * FF, pjTL + (size_t)l * DD * FF,
            part, nullptr, nullptr, DD, 1024, FF);
        reduce3<<<NN, 256>>>(part, proj_b + (size_t)l * DD, x);
    }

    {
        int n4 = VV * DD / 4;
        conv16<<<(n4 + 255) / 256, 256>>>(wte, wteH, n4);
    }
    ln16_kernel<<<NN, 256>>>(x, lnf_g, lnf_b, ln16);
    mma_gemm<0, 1><<<gV, 256, SM1>>>(ln16, wteH, nullptr,
                                     out, nullptr, nullptr, VV, DD, DD);
}